// round 1
// baseline (speedup 1.0000x reference)
#include <cuda_runtime.h>
#include <math.h>

#define BB 2
#define SS 2048
#define DD 1024
#define NH 16
#define DH 64
#define NE 8
#define FF 4096
#define TT (BB*SS)   // 4096 tokens
#define NMAIN (TT*DD)

// ---------------- scratch (static device allocations; no cudaMalloc allowed) ----
__device__ float g_xn[TT*DD];
__device__ float g_q[TT*DD];
__device__ float g_k[TT*DD];
__device__ float g_v[TT*DD];
__device__ float g_ctx[TT*DD];
__device__ float g_x2[TT*DD];
__device__ float g_xn2[TT*DD];
__device__ float g_probs[TT*NE];
__device__ float g_zz[TT];
__device__ int   g_cnt[NE];
__device__ int   g_rowlist[NE*TT];
__device__ int   g_slot_e[2*TT];
__device__ int   g_slot_r[2*TT];
__device__ float g_slot_w[2*TT];
__device__ float g_H[(size_t)NE*TT*FF];   // 512 MB
__device__ float g_Y[(size_t)NE*TT*DD];   // 128 MB

// ---------------- rmsnorm ----------------
__global__ void rmsnorm_kernel(const float* __restrict__ x, const float* __restrict__ w,
                               float* __restrict__ y)
{
    int row = blockIdx.x;
    int tid = threadIdx.x;
    const float* xr = x + (size_t)row * DD;
    float s = 0.f;
    for (int d = tid; d < DD; d += 256) { float v = xr[d]; s += v * v; }
    __shared__ float red[256];
    red[tid] = s; __syncthreads();
    for (int o = 128; o > 0; o >>= 1) { if (tid < o) red[tid] += red[tid + o]; __syncthreads(); }
    float inv = rsqrtf(red[0] / (float)DD + 1e-6f);
    float* yr = y + (size_t)row * DD;
    for (int d = tid; d < DD; d += 256) yr[d] = xr[d] * inv * w[d];
}

// ---------------- generic tiled GEMM ----------------
#define GM_PLAIN 0
#define GM_QKV   1
#define GM_RES   2
#define GM_MOE1  3
#define GM_MOE2  4

__device__ __forceinline__ float gelu_tanh(float x) {
    float x3 = x * x * x;
    return 0.5f * x * (1.f + tanhf(0.7978845608028654f * (x + 0.044715f * x3)));
}

template<int MODE>
__global__ void gemm_kernel(const float* __restrict__ A, const float* __restrict__ Bm,
                            float* __restrict__ C, const float* __restrict__ Res,
                            int M, int N, int K)
{
    const int BMt = 64, BNt = 64, BKt = 16;
    int e  = blockIdx.z;
    int m0 = blockIdx.y * BMt;
    int n0 = blockIdx.x * BNt;
    int Me = M;
    const float* Bbase = Bm;
    if (MODE == GM_MOE1 || MODE == GM_MOE2) {
        Me = g_cnt[e];
        if (m0 >= Me) return;
        Bbase = Bm + (size_t)e * K * N;
    }
    __shared__ __align__(16) float As[BKt][BMt + 4];
    __shared__ __align__(16) float Bs[BKt][BNt + 4];
    int tid = threadIdx.x;
    int tx = tid & 15, ty = tid >> 4;
    int a_row = tid >> 2;
    int a_k   = (tid & 3) << 2;
    int b_row = tid >> 4;
    int b_c   = (tid & 15) << 2;
    int gm = m0 + a_row;
    const float* Arow = nullptr;
    bool av = (gm < Me);
    if (MODE == GM_MOE1)      { if (av) Arow = A + (size_t)g_rowlist[e * TT + gm] * K; }
    else if (MODE == GM_MOE2) { if (av) Arow = A + ((size_t)e * TT + gm) * K; }
    else                      { Arow = A + (size_t)gm * K; }

    float acc[4][4];
#pragma unroll
    for (int i = 0; i < 4; i++)
#pragma unroll
        for (int j = 0; j < 4; j++) acc[i][j] = 0.f;

    for (int k0 = 0; k0 < K; k0 += BKt) {
        float4 avv = av ? *(const float4*)(Arow + k0 + a_k) : make_float4(0.f, 0.f, 0.f, 0.f);
        As[a_k + 0][a_row] = avv.x;
        As[a_k + 1][a_row] = avv.y;
        As[a_k + 2][a_row] = avv.z;
        As[a_k + 3][a_row] = avv.w;
        float4 bvv = *(const float4*)(Bbase + (size_t)(k0 + b_row) * N + n0 + b_c);
        *(float4*)&Bs[b_row][b_c] = bvv;
        __syncthreads();
#pragma unroll
        for (int k = 0; k < BKt; k++) {
            float ar[4];
            float4 br4 = *(float4*)&Bs[k][tx * 4];
            float br[4] = {br4.x, br4.y, br4.z, br4.w};
#pragma unroll
            for (int i = 0; i < 4; i++) ar[i] = As[k][ty * 4 + i];
#pragma unroll
            for (int i = 0; i < 4; i++)
#pragma unroll
                for (int j = 0; j < 4; j++) acc[i][j] = fmaf(ar[i], br[j], acc[i][j]);
        }
        __syncthreads();
    }

#pragma unroll
    for (int i = 0; i < 4; i++) {
        int row = m0 + ty * 4 + i;
        if (row >= Me) continue;
#pragma unroll
        for (int j = 0; j < 4; j++) {
            int col = n0 + tx * 4 + j;
            float v = acc[i][j];
            if (MODE == GM_PLAIN) {
                C[(size_t)row * N + col] = v;
            } else if (MODE == GM_RES) {
                C[(size_t)row * N + col] = v + Res[(size_t)row * N + col];
            } else if (MODE == GM_QKV) {
                int b = row >> 11, s = row & (SS - 1);
                int h = col >> 6, dh = col & 63;
                C[(((size_t)(b * NH + h)) * SS + s) * DH + dh] = v;
            } else if (MODE == GM_MOE1) {
                C[((size_t)e * TT + row) * N + col] = gelu_tanh(v);
            } else if (MODE == GM_MOE2) {
                C[((size_t)e * TT + row) * N + col] = v;
            }
        }
    }
}

// ---------------- flash attention ----------------
#define ATTN_SMEM ((4 * 64 * 65 + 3 * 64) * 4)

__global__ void attn_kernel(const float* __restrict__ q, const float* __restrict__ k,
                            const float* __restrict__ v, float* __restrict__ ctx)
{
    extern __shared__ float sm[];
    float* Qs   = sm;               // 64x65
    float* Ks   = Qs + 64 * 65;
    float* Vs   = Ks + 64 * 65;
    float* Ps   = Vs + 64 * 65;
    float* mrow = Ps + 64 * 65;
    float* lrow = mrow + 64;
    float* arow = lrow + 64;

    int bh = blockIdx.x;   // b*NH+h, 0..31
    int qt = blockIdx.y;   // q tile, 0..31
    int tid = threadIdx.x;
    int tx = tid & 15, ty = tid >> 4;
    const float scale = 0.125f;   // 1/sqrt(64)

    const float* Qg = q + ((size_t)bh * SS + qt * 64) * DH;
    for (int i = tid; i < 64 * 64; i += 256) {
        int r = i >> 6, d = i & 63;
        Qs[r * 65 + d] = Qg[r * 64 + d] * scale;
    }
    if (tid < 64) { mrow[tid] = -1e30f; lrow[tid] = 0.f; }
    float acc[4][4];
#pragma unroll
    for (int i = 0; i < 4; i++)
#pragma unroll
        for (int j = 0; j < 4; j++) acc[i][j] = 0.f;
    __syncthreads();

    for (int kt = 0; kt < SS / 64; kt++) {
        const float* Kg = k + ((size_t)bh * SS + kt * 64) * DH;
        const float* Vg = v + ((size_t)bh * SS + kt * 64) * DH;
        for (int i = tid; i < 64 * 64; i += 256) {
            int r = i >> 6, d = i & 63;
            Ks[r * 65 + d] = Kg[r * 64 + d];
            Vs[r * 65 + d] = Vg[r * 64 + d];
        }
        __syncthreads();

        float sv[4][4];
#pragma unroll
        for (int i = 0; i < 4; i++)
#pragma unroll
            for (int j = 0; j < 4; j++) sv[i][j] = 0.f;
#pragma unroll 8
        for (int d = 0; d < 64; d++) {
            float ar[4], br[4];
#pragma unroll
            for (int i = 0; i < 4; i++) ar[i] = Qs[(ty * 4 + i) * 65 + d];
#pragma unroll
            for (int j = 0; j < 4; j++) br[j] = Ks[(tx * 4 + j) * 65 + d];
#pragma unroll
            for (int i = 0; i < 4; i++)
#pragma unroll
                for (int j = 0; j < 4; j++) sv[i][j] = fmaf(ar[i], br[j], sv[i][j]);
        }
#pragma unroll
        for (int i = 0; i < 4; i++)
#pragma unroll
            for (int j = 0; j < 4; j++)
                Ps[(ty * 4 + i) * 65 + tx * 4 + j] = sv[i][j];
        __syncthreads();

        if (tid < 64) {
            int r = tid;
            float m = mrow[r];
            float mx = m;
            for (int c = 0; c < 64; c++) mx = fmaxf(mx, Ps[r * 65 + c]);
            float a = expf(m - mx);
            float sum = 0.f;
            for (int c = 0; c < 64; c++) {
                float p = expf(Ps[r * 65 + c] - mx);
                Ps[r * 65 + c] = p;
                sum += p;
            }
            lrow[r] = lrow[r] * a + sum;
            mrow[r] = mx;
            arow[r] = a;
        }
        __syncthreads();

#pragma unroll
        for (int i = 0; i < 4; i++) {
            float a = arow[ty * 4 + i];
#pragma unroll
            for (int j = 0; j < 4; j++) acc[i][j] *= a;
        }
#pragma unroll 8
        for (int kk = 0; kk < 64; kk++) {
            float pr[4], vr[4];
#pragma unroll
            for (int i = 0; i < 4; i++) pr[i] = Ps[(ty * 4 + i) * 65 + kk];
#pragma unroll
            for (int j = 0; j < 4; j++) vr[j] = Vs[kk * 65 + tx * 4 + j];
#pragma unroll
            for (int i = 0; i < 4; i++)
#pragma unroll
                for (int j = 0; j < 4; j++) acc[i][j] = fmaf(pr[i], vr[j], acc[i][j]);
        }
        __syncthreads();
    }

    int b = bh >> 4, h = bh & 15;
#pragma unroll
    for (int i = 0; i < 4; i++) {
        int r = ty * 4 + i;
        float inv = 1.f / lrow[r];
        int s = qt * 64 + r;
#pragma unroll
        for (int j = 0; j < 4; j++) {
            int d = tx * 4 + j;
            ctx[((size_t)(b * SS + s)) * DD + h * 64 + d] = acc[i][j] * inv;
        }
    }
}

// ---------------- router ----------------
__global__ void zero_cnt_kernel() {
    if (threadIdx.x < NE) g_cnt[threadIdx.x] = 0;
}

__global__ void router_kernel(const float* __restrict__ xn2, const float* __restrict__ wr)
{
    int t = blockIdx.x;
    int lane = threadIdx.x;
    float p[NE];
#pragma unroll
    for (int e = 0; e < NE; e++) p[e] = 0.f;
    const float* xr = xn2 + (size_t)t * DD;
    for (int d = lane; d < DD; d += 32) {
        float xv = xr[d];
        const float* wrow = wr + (size_t)d * NE;
#pragma unroll
        for (int e = 0; e < NE; e++) p[e] = fmaf(xv, wrow[e], p[e]);
    }
#pragma unroll
    for (int e = 0; e < NE; e++) {
        for (int o = 16; o > 0; o >>= 1) p[e] += __shfl_xor_sync(0xffffffffu, p[e], o);
    }
    if (lane == 0) {
        float m = p[0];
#pragma unroll
        for (int e = 1; e < NE; e++) m = fmaxf(m, p[e]);
        float pr[NE];
        float sum = 0.f;
#pragma unroll
        for (int e = 0; e < NE; e++) { pr[e] = expf(p[e] - m); sum += pr[e]; }
        float inv = 1.f / sum;
#pragma unroll
        for (int e = 0; e < NE; e++) pr[e] *= inv;
        g_zz[t] = m + logf(sum);
#pragma unroll
        for (int e = 0; e < NE; e++) g_probs[t * NE + e] = pr[e];
        int i0 = 0; float v0 = pr[0];
#pragma unroll
        for (int e = 1; e < NE; e++) if (pr[e] > v0) { v0 = pr[e]; i0 = e; }
        int i1 = -1; float v1 = -1.f;
#pragma unroll
        for (int e = 0; e < NE; e++) { if (e == i0) continue; if (pr[e] > v1) { v1 = pr[e]; i1 = e; } }
        float wsum = v0 + v1;
        float w0 = v0 / wsum, w1 = v1 / wsum;
        int r0 = atomicAdd(&g_cnt[i0], 1); g_rowlist[i0 * TT + r0] = t;
        int r1 = atomicAdd(&g_cnt[i1], 1); g_rowlist[i1 * TT + r1] = t;
        g_slot_e[2 * t]     = i0; g_slot_r[2 * t]     = r0; g_slot_w[2 * t]     = w0;
        g_slot_e[2 * t + 1] = i1; g_slot_r[2 * t + 1] = r1; g_slot_w[2 * t + 1] = w1;
    }
}

// ---------------- loss (deterministic tree reduction) ----------------
__global__ void loss_kernel(float* __restrict__ out, int out_size)
{
    int tid = threadIdx.x;
    __shared__ float red[256];
    __shared__ float sumsp[NE];
    __shared__ float sumz;
    float accp[NE];
#pragma unroll
    for (int e = 0; e < NE; e++) accp[e] = 0.f;
    float accz = 0.f;
    for (int t = tid; t < TT; t += 256) {
        float z = g_zz[t];
        accz += z * z;
#pragma unroll
        for (int e = 0; e < NE; e++) accp[e] += g_probs[t * NE + e];
    }
    red[tid] = accz; __syncthreads();
    for (int o = 128; o > 0; o >>= 1) { if (tid < o) red[tid] += red[tid + o]; __syncthreads(); }
    if (tid == 0) sumz = red[0];
    __syncthreads();
    for (int e = 0; e < NE; e++) {
        red[tid] = accp[e]; __syncthreads();
        for (int o = 128; o > 0; o >>= 1) { if (tid < o) red[tid] += red[tid + o]; __syncthreads(); }
        if (tid == 0) sumsp[e] = red[0];
        __syncthreads();
    }
    if (tid == 0) {
        float aux = 0.f;
        for (int e = 0; e < NE; e++) {
            float ft = (float)g_cnt[e] / (float)TT;
            float fp = sumsp[e] / (float)TT;
            aux += ft * fp;
        }
        aux *= (float)NE / 2.f;   // E * sum / K, K=2
        float loss = aux + 0.001f * (sumz / (float)TT);
        for (int i = NMAIN; i < out_size; i++) out[i] = loss;
    }
}

// ---------------- combine ----------------
__global__ void combine_kernel(float* __restrict__ out)
{
    int idx = blockIdx.x * 256 + threadIdx.x;
    if (idx >= NMAIN) return;
    int t = idx >> 10;
    int d = idx & 1023;
    int e0 = g_slot_e[2 * t], r0 = g_slot_r[2 * t];
    int e1 = g_slot_e[2 * t + 1], r1 = g_slot_r[2 * t + 1];
    float w0 = g_slot_w[2 * t], w1 = g_slot_w[2 * t + 1];
    float y = g_x2[idx]
            + w0 * g_Y[((size_t)e0 * TT + r0) * DD + d]
            + w1 * g_Y[((size_t)e1 * TT + r1) * DD + d];
    out[idx] = y;
}

// ---------------- launch ----------------
extern "C" void kernel_launch(void* const* d_in, const int* in_sizes, int n_in,
                              void* d_out, int out_size)
{
    const float* x   = (const float*)d_in[0];
    const float* ln1 = (const float*)d_in[1];
    const float* ln2 = (const float*)d_in[2];
    const float* wq  = (const float*)d_in[3];
    const float* wk  = (const float*)d_in[4];
    const float* wv  = (const float*)d_in[5];
    const float* wo  = (const float*)d_in[6];
    const float* wr  = (const float*)d_in[7];
    const float* w1  = (const float*)d_in[8];
    const float* w2  = (const float*)d_in[9];
    float* out = (float*)d_out;

    cudaFuncSetAttribute(attn_kernel, cudaFuncAttributeMaxDynamicSharedMemorySize, ATTN_SMEM);

    float *p_xn, *p_q, *p_k, *p_v, *p_ctx, *p_x2, *p_xn2, *p_H, *p_Y;
    cudaGetSymbolAddress((void**)&p_xn,  g_xn);
    cudaGetSymbolAddress((void**)&p_q,   g_q);
    cudaGetSymbolAddress((void**)&p_k,   g_k);
    cudaGetSymbolAddress((void**)&p_v,   g_v);
    cudaGetSymbolAddress((void**)&p_ctx, g_ctx);
    cudaGetSymbolAddress((void**)&p_x2,  g_x2);
    cudaGetSymbolAddress((void**)&p_xn2, g_xn2);
    cudaGetSymbolAddress((void**)&p_H,   g_H);
    cudaGetSymbolAddress((void**)&p_Y,   g_Y);

    // 1. rmsnorm 1
    rmsnorm_kernel<<<TT, 256>>>(x, ln1, p_xn);

    // 2. QKV projections (write [B,H,S,Dh])
    dim3 gproj(DD / 64, TT / 64, 1);
    gemm_kernel<GM_QKV><<<gproj, 256>>>(p_xn, wq, p_q, nullptr, TT, DD, DD);
    gemm_kernel<GM_QKV><<<gproj, 256>>>(p_xn, wk, p_k, nullptr, TT, DD, DD);
    gemm_kernel<GM_QKV><<<gproj, 256>>>(p_xn, wv, p_v, nullptr, TT, DD, DD);

    // 3. attention
    attn_kernel<<<dim3(BB * NH, SS / 64), 256, ATTN_SMEM>>>(p_q, p_k, p_v, p_ctx);

    // 4. output projection + residual
    gemm_kernel<GM_RES><<<gproj, 256>>>(p_ctx, wo, p_x2, x, TT, DD, DD);

    // 5. rmsnorm 2
    rmsnorm_kernel<<<TT, 256>>>(p_x2, ln2, p_xn2);

    // 6. router
    zero_cnt_kernel<<<1, 32>>>();
    router_kernel<<<TT, 32>>>(p_xn2, wr);

    // 7. loss -> out[NMAIN..]
    loss_kernel<<<1, 256>>>(out, out_size);

    // 8. MoE expert GEMMs (grouped; tiles beyond per-expert count early-exit)
    dim3 gmoe1(FF / 64, TT / 64, NE);
    gemm_kernel<GM_MOE1><<<gmoe1, 256>>>(p_xn2, w1, p_H, nullptr, TT, FF, DD);
    dim3 gmoe2(DD / 64, TT / 64, NE);
    gemm_kernel<GM_MOE2><<<gmoe2, 256>>>(p_H, w2, p_Y, nullptr, TT, DD, FF);

    // 9. combine + residual -> out
    combine_kernel<<<(NMAIN + 255) / 256, 256>>>(out);
}

// round 3
// speedup vs baseline: 1.4971x; 1.4971x over previous
#include <cuda_runtime.h>
#include <cuda_bf16.h>
#include <math.h>
#include <stdint.h>

#define BB 2
#define SS 2048
#define DD 1024
#define NH 16
#define DH 64
#define NE 8
#define FF 4096
#define TT (BB*SS)   // 4096 tokens
#define NMAIN (TT*DD)

typedef __nv_bfloat16 bf16;

// ---------------- scratch (static device globals; no cudaMalloc allowed) ----
__device__ bf16  g_xnh[TT*DD],  g_xnl[TT*DD];          // rmsnorm1 out, split
__device__ float g_xn2[TT*DD];                          // rmsnorm2 out fp32 (router)
__device__ bf16  g_xn2h[TT*DD], g_xn2l[TT*DD];          // rmsnorm2 out, split
__device__ float g_qkv[3][(size_t)TT*DD];               // q,k,v fp32 [B,H,S,Dh]
__device__ bf16  g_ctxh[TT*DD], g_ctxl[TT*DD];          // attention ctx, split
__device__ float g_x2[TT*DD];                           // x + attn_out
__device__ bf16  g_wpth[4*DD*DD], g_wptl[4*DD*DD];      // wq,wk,wv,wo transposed split
__device__ bf16  g_w1th[(size_t)NE*DD*FF], g_w1tl[(size_t)NE*DD*FF];
__device__ bf16  g_w2th[(size_t)NE*DD*FF], g_w2tl[(size_t)NE*DD*FF];
__device__ bf16  g_Hh[(size_t)NE*TT*FF], g_Hl[(size_t)NE*TT*FF];  // gelu(h) split
__device__ float g_Y[(size_t)NE*TT*DD];
__device__ float g_probs[TT*NE];
__device__ float g_zz[TT];
__device__ int   g_cnt[NE];
__device__ int   g_rowlist[NE*TT];
__device__ int   g_slot_e[2*TT];
__device__ int   g_slot_r[2*TT];
__device__ float g_slot_w[2*TT];

// ---------------- PTX helpers ----------------
__device__ __forceinline__ uint32_t smem_u32(const void* p) {
    uint32_t a;
    asm("{ .reg .u64 t; cvta.to.shared.u64 t, %1; cvt.u32.u64 %0, t; }" : "=r"(a) : "l"(p));
    return a;
}
__device__ __forceinline__ uint32_t elect1() {
    uint32_t p;
    asm volatile("{\n.reg .pred p;\nelect.sync _|p, 0xFFFFFFFF;\nselp.b32 %0, 1, 0, p;\n}" : "=r"(p));
    return p;
}
__device__ __forceinline__ void mbar_init(uint32_t a, uint32_t n) {
    asm volatile("mbarrier.init.shared.b64 [%0], %1;" :: "r"(a), "r"(n) : "memory");
}
__device__ __forceinline__ void mbar_wait(uint32_t a, uint32_t par) {
    asm volatile(
        "{\n.reg .pred P;\n"
        "LW%=:\n"
        "mbarrier.try_wait.parity.acquire.cta.shared::cta.b64 P, [%0], %1, 0x989680;\n"
        "@P bra LD%=;\n"
        "bra LW%=;\n"
        "LD%=:\n}"
        :: "r"(a), "r"(par) : "memory");
}
__device__ __forceinline__ uint64_t mk_desc(uint32_t addr) {
    return ((uint64_t)2 << 61) | ((uint64_t)1 << 46) | ((uint64_t)64 << 32)
         | ((uint64_t)1 << 16) | ((addr >> 4) & 0x3FFF);
}
__device__ __forceinline__ void tc_commit(uint32_t mbar) {
#if defined(__CUDA_ARCH_FEAT_SM103_ALL)
    asm volatile("tcgen05.commit.cta_group::1.mbarrier::arrive::one.shared::cluster.b64 [%0];"
                 :: "r"(mbar) : "memory");
#endif
}
__device__ __forceinline__ void mma_f16_ss(uint32_t d, uint64_t ad, uint64_t bd,
                                           uint32_t idesc, uint32_t en) {
#if defined(__CUDA_ARCH_FEAT_SM103_ALL)
    asm volatile(
        "{\n.reg .pred p;\n"
        "setp.ne.u32 p, %4, 0;\n"
        "tcgen05.mma.cta_group::1.kind::f16 [%0], %1, %2, %3, {%5, %5, %5, %5}, p;\n}"
        :: "r"(d), "l"(ad), "l"(bd), "r"(idesc), "r"(en), "r"(0u) : "memory");
#endif
}

#if defined(__CUDA_ARCH_FEAT_SM103_ALL)
#define TC_ALLOC(sbaddr, n) \
    asm volatile("tcgen05.alloc.cta_group::1.sync.aligned.shared::cta.b32 [%0], %1;" \
                 :: "r"(sbaddr), "r"((uint32_t)(n)) : "memory")
#define TC_RELINQ() \
    asm volatile("tcgen05.relinquish_alloc_permit.cta_group::1.sync.aligned;")
#define TC_DEALLOC(t, n) \
    asm volatile("tcgen05.dealloc.cta_group::1.sync.aligned.b32 %0, %1;" :: "r"(t), "r"((uint32_t)(n)))
#define TC_FENCE_AFTER()  asm volatile("tcgen05.fence::after_thread_sync;" ::: "memory")
#define TC_FENCE_BEFORE() asm volatile("tcgen05.fence::before_thread_sync;" ::: "memory")
#define TC_WAIT_LD()      asm volatile("tcgen05.wait::ld.sync.aligned;" ::: "memory")
#define TC_LD_X32(r, ta) \
    asm volatile( \
        "tcgen05.ld.sync.aligned.32x32b.x32.b32 " \
        "{%0, %1, %2, %3, %4, %5, %6, %7, " \
        " %8, %9, %10, %11, %12, %13, %14, %15, " \
        " %16, %17, %18, %19, %20, %21, %22, %23, " \
        " %24, %25, %26, %27, %28, %29, %30, %31}, [%32];" \
        : "=r"((r)[0]),  "=r"((r)[1]),  "=r"((r)[2]),  "=r"((r)[3]), \
          "=r"((r)[4]),  "=r"((r)[5]),  "=r"((r)[6]),  "=r"((r)[7]), \
          "=r"((r)[8]),  "=r"((r)[9]),  "=r"((r)[10]), "=r"((r)[11]), \
          "=r"((r)[12]), "=r"((r)[13]), "=r"((r)[14]), "=r"((r)[15]), \
          "=r"((r)[16]), "=r"((r)[17]), "=r"((r)[18]), "=r"((r)[19]), \
          "=r"((r)[20]), "=r"((r)[21]), "=r"((r)[22]), "=r"((r)[23]), \
          "=r"((r)[24]), "=r"((r)[25]), "=r"((r)[26]), "=r"((r)[27]), \
          "=r"((r)[28]), "=r"((r)[29]), "=r"((r)[30]), "=r"((r)[31]) \
        : "r"(ta))
#endif

__device__ __forceinline__ float gelu_tanh(float x) {
    float x3 = x * x * x;
    return 0.5f * x * (1.f + tanhf(0.7978845608028654f * (x + 0.044715f * x3)));
}

// ---------------- rmsnorm (writes fp32 optional + bf16 hi/lo) ----------------
__global__ void rmsnorm_kernel(const float* __restrict__ x, const float* __restrict__ w,
                               float* __restrict__ yf, bf16* __restrict__ yh, bf16* __restrict__ yl)
{
    int row = blockIdx.x;
    int tid = threadIdx.x;
    const float* xr = x + (size_t)row * DD;
    float s = 0.f;
    for (int d = tid; d < DD; d += 256) { float v = xr[d]; s += v * v; }
    __shared__ float red[256];
    red[tid] = s; __syncthreads();
    for (int o = 128; o > 0; o >>= 1) { if (tid < o) red[tid] += red[tid + o]; __syncthreads(); }
    float inv = rsqrtf(red[0] / (float)DD + 1e-6f);
    size_t base = (size_t)row * DD;
    for (int d = tid; d < DD; d += 256) {
        float v = xr[d] * inv * w[d];
        if (yf) yf[base + d] = v;
        bf16 h = __float2bfloat16(v);
        yh[base + d] = h;
        yl[base + d] = __float2bfloat16(v - __bfloat162float(h));
    }
}

// ---------------- weight transpose + bf16 split ----------------
__global__ void wt_convert_kernel(const float* __restrict__ W,
                                  bf16* __restrict__ Th, bf16* __restrict__ Tl,
                                  int K, int N)
{
    __shared__ float tile[32][33];
    size_t zoff = (size_t)blockIdx.z * K * N;
    const float* Wb = W + zoff;
    int n0 = blockIdx.x * 32, k0 = blockIdx.y * 32;
    for (int i = threadIdx.y; i < 32; i += 8)
        tile[i][threadIdx.x] = Wb[(size_t)(k0 + i) * N + n0 + threadIdx.x];
    __syncthreads();
    for (int i = threadIdx.y; i < 32; i += 8) {
        float v = tile[threadIdx.x][i];   // W[k0+tx][n0+i]
        size_t idx = zoff + (size_t)(n0 + i) * K + k0 + threadIdx.x;
        bf16 h = __float2bfloat16(v);
        Th[idx] = h;
        Tl[idx] = __float2bfloat16(v - __bfloat162float(h));
    }
}

// ---------------- GEMM epilogue (shared by tcgen05 + fallback paths) --------
#define GM_QKV  1
#define GM_RES  2
#define GM_MOE1 3
#define GM_MOE2 4
#define G_SMEM  (1024 + 2 * 4 * 16384)   // 132096 B

template<int MODE>
__device__ __forceinline__ void store_elem(int e, int N, int row, int col, float v,
        float* __restrict__ Cf, const float* __restrict__ Res,
        bf16* __restrict__ Ch, bf16* __restrict__ Cl)
{
    if (MODE == GM_QKV) {
        float* Cq = Cf + (size_t)e * TT * DD;
        int b = row >> 11, s5 = row & (SS - 1);
        int h = col >> 6, dh = col & 63;
        Cq[(((size_t)(b * NH + h)) * SS + s5) * DH + dh] = v;
    } else if (MODE == GM_RES) {
        size_t o = (size_t)row * N + col;
        Cf[o] = v + Res[o];
    } else if (MODE == GM_MOE1) {
        size_t o = ((size_t)e * TT + row) * N + col;
        float g = gelu_tanh(v);
        bf16 h = __float2bfloat16(g);
        Ch[o] = h;
        Cl[o] = __float2bfloat16(g - __bfloat162float(h));
    } else { // GM_MOE2
        Cf[((size_t)e * TT + row) * N + col] = v;
    }
}

// ---------------- tcgen05 GEMM: C[128x128] tiles, 3-term bf16 split ----------
template<int MODE>
__global__ void __launch_bounds__(256, 1)
tc_gemm(const bf16* __restrict__ Ah, const bf16* __restrict__ Al,
        const bf16* __restrict__ Bh0, const bf16* __restrict__ Bl0,
        float* __restrict__ Cf, const float* __restrict__ Res,
        bf16* __restrict__ Ch, bf16* __restrict__ Cl,
        int M, int N, int K)
{
#if defined(__CUDA_ARCH__)
    extern __shared__ char sm[];
    int tid = threadIdx.x;
    int e  = blockIdx.z;
    int m0 = blockIdx.y * 128, n0 = blockIdx.x * 128;
    int Me = M;
    const bf16* Bh = Bh0;
    const bf16* Bl = Bl0;
    if (MODE == GM_MOE1 || MODE == GM_MOE2) {
        Me = g_cnt[e];
        if (m0 >= Me) return;
        Bh += (size_t)e * (size_t)K * N; Bl += (size_t)e * (size_t)K * N;
    } else if (MODE == GM_QKV) {
        Bh += (size_t)e * (size_t)K * N; Bl += (size_t)e * (size_t)K * N;
    }

#if defined(__CUDA_ARCH_FEAT_SM103_ALL)
    uint32_t sb = smem_u32(sm);
    int wid = tid >> 5, lid = tid & 31;

    if (wid == 0) { TC_ALLOC(sb, 128); TC_RELINQ(); }
    if (tid == 0) { mbar_init(sb + 8, 1); mbar_init(sb + 16, 1); }
    __syncthreads();
    uint32_t tmem;
    asm volatile("ld.shared.b32 %0, [%1];" : "=r"(tmem) : "r"(sb));

    // loader assignment: threads 0-127 -> A rows, 128-255 -> B rows
    int r = tid & 127;
    bool valid = true;
    const bf16* rowH = nullptr;
    const bf16* rowL = nullptr;
    if (tid < 128) {
        int gr = m0 + r;
        valid = gr < Me;
        if (valid) {
            size_t ri;
            if (MODE == GM_MOE1)      ri = (size_t)g_rowlist[e * TT + gr];
            else if (MODE == GM_MOE2) ri = (size_t)e * TT + gr;
            else                      ri = (size_t)gr;
            rowH = Ah + ri * (size_t)K;
            rowL = Al + ri * (size_t)K;
        }
    } else {
        rowH = Bh + (size_t)(n0 + r) * K;
        rowL = Bl + (size_t)(n0 + r) * K;
    }

    const uint32_t IDESC = (1u << 4) | (1u << 7) | (1u << 10) | (16u << 17) | (8u << 24);
    int nk = K / 64;
    int ph0 = 0, ph1 = 0;
    for (int kc = 0; kc < nk; kc++) {
        int bufi = kc & 1;
        if (kc >= 2) {
            if (bufi == 0) { mbar_wait(sb + 8,  (uint32_t)(ph0 & 1)); ph0++; }
            else           { mbar_wait(sb + 16, (uint32_t)(ph1 & 1)); ph1++; }
        }
        // fill this buffer: 128B (64 bf16) per row, hi and lo, SW128 swizzle
        char* tb = sm + 1024 + bufi * 65536 + (tid < 128 ? 0 : 32768);
        {
            const uint4* srcH = (const uint4*)(rowH + kc * 64);
            const uint4* srcL = (const uint4*)(rowL + kc * 64);
#pragma unroll
            for (int j = 0; j < 8; j++) {
                uint32_t off = (uint32_t)r * 128u + j * 16u;
                uint32_t sw = off ^ ((off >> 3) & 0x70);
                uint4 vh = valid ? srcH[j] : make_uint4(0, 0, 0, 0);
                uint4 vl = valid ? srcL[j] : make_uint4(0, 0, 0, 0);
                *(uint4*)(tb + sw)         = vh;
                *(uint4*)(tb + 16384 + sw) = vl;
            }
        }
        asm volatile("fence.proxy.async.shared::cta;" ::: "memory");
        __syncthreads();
        if (wid == 0 && elect1()) {
            uint32_t base = sb + 1024 + bufi * 65536;
            uint64_t dAh = mk_desc(base);
            uint64_t dAl = mk_desc(base + 16384);
            uint64_t dBh = mk_desc(base + 32768);
            uint64_t dBl = mk_desc(base + 49152);
#pragma unroll
            for (int s = 0; s < 4; s++) {
                uint32_t en0 = (kc == 0 && s == 0) ? 0u : 1u;
                mma_f16_ss(tmem, dAh + 2 * s, dBh + 2 * s, IDESC, en0);
                mma_f16_ss(tmem, dAh + 2 * s, dBl + 2 * s, IDESC, 1u);
                mma_f16_ss(tmem, dAl + 2 * s, dBh + 2 * s, IDESC, 1u);
            }
            tc_commit(sb + 8 + bufi * 8);
        }
    }
    // wait for the last chunk's MMA (in-order completion covers all)
    if (((nk - 1) & 1) == 0) mbar_wait(sb + 8,  (uint32_t)(ph0 & 1));
    else                     mbar_wait(sb + 16, (uint32_t)(ph1 & 1));
    TC_FENCE_AFTER();

    // epilogue: warp (w&3) covers rows (w&3)*32+lane, warp (w>>2) covers col half
    int rw = wid & 3, cw = wid >> 2;
    uint32_t d0[32], d1[32];
    TC_LD_X32(d0, tmem + cw * 64);
    TC_LD_X32(d1, tmem + cw * 64 + 32);
    TC_WAIT_LD();
    TC_FENCE_BEFORE();

    int lrow = m0 + rw * 32 + lid;
    if (lrow < Me) {
        int cbase = n0 + cw * 64;
#pragma unroll
        for (int j = 0; j < 64; j++) {
            float v = __uint_as_float(j < 32 ? d0[j] : d1[j - 32]);
            store_elem<MODE>(e, N, lrow, cbase + j, v, Cf, Res, Ch, Cl);
        }
    }
    __syncthreads();
    if (wid == 0) { TC_DEALLOC(tmem, 128); }

#else
    // ---- SIMT fallback (base-arch pass; executes only if sm_103a SASS absent) ----
    float* As = (float*)sm;            // [16][128]
    float* Bs = As + 16 * 128;         // [16][128]
    int tx = tid & 15, ty = tid >> 4;
    float acc[8][8];
#pragma unroll
    for (int i = 0; i < 8; i++)
#pragma unroll
        for (int j = 0; j < 8; j++) acc[i][j] = 0.f;

    for (int k0 = 0; k0 < K; k0 += 16) {
        __syncthreads();
        for (int l = tid; l < 16 * 128; l += 256) {
            int kk = l >> 7, rr = l & 127;
            int gr = m0 + rr;
            float av = 0.f;
            if (gr < Me) {
                size_t ri;
                if (MODE == GM_MOE1)      ri = (size_t)g_rowlist[e * TT + gr];
                else if (MODE == GM_MOE2) ri = (size_t)e * TT + gr;
                else                      ri = (size_t)gr;
                av = __bfloat162float(Ah[ri * (size_t)K + k0 + kk])
                   + __bfloat162float(Al[ri * (size_t)K + k0 + kk]);
            }
            As[kk * 128 + rr] = av;
            Bs[kk * 128 + rr] = __bfloat162float(Bh[(size_t)(n0 + rr) * K + k0 + kk])
                              + __bfloat162float(Bl[(size_t)(n0 + rr) * K + k0 + kk]);
        }
        __syncthreads();
        for (int kk = 0; kk < 16; kk++) {
            float ar[8], br[8];
#pragma unroll
            for (int i = 0; i < 8; i++) ar[i] = As[kk * 128 + ty * 8 + i];
#pragma unroll
            for (int j = 0; j < 8; j++) br[j] = Bs[kk * 128 + tx * 8 + j];
#pragma unroll
            for (int i = 0; i < 8; i++)
#pragma unroll
                for (int j = 0; j < 8; j++) acc[i][j] = fmaf(ar[i], br[j], acc[i][j]);
        }
    }
#pragma unroll
    for (int i = 0; i < 8; i++) {
        int row = m0 + ty * 8 + i;
        if (row >= Me) continue;
#pragma unroll
        for (int j = 0; j < 8; j++)
            store_elem<MODE>(e, N, row, n0 + tx * 8 + j, acc[i][j], Cf, Res, Ch, Cl);
    }
#endif
#endif // __CUDA_ARCH__
}

// ---------------- flash attention (SIMT fp32, epilogue writes bf16 hi/lo) ----
#define ATTN_SMEM ((4 * 64 * 65 + 3 * 64) * 4)

__global__ void attn_kernel(const float* __restrict__ q, const float* __restrict__ k,
                            const float* __restrict__ v,
                            bf16* __restrict__ outh, bf16* __restrict__ outl)
{
    extern __shared__ float smf[];
    float* Qs   = smf;              // 64x65
    float* Ks   = Qs + 64 * 65;
    float* Vs   = Ks + 64 * 65;
    float* Ps   = Vs + 64 * 65;
    float* mrow = Ps + 64 * 65;
    float* lrow = mrow + 64;
    float* arow = lrow + 64;

    int bh = blockIdx.x;
    int qt = blockIdx.y;
    int tid = threadIdx.x;
    int tx = tid & 15, ty = tid >> 4;
    const float scale = 0.125f;

    const float* Qg = q + ((size_t)bh * SS + qt * 64) * DH;
    for (int i = tid; i < 64 * 64; i += 256) {
        int r = i >> 6, d = i & 63;
        Qs[r * 65 + d] = Qg[r * 64 + d] * scale;
    }
    if (tid < 64) { mrow[tid] = -1e30f; lrow[tid] = 0.f; }
    float acc[4][4];
#pragma unroll
    for (int i = 0; i < 4; i++)
#pragma unroll
        for (int j = 0; j < 4; j++) acc[i][j] = 0.f;
    __syncthreads();

    for (int kt = 0; kt < SS / 64; kt++) {
        const float* Kg = k + ((size_t)bh * SS + kt * 64) * DH;
        const float* Vg = v + ((size_t)bh * SS + kt * 64) * DH;
        for (int i = tid; i < 64 * 64; i += 256) {
            int r = i >> 6, d = i & 63;
            Ks[r * 65 + d] = Kg[r * 64 + d];
            Vs[r * 65 + d] = Vg[r * 64 + d];
        }
        __syncthreads();

        float sv[4][4];
#pragma unroll
        for (int i = 0; i < 4; i++)
#pragma unroll
            for (int j = 0; j < 4; j++) sv[i][j] = 0.f;
#pragma unroll 8
        for (int d = 0; d < 64; d++) {
            float ar[4], br[4];
#pragma unroll
            for (int i = 0; i < 4; i++) ar[i] = Qs[(ty * 4 + i) * 65 + d];
#pragma unroll
            for (int j = 0; j < 4; j++) br[j] = Ks[(tx * 4 + j) * 65 + d];
#pragma unroll
            for (int i = 0; i < 4; i++)
#pragma unroll
                for (int j = 0; j < 4; j++) sv[i][j] = fmaf(ar[i], br[j], sv[i][j]);
        }
#pragma unroll
        for (int i = 0; i < 4; i++)
#pragma unroll
            for (int j = 0; j < 4; j++)
                Ps[(ty * 4 + i) * 65 + tx * 4 + j] = sv[i][j];
        __syncthreads();

        if (tid < 64) {
            int rr = tid;
            float m = mrow[rr];
            float mx = m;
            for (int c = 0; c < 64; c++) mx = fmaxf(mx, Ps[rr * 65 + c]);
            float a = expf(m - mx);
            float sum = 0.f;
            for (int c = 0; c < 64; c++) {
                float p = expf(Ps[rr * 65 + c] - mx);
                Ps[rr * 65 + c] = p;
                sum += p;
            }
            lrow[rr] = lrow[rr] * a + sum;
            mrow[rr] = mx;
            arow[rr] = a;
        }
        __syncthreads();

#pragma unroll
        for (int i = 0; i < 4; i++) {
            float a = arow[ty * 4 + i];
#pragma unroll
            for (int j = 0; j < 4; j++) acc[i][j] *= a;
        }
#pragma unroll 8
        for (int kk = 0; kk < 64; kk++) {
            float pr[4], vr[4];
#pragma unroll
            for (int i = 0; i < 4; i++) pr[i] = Ps[(ty * 4 + i) * 65 + kk];
#pragma unroll
            for (int j = 0; j < 4; j++) vr[j] = Vs[kk * 65 + tx * 4 + j];
#pragma unroll
            for (int i = 0; i < 4; i++)
#pragma unroll
                for (int j = 0; j < 4; j++) acc[i][j] = fmaf(pr[i], vr[j], acc[i][j]);
        }
        __syncthreads();
    }

    int b = bh >> 4, h = bh & 15;
#pragma unroll
    for (int i = 0; i < 4; i++) {
        int rr = ty * 4 + i;
        float inv = 1.f / lrow[rr];
        int s = qt * 64 + rr;
#pragma unroll
        for (int j = 0; j < 4; j++) {
            int d = tx * 4 + j;
            size_t idx = ((size_t)(b * SS + s)) * DD + h * 64 + d;
            float val = acc[i][j] * inv;
            bf16 hh = __float2bfloat16(val);
            outh[idx] = hh;
            outl[idx] = __float2bfloat16(val - __bfloat162float(hh));
        }
    }
}

// ---------------- router ----------------
__global__ void zero_cnt_kernel() {
    if (threadIdx.x < NE) g_cnt[threadIdx.x] = 0;
}

__global__ void router_kernel(const float* __restrict__ xn2, const float* __restrict__ wr)
{
    int t = blockIdx.x;
    int lane = threadIdx.x;
    float p[NE];
#pragma unroll
    for (int e = 0; e < NE; e++) p[e] = 0.f;
    const float* xr = xn2 + (size_t)t * DD;
    for (int d = lane; d < DD; d += 32) {
        float xv = xr[d];
        const float* wrow = wr + (size_t)d * NE;
#pragma unroll
        for (int e = 0; e < NE; e++) p[e] = fmaf(xv, wrow[e], p[e]);
    }
#pragma unroll
    for (int e = 0; e < NE; e++) {
        for (int o = 16; o > 0; o >>= 1) p[e] += __shfl_xor_sync(0xffffffffu, p[e], o);
    }
    if (lane == 0) {
        float m = p[0];
#pragma unroll
        for (int e = 1; e < NE; e++) m = fmaxf(m, p[e]);
        float pr[NE];
        float sum = 0.f;
#pragma unroll
        for (int e = 0; e < NE; e++) { pr[e] = expf(p[e] - m); sum += pr[e]; }
        float inv = 1.f / sum;
#pragma unroll
        for (int e = 0; e < NE; e++) pr[e] *= inv;
        g_zz[t] = m + logf(sum);
#pragma unroll
        for (int e = 0; e < NE; e++) g_probs[t * NE + e] = pr[e];
        int i0 = 0; float v0 = pr[0];
#pragma unroll
        for (int e = 1; e < NE; e++) if (pr[e] > v0) { v0 = pr[e]; i0 = e; }
        int i1 = -1; float v1 = -1.f;
#pragma unroll
        for (int e = 0; e < NE; e++) { if (e == i0) continue; if (pr[e] > v1) { v1 = pr[e]; i1 = e; } }
        float wsum = v0 + v1;
        float w0 = v0 / wsum, w1 = v1 / wsum;
        int r0 = atomicAdd(&g_cnt[i0], 1); g_rowlist[i0 * TT + r0] = t;
        int r1 = atomicAdd(&g_cnt[i1], 1); g_rowlist[i1 * TT + r1] = t;
        g_slot_e[2 * t]     = i0; g_slot_r[2 * t]     = r0; g_slot_w[2 * t]     = w0;
        g_slot_e[2 * t + 1] = i1; g_slot_r[2 * t + 1] = r1; g_slot_w[2 * t + 1] = w1;
    }
}

// ---------------- loss (deterministic tree reduction) ----------------
__global__ void loss_kernel(float* __restrict__ out, int out_size)
{
    int tid = threadIdx.x;
    __shared__ float red[256];
    __shared__ float sumsp[NE];
    __shared__ float sumz;
    float accp[NE];
#pragma unroll
    for (int e = 0; e < NE; e++) accp[e] = 0.f;
    float accz = 0.f;
    for (int t = tid; t < TT; t += 256) {
        float z = g_zz[t];
        accz += z * z;
#pragma unroll
        for (int e = 0; e < NE; e++) accp[e] += g_probs[t * NE + e];
    }
    red[tid] = accz; __syncthreads();
    for (int o = 128; o > 0; o >>= 1) { if (tid < o) red[tid] += red[tid + o]; __syncthreads(); }
    if (tid == 0) sumz = red[0];
    __syncthreads();
    for (int e = 0; e < NE; e++) {
        red[tid] = accp[e]; __syncthreads();
        for (int o = 128; o > 0; o >>= 1) { if (tid < o) red[tid] += red[tid + o]; __syncthreads(); }
        if (tid == 0) sumsp[e] = red[0];
        __syncthreads();
    }
    if (tid == 0) {
        float aux = 0.f;
        for (int e = 0; e < NE; e++) {
            float ft = (float)g_cnt[e] / (float)TT;
            float fp = sumsp[e] / (float)TT;
            aux += ft * fp;
        }
        aux *= (float)NE / 2.f;
        float loss = aux + 0.001f * (sumz / (float)TT);
        for (int i = NMAIN; i < out_size; i++) out[i] = loss;
    }
}

// ---------------- combine ----------------
__global__ void combine_kernel(float* __restrict__ out)
{
    int idx = blockIdx.x * 256 + threadIdx.x;
    if (idx >= NMAIN) return;
    int t = idx >> 10;
    int d = idx & 1023;
    int e0 = g_slot_e[2 * t], r0 = g_slot_r[2 * t];
    int e1 = g_slot_e[2 * t + 1], r1 = g_slot_r[2 * t + 1];
    float w0 = g_slot_w[2 * t], w1 = g_slot_w[2 * t + 1];
    float y = g_x2[idx]
            + w0 * g_Y[((size_t)e0 * TT + r0) * DD + d]
            + w1 * g_Y[((size_t)e1 * TT + r1) * DD + d];
    out[idx] = y;
}

// ---------------- launch ----------------
extern "C" void kernel_launch(void* const* d_in, const int* in_sizes, int n_in,
                              void* d_out, int out_size)
{
    const float* x   = (const float*)d_in[0];
    const float* ln1 = (const float*)d_in[1];
    const float* ln2 = (const float*)d_in[2];
    const float* wq  = (const float*)d_in[3];
    const float* wk  = (const float*)d_in[4];
    const float* wv  = (const float*)d_in[5];
    const float* wo  = (const float*)d_in[6];
    const float* wr  = (const float*)d_in[7];
    const float* w1  = (const float*)d_in[8];
    const float* w2  = (const float*)d_in[9];
    float* out = (float*)d_out;

    cudaFuncSetAttribute(attn_kernel, cudaFuncAttributeMaxDynamicSharedMemorySize, ATTN_SMEM);
    cudaFuncSetAttribute(tc_gemm<GM_QKV>,  cudaFuncAttributeMaxDynamicSharedMemorySize, G_SMEM);
    cudaFuncSetAttribute(tc_gemm<GM_RES>,  cudaFuncAttributeMaxDynamicSharedMemorySize, G_SMEM);
    cudaFuncSetAttribute(tc_gemm<GM_MOE1>, cudaFuncAttributeMaxDynamicSharedMemorySize, G_SMEM);
    cudaFuncSetAttribute(tc_gemm<GM_MOE2>, cudaFuncAttributeMaxDynamicSharedMemorySize, G_SMEM);

    bf16 *p_xnh, *p_xnl, *p_xn2h, *p_xn2l, *p_ctxh, *p_ctxl;
    bf16 *p_wpth, *p_wptl, *p_w1th, *p_w1tl, *p_w2th, *p_w2tl, *p_Hh, *p_Hl;
    float *p_xn2, *p_qkv, *p_x2, *p_Y;
    cudaGetSymbolAddress((void**)&p_xnh,  g_xnh);
    cudaGetSymbolAddress((void**)&p_xnl,  g_xnl);
    cudaGetSymbolAddress((void**)&p_xn2,  g_xn2);
    cudaGetSymbolAddress((void**)&p_xn2h, g_xn2h);
    cudaGetSymbolAddress((void**)&p_xn2l, g_xn2l);
    cudaGetSymbolAddress((void**)&p_qkv,  g_qkv);
    cudaGetSymbolAddress((void**)&p_ctxh, g_ctxh);
    cudaGetSymbolAddress((void**)&p_ctxl, g_ctxl);
    cudaGetSymbolAddress((void**)&p_x2,   g_x2);
    cudaGetSymbolAddress((void**)&p_wpth, g_wpth);
    cudaGetSymbolAddress((void**)&p_wptl, g_wptl);
    cudaGetSymbolAddress((void**)&p_w1th, g_w1th);
    cudaGetSymbolAddress((void**)&p_w1tl, g_w1tl);
    cudaGetSymbolAddress((void**)&p_w2th, g_w2th);
    cudaGetSymbolAddress((void**)&p_w2tl, g_w2tl);
    cudaGetSymbolAddress((void**)&p_Hh,   g_Hh);
    cudaGetSymbolAddress((void**)&p_Hl,   g_Hl);
    cudaGetSymbolAddress((void**)&p_Y,    g_Y);

    // 0. weight transpose + bf16 split
    dim3 bt(32, 8);
    wt_convert_kernel<<<dim3(DD/32, DD/32, 1), bt>>>(wq, p_wpth,           p_wptl,           DD, DD);
    wt_convert_kernel<<<dim3(DD/32, DD/32, 1), bt>>>(wk, p_wpth + DD*DD,   p_wptl + DD*DD,   DD, DD);
    wt_convert_kernel<<<dim3(DD/32, DD/32, 1), bt>>>(wv, p_wpth + 2*DD*DD, p_wptl + 2*DD*DD, DD, DD);
    wt_convert_kernel<<<dim3(DD/32, DD/32, 1), bt>>>(wo, p_wpth + 3*DD*DD, p_wptl + 3*DD*DD, DD, DD);
    wt_convert_kernel<<<dim3(FF/32, DD/32, NE), bt>>>(w1, p_w1th, p_w1tl, DD, FF);
    wt_convert_kernel<<<dim3(DD/32, FF/32, NE), bt>>>(w2, p_w2th, p_w2tl, FF, DD);

    // 1. rmsnorm 1 (bf16 split only)
    rmsnorm_kernel<<<TT, 256>>>(x, ln1, nullptr, p_xnh, p_xnl);

    // 2. QKV projections (z selects wq/wk/wv; scatter to [B,H,S,Dh])
    tc_gemm<GM_QKV><<<dim3(DD/128, TT/128, 3), 256, G_SMEM>>>(
        p_xnh, p_xnl, p_wpth, p_wptl, p_qkv, nullptr, nullptr, nullptr, TT, DD, DD);

    // 3. attention (fp32 SIMT) -> ctx bf16 split
    attn_kernel<<<dim3(BB * NH, SS / 64), 256, ATTN_SMEM>>>(
        p_qkv, p_qkv + (size_t)TT * DD, p_qkv + 2 * (size_t)TT * DD, p_ctxh, p_ctxl);

    // 4. output projection + residual
    tc_gemm<GM_RES><<<dim3(DD/128, TT/128, 1), 256, G_SMEM>>>(
        p_ctxh, p_ctxl, p_wpth + 3*DD*DD, p_wptl + 3*DD*DD, p_x2, x, nullptr, nullptr, TT, DD, DD);

    // 5. rmsnorm 2 (fp32 + bf16 split)
    rmsnorm_kernel<<<TT, 256>>>(p_x2, ln2, p_xn2, p_xn2h, p_xn2l);

    // 6. router
    zero_cnt_kernel<<<1, 32>>>();
    router_kernel<<<TT, 32>>>(p_xn2, wr);

    // 7. loss scalar -> out[NMAIN..]
    loss_kernel<<<1, 256>>>(out, out_size);

    // 8. MoE expert GEMMs (grouped; tiles beyond per-expert count early-exit)
    tc_gemm<GM_MOE1><<<dim3(FF/128, TT/128, NE), 256, G_SMEM>>>(
        p_xn2h, p_xn2l, p_w1th, p_w1tl, nullptr, nullptr, p_Hh, p_Hl, TT, FF, DD);
    tc_gemm<GM_MOE2><<<dim3(DD/128, TT/128, NE), 256, G_SMEM>>>(
        p_Hh, p_Hl, p_w2th, p_w2tl, p_Y, nullptr, nullptr, nullptr, TT, DD, FF);

    // 9. combine + residual -> out
    combine_kernel<<<(NMAIN + 255) / 256, 256>>>(out);
}

// round 5
// speedup vs baseline: 2.2099x; 1.4761x over previous
#include <cuda_runtime.h>
#include <cuda_bf16.h>
#include <math.h>
#include <stdint.h>

#define BB 2
#define SS 2048
#define DD 1024
#define NH 16
#define DH 64
#define NE 8
#define FF 4096
#define TT (BB*SS)   // 4096 tokens
#define NMAIN (TT*DD)

typedef __nv_bfloat16 bf16;

// ---------------- scratch (static device globals; no cudaMalloc allowed) ----
__device__ bf16  g_xnh[TT*DD],  g_xnl[TT*DD];          // rmsnorm1 out, split
__device__ float g_xn2[TT*DD];                          // rmsnorm2 out fp32 (router)
__device__ bf16  g_xn2h[TT*DD], g_xn2l[TT*DD];          // rmsnorm2 out, split
__device__ bf16  g_qkvh[3][(size_t)TT*DD];              // q,k,v hi  [B,H,S,Dh]
__device__ bf16  g_qkvl[3][(size_t)TT*DD];              // q,k,v lo  [B,H,S,Dh]
__device__ bf16  g_ctxh[TT*DD], g_ctxl[TT*DD];          // attention ctx, split
__device__ float g_x2[TT*DD];                           // x + attn_out
__device__ bf16  g_wpth[4*DD*DD], g_wptl[4*DD*DD];      // wq,wk,wv,wo transposed split
__device__ bf16  g_w1th[(size_t)NE*DD*FF], g_w1tl[(size_t)NE*DD*FF];
__device__ bf16  g_w2th[(size_t)NE*DD*FF], g_w2tl[(size_t)NE*DD*FF];
__device__ bf16  g_Hh[(size_t)NE*TT*FF], g_Hl[(size_t)NE*TT*FF];  // gelu(h) split
__device__ float g_Y[(size_t)NE*TT*DD];
__device__ float g_probs[TT*NE];
__device__ float g_zz[TT];
__device__ int   g_cnt[NE];
__device__ int   g_rowlist[NE*TT];
__device__ int   g_slot_e[2*TT];
__device__ int   g_slot_r[2*TT];
__device__ float g_slot_w[2*TT];

// ---------------- PTX helpers ----------------
__device__ __forceinline__ uint32_t smem_u32(const void* p) {
    uint32_t a;
    asm("{ .reg .u64 t; cvta.to.shared.u64 t, %1; cvt.u32.u64 %0, t; }" : "=r"(a) : "l"(p));
    return a;
}
__device__ __forceinline__ uint32_t elect1() {
    uint32_t p;
    asm volatile("{\n.reg .pred p;\nelect.sync _|p, 0xFFFFFFFF;\nselp.b32 %0, 1, 0, p;\n}" : "=r"(p));
    return p;
}
__device__ __forceinline__ void mbar_init(uint32_t a, uint32_t n) {
    asm volatile("mbarrier.init.shared.b64 [%0], %1;" :: "r"(a), "r"(n) : "memory");
}
__device__ __forceinline__ void mbar_wait(uint32_t a, uint32_t par) {
    asm volatile(
        "{\n.reg .pred P;\n"
        "LW%=:\n"
        "mbarrier.try_wait.parity.acquire.cta.shared::cta.b64 P, [%0], %1, 0x989680;\n"
        "@P bra LD%=;\n"
        "bra LW%=;\n"
        "LD%=:\n}"
        :: "r"(a), "r"(par) : "memory");
}
// K-major SW128 descriptor (row = 128B)
__device__ __forceinline__ uint64_t mk_desc(uint32_t addr) {
    return ((uint64_t)2 << 61) | ((uint64_t)1 << 46) | ((uint64_t)64 << 32)
         | ((uint64_t)1 << 16) | ((addr >> 4) & 0x3FFF);
}
__device__ __forceinline__ void tc_commit(uint32_t mbar) {
#if defined(__CUDA_ARCH_FEAT_SM103_ALL)
    asm volatile("tcgen05.commit.cta_group::1.mbarrier::arrive::one.shared::cluster.b64 [%0];"
                 :: "r"(mbar) : "memory");
#endif
}
__device__ __forceinline__ void mma_f16_ss(uint32_t d, uint64_t ad, uint64_t bd,
                                           uint32_t idesc, uint32_t en) {
#if defined(__CUDA_ARCH_FEAT_SM103_ALL)
    asm volatile(
        "{\n.reg .pred p;\n"
        "setp.ne.u32 p, %4, 0;\n"
        "tcgen05.mma.cta_group::1.kind::f16 [%0], %1, %2, %3, {%5, %5, %5, %5}, p;\n}"
        :: "r"(d), "l"(ad), "l"(bd), "r"(idesc), "r"(en), "r"(0u) : "memory");
#endif
}

#if defined(__CUDA_ARCH_FEAT_SM103_ALL)
#define TC_ALLOC(sbaddr, n) \
    asm volatile("tcgen05.alloc.cta_group::1.sync.aligned.shared::cta.b32 [%0], %1;" \
                 :: "r"(sbaddr), "r"((uint32_t)(n)) : "memory")
#define TC_RELINQ() \
    asm volatile("tcgen05.relinquish_alloc_permit.cta_group::1.sync.aligned;")
#define TC_DEALLOC(t, n) \
    asm volatile("tcgen05.dealloc.cta_group::1.sync.aligned.b32 %0, %1;" :: "r"(t), "r"((uint32_t)(n)))
#define TC_FENCE_AFTER()  asm volatile("tcgen05.fence::after_thread_sync;" ::: "memory")
#define TC_FENCE_BEFORE() asm volatile("tcgen05.fence::before_thread_sync;" ::: "memory")
#define TC_WAIT_LD()      asm volatile("tcgen05.wait::ld.sync.aligned;" ::: "memory")
#define TC_LD_X32(r, ta) \
    asm volatile( \
        "tcgen05.ld.sync.aligned.32x32b.x32.b32 " \
        "{%0, %1, %2, %3, %4, %5, %6, %7, " \
        " %8, %9, %10, %11, %12, %13, %14, %15, " \
        " %16, %17, %18, %19, %20, %21, %22, %23, " \
        " %24, %25, %26, %27, %28, %29, %30, %31}, [%32];" \
        : "=r"((r)[0]),  "=r"((r)[1]),  "=r"((r)[2]),  "=r"((r)[3]), \
          "=r"((r)[4]),  "=r"((r)[5]),  "=r"((r)[6]),  "=r"((r)[7]), \
          "=r"((r)[8]),  "=r"((r)[9]),  "=r"((r)[10]), "=r"((r)[11]), \
          "=r"((r)[12]), "=r"((r)[13]), "=r"((r)[14]), "=r"((r)[15]), \
          "=r"((r)[16]), "=r"((r)[17]), "=r"((r)[18]), "=r"((r)[19]), \
          "=r"((r)[20]), "=r"((r)[21]), "=r"((r)[22]), "=r"((r)[23]), \
          "=r"((r)[24]), "=r"((r)[25]), "=r"((r)[26]), "=r"((r)[27]), \
          "=r"((r)[28]), "=r"((r)[29]), "=r"((r)[30]), "=r"((r)[31]) \
        : "r"(ta))
#endif

__device__ __forceinline__ float gelu_tanh(float x) {
    float x3 = x * x * x;
    return 0.5f * x * (1.f + tanhf(0.7978845608028654f * (x + 0.044715f * x3)));
}
__device__ __forceinline__ uint32_t pack_bf2(float a, float b) {
    return ((uint32_t)__bfloat16_as_ushort(__float2bfloat16(b)) << 16)
         |  (uint32_t)__bfloat16_as_ushort(__float2bfloat16(a));
}

// ---------------- rmsnorm (writes fp32 optional + bf16 hi/lo) ----------------
__global__ void rmsnorm_kernel(const float* __restrict__ x, const float* __restrict__ w,
                               float* __restrict__ yf, bf16* __restrict__ yh, bf16* __restrict__ yl)
{
    int row = blockIdx.x;
    int tid = threadIdx.x;
    const float* xr = x + (size_t)row * DD;
    float s = 0.f;
    for (int d = tid; d < DD; d += 256) { float v = xr[d]; s += v * v; }
    __shared__ float red[256];
    red[tid] = s; __syncthreads();
    for (int o = 128; o > 0; o >>= 1) { if (tid < o) red[tid] += red[tid + o]; __syncthreads(); }
    float inv = rsqrtf(red[0] / (float)DD + 1e-6f);
    size_t base = (size_t)row * DD;
    for (int d = tid; d < DD; d += 256) {
        float v = xr[d] * inv * w[d];
        if (yf) yf[base + d] = v;
        bf16 h = __float2bfloat16(v);
        yh[base + d] = h;
        yl[base + d] = __float2bfloat16(v - __bfloat162float(h));
    }
}

// ---------------- weight transpose + bf16 split (vectorized) ----------------
__global__ void wt_convert_kernel(const float* __restrict__ W,
                                  bf16* __restrict__ Th, bf16* __restrict__ Tl,
                                  int K, int N)
{
    __shared__ float tile[64][68];
    size_t zoff = (size_t)blockIdx.z * K * N;
    int n0 = blockIdx.x * 64, k0 = blockIdx.y * 64;
    int tx = threadIdx.x & 15, ty = threadIdx.x >> 4;   // 16x16
#pragma unroll
    for (int i = 0; i < 4; i++) {
        int r = ty + 16 * i;
        float4 v = *(const float4*)(W + zoff + (size_t)(k0 + r) * N + n0 + tx * 4);
        *(float4*)&tile[r][tx * 4] = v;
    }
    __syncthreads();
#pragma unroll
    for (int i = 0; i < 4; i++) {
        int n = ty + 16 * i;
        int kk = tx * 4;
        float v0 = tile[kk + 0][n], v1 = tile[kk + 1][n];
        float v2 = tile[kk + 2][n], v3 = tile[kk + 3][n];
        bf16 h0 = __float2bfloat16(v0), h1 = __float2bfloat16(v1);
        bf16 h2 = __float2bfloat16(v2), h3 = __float2bfloat16(v3);
        float l0 = v0 - __bfloat162float(h0), l1 = v1 - __bfloat162float(h1);
        float l2 = v2 - __bfloat162float(h2), l3 = v3 - __bfloat162float(h3);
        size_t idx = zoff + (size_t)(n0 + n) * K + k0 + kk;
        uint2 ph, pl;
        ph.x = ((uint32_t)__bfloat16_as_ushort(h1) << 16) | __bfloat16_as_ushort(h0);
        ph.y = ((uint32_t)__bfloat16_as_ushort(h3) << 16) | __bfloat16_as_ushort(h2);
        pl.x = pack_bf2(l0, l1);
        pl.y = pack_bf2(l2, l3);
        *(uint2*)(Th + idx) = ph;
        *(uint2*)(Tl + idx) = pl;
    }
}

// ---------------- GEMM modes ----------------
#define GM_QKV  1
#define GM_RES  2
#define GM_MOE1 3
#define GM_MOE2 4
#define G_SMEM  (1024 + 2 * 4 * 16384)   // 132096 B

// scalar store (fallback path only)
template<int MODE>
__device__ __forceinline__ void store_elem(int e, int N, int row, int col, float v,
        float* __restrict__ Cf, const float* __restrict__ Res,
        bf16* __restrict__ Ch, bf16* __restrict__ Cl)
{
    if (MODE == GM_QKV) {
        int b = row >> 11, s5 = row & (SS - 1);
        int h = col >> 6, dh = col & 63;
        size_t o = (((size_t)(b * NH + h)) * SS + s5) * DH + dh;
        bf16 hh = __float2bfloat16(v);
        g_qkvh[e][o] = hh;
        g_qkvl[e][o] = __float2bfloat16(v - __bfloat162float(hh));
    } else if (MODE == GM_RES) {
        size_t o = (size_t)row * N + col;
        Cf[o] = v + Res[o];
    } else if (MODE == GM_MOE1) {
        size_t o = ((size_t)e * TT + row) * N + col;
        float g = gelu_tanh(v);
        bf16 h = __float2bfloat16(g);
        Ch[o] = h;
        Cl[o] = __float2bfloat16(g - __bfloat162float(h));
    } else {
        Cf[((size_t)e * TT + row) * N + col] = v;
    }
}

// ---------------- tcgen05 GEMM: C[128x128] tiles, 3-term bf16 split ----------
template<int MODE>
__global__ void __launch_bounds__(256, 1)
tc_gemm(const bf16* __restrict__ Ah, const bf16* __restrict__ Al,
        const bf16* __restrict__ Bh0, const bf16* __restrict__ Bl0,
        float* __restrict__ Cf, const float* __restrict__ Res,
        bf16* __restrict__ Ch, bf16* __restrict__ Cl,
        int M, int N, int K)
{
#if defined(__CUDA_ARCH__)
    extern __shared__ char sm[];
    int tid = threadIdx.x;
    int e  = blockIdx.z;
    int m0 = blockIdx.y * 128, n0 = blockIdx.x * 128;
    int Me = M;
    const bf16* Bh = Bh0;
    const bf16* Bl = Bl0;
    if (MODE == GM_MOE1 || MODE == GM_MOE2) {
        Me = g_cnt[e];
        if (m0 >= Me) return;
        Bh += (size_t)e * (size_t)K * N; Bl += (size_t)e * (size_t)K * N;
    } else if (MODE == GM_QKV) {
        Bh += (size_t)e * (size_t)K * N; Bl += (size_t)e * (size_t)K * N;
    }

#if defined(__CUDA_ARCH_FEAT_SM103_ALL)
    uint32_t sb = smem_u32(sm);
    int wid = tid >> 5, lid = tid & 31;

    if (wid == 0) { TC_ALLOC(sb, 128); TC_RELINQ(); }
    if (tid == 0) { mbar_init(sb + 8, 1); mbar_init(sb + 16, 1); }
    __syncthreads();
    uint32_t tmem;
    asm volatile("ld.shared.b32 %0, [%1];" : "=r"(tmem) : "r"(sb));

    // loader assignment: threads 0-127 -> A rows, 128-255 -> B rows
    int r = tid & 127;
    bool valid = true;
    const bf16* rowH = nullptr;
    const bf16* rowL = nullptr;
    if (tid < 128) {
        int gr = m0 + r;
        valid = gr < Me;
        if (valid) {
            size_t ri;
            if (MODE == GM_MOE1)      ri = (size_t)g_rowlist[e * TT + gr];
            else if (MODE == GM_MOE2) ri = (size_t)e * TT + gr;
            else                      ri = (size_t)gr;
            rowH = Ah + ri * (size_t)K;
            rowL = Al + ri * (size_t)K;
        }
    } else {
        rowH = Bh + (size_t)(n0 + r) * K;
        rowL = Bl + (size_t)(n0 + r) * K;
    }

    const uint32_t IDESC = (1u << 4) | (1u << 7) | (1u << 10) | (16u << 17) | (8u << 24);
    int nk = K / 64;
    int ph0 = 0, ph1 = 0;
    for (int kc = 0; kc < nk; kc++) {
        int bufi = kc & 1;
        if (kc >= 2) {
            if (bufi == 0) { mbar_wait(sb + 8,  (uint32_t)(ph0 & 1)); ph0++; }
            else           { mbar_wait(sb + 16, (uint32_t)(ph1 & 1)); ph1++; }
        }
        char* tb = sm + 1024 + bufi * 65536 + (tid < 128 ? 0 : 32768);
        {
            const uint4* srcH = (const uint4*)(rowH + kc * 64);
            const uint4* srcL = (const uint4*)(rowL + kc * 64);
#pragma unroll
            for (int j = 0; j < 8; j++) {
                uint32_t off = (uint32_t)r * 128u + j * 16u;
                uint32_t sw = off ^ ((off >> 3) & 0x70);
                uint4 vh = valid ? srcH[j] : make_uint4(0, 0, 0, 0);
                uint4 vl = valid ? srcL[j] : make_uint4(0, 0, 0, 0);
                *(uint4*)(tb + sw)         = vh;
                *(uint4*)(tb + 16384 + sw) = vl;
            }
        }
        asm volatile("fence.proxy.async.shared::cta;" ::: "memory");
        __syncthreads();
        if (wid == 0 && elect1()) {
            uint32_t base = sb + 1024 + bufi * 65536;
            uint64_t dAh = mk_desc(base);
            uint64_t dAl = mk_desc(base + 16384);
            uint64_t dBh = mk_desc(base + 32768);
            uint64_t dBl = mk_desc(base + 49152);
#pragma unroll
            for (int s = 0; s < 4; s++) {
                uint32_t en0 = (kc == 0 && s == 0) ? 0u : 1u;
                mma_f16_ss(tmem, dAh + 2 * s, dBh + 2 * s, IDESC, en0);
                mma_f16_ss(tmem, dAh + 2 * s, dBl + 2 * s, IDESC, 1u);
                mma_f16_ss(tmem, dAl + 2 * s, dBh + 2 * s, IDESC, 1u);
            }
            tc_commit(sb + 8 + bufi * 8);
        }
    }
    if (((nk - 1) & 1) == 0) mbar_wait(sb + 8,  (uint32_t)(ph0 & 1));
    else                     mbar_wait(sb + 16, (uint32_t)(ph1 & 1));
    TC_FENCE_AFTER();

    // ---- staged epilogue: TMEM -> smem (fp32, 128x129) -> coalesced global ----
    int rw = wid & 3, cw = wid >> 2;
    uint32_t d0[32], d1[32];
    TC_LD_X32(d0, tmem + cw * 64);
    TC_LD_X32(d1, tmem + cw * 64 + 32);
    TC_WAIT_LD();
    TC_FENCE_BEFORE();
    __syncthreads();   // all MMAs done; buffers reusable as staging

    float* Cs = (float*)(sm + 1024);
    {
        int rr = rw * 32 + lid;
        int cb = cw * 64;
#pragma unroll
        for (int j = 0; j < 32; j++) {
            Cs[rr * 129 + cb + j]      = __uint_as_float(d0[j]);
            Cs[rr * 129 + cb + 32 + j] = __uint_as_float(d1[j]);
        }
    }
    __syncthreads();
    int rows_here = Me - m0; if (rows_here > 128) rows_here = 128;
#pragma unroll 4
    for (int it = 0; it < 16; it++) {
        int idx4 = (it * 256 + tid) * 4;
        int rr = idx4 >> 7, cc = idx4 & 127;
        if (rr >= rows_here) continue;
        float v0 = Cs[rr * 129 + cc + 0];
        float v1 = Cs[rr * 129 + cc + 1];
        float v2 = Cs[rr * 129 + cc + 2];
        float v3 = Cs[rr * 129 + cc + 3];
        if (MODE == GM_RES) {
            size_t o = (size_t)(m0 + rr) * N + n0 + cc;
            float4 rs = *(const float4*)(Res + o);
            float4 w4 = make_float4(v0 + rs.x, v1 + rs.y, v2 + rs.z, v3 + rs.w);
            *(float4*)(Cf + o) = w4;
        } else if (MODE == GM_MOE2) {
            size_t o = ((size_t)e * TT + m0 + rr) * N + n0 + cc;
            *(float4*)(Cf + o) = make_float4(v0, v1, v2, v3);
        } else if (MODE == GM_MOE1) {
            size_t o = ((size_t)e * TT + m0 + rr) * N + n0 + cc;
            float g0 = gelu_tanh(v0), g1 = gelu_tanh(v1);
            float g2 = gelu_tanh(v2), g3 = gelu_tanh(v3);
            bf16 h0 = __float2bfloat16(g0), h1 = __float2bfloat16(g1);
            bf16 h2 = __float2bfloat16(g2), h3 = __float2bfloat16(g3);
            uint2 ph, pl;
            ph.x = ((uint32_t)__bfloat16_as_ushort(h1) << 16) | __bfloat16_as_ushort(h0);
            ph.y = ((uint32_t)__bfloat16_as_ushort(h3) << 16) | __bfloat16_as_ushort(h2);
            pl.x = pack_bf2(g0 - __bfloat162float(h0), g1 - __bfloat162float(h1));
            pl.y = pack_bf2(g2 - __bfloat162float(h2), g3 - __bfloat162float(h3));
            *(uint2*)(Ch + o) = ph;
            *(uint2*)(Cl + o) = pl;
        } else { // GM_QKV -> bf16 hi/lo [B,H,S,Dh]
            int row = m0 + rr, col = n0 + cc;
            int b = row >> 11, s5 = row & (SS - 1);
            int h = col >> 6, dh = col & 63;
            size_t o = (((size_t)(b * NH + h)) * SS + s5) * DH + dh;
            bf16 h0 = __float2bfloat16(v0), h1 = __float2bfloat16(v1);
            bf16 h2 = __float2bfloat16(v2), h3 = __float2bfloat16(v3);
            uint2 ph, pl;
            ph.x = ((uint32_t)__bfloat16_as_ushort(h1) << 16) | __bfloat16_as_ushort(h0);
            ph.y = ((uint32_t)__bfloat16_as_ushort(h3) << 16) | __bfloat16_as_ushort(h2);
            pl.x = pack_bf2(v0 - __bfloat162float(h0), v1 - __bfloat162float(h1));
            pl.y = pack_bf2(v2 - __bfloat162float(h2), v3 - __bfloat162float(h3));
            *(uint2*)(g_qkvh[e] + o) = ph;
            *(uint2*)(g_qkvl[e] + o) = pl;
        }
    }
    __syncthreads();
    if (wid == 0) { TC_DEALLOC(tmem, 128); }

#else
    // ---- SIMT fallback (base-arch pass) ----
    float* As = (float*)sm;
    float* Bs = As + 16 * 128;
    int tx = tid & 15, ty = tid >> 4;
    float acc[8][8];
#pragma unroll
    for (int i = 0; i < 8; i++)
#pragma unroll
        for (int j = 0; j < 8; j++) acc[i][j] = 0.f;

    for (int k0 = 0; k0 < K; k0 += 16) {
        __syncthreads();
        for (int l = tid; l < 16 * 128; l += 256) {
            int kk = l >> 7, rr = l & 127;
            int gr = m0 + rr;
            float av = 0.f;
            if (gr < Me) {
                size_t ri;
                if (MODE == GM_MOE1)      ri = (size_t)g_rowlist[e * TT + gr];
                else if (MODE == GM_MOE2) ri = (size_t)e * TT + gr;
                else                      ri = (size_t)gr;
                av = __bfloat162float(Ah[ri * (size_t)K + k0 + kk])
                   + __bfloat162float(Al[ri * (size_t)K + k0 + kk]);
            }
            As[kk * 128 + rr] = av;
            Bs[kk * 128 + rr] = __bfloat162float(Bh[(size_t)(n0 + rr) * K + k0 + kk])
                              + __bfloat162float(Bl[(size_t)(n0 + rr) * K + k0 + kk]);
        }
        __syncthreads();
        for (int kk = 0; kk < 16; kk++) {
            float ar[8], br[8];
#pragma unroll
            for (int i = 0; i < 8; i++) ar[i] = As[kk * 128 + ty * 8 + i];
#pragma unroll
            for (int j = 0; j < 8; j++) br[j] = Bs[kk * 128 + tx * 8 + j];
#pragma unroll
            for (int i = 0; i < 8; i++)
#pragma unroll
                for (int j = 0; j < 8; j++) acc[i][j] = fmaf(ar[i], br[j], acc[i][j]);
        }
    }
#pragma unroll
    for (int i = 0; i < 8; i++) {
        int row = m0 + ty * 8 + i;
        if (row >= Me) continue;
#pragma unroll
        for (int j = 0; j < 8; j++)
            store_elem<MODE>(e, N, row, n0 + tx * 8 + j, acc[i][j], Cf, Res, Ch, Cl);
    }
#endif
#endif // __CUDA_ARCH__
}

// ---------------- tcgen05 flash attention --------------------------------
// grid (B*NH, SS/128); 256 threads; Q tile 128 rows; K chunks of 128.
// V explicitly transposed in smem (no TransB). No running max (bounded scores).
#define SM_Q   1024
#define SM_K   33792
#define SM_VST 66560
#define SM_VT  99328
#define SM_P   132096
#define ATT_SMEM 197632

__global__ void __launch_bounds__(256, 1)
tc_attn(bf16* __restrict__ outh, bf16* __restrict__ outl)
{
#if defined(__CUDA_ARCH__)
    extern __shared__ char sm[];
    int tid = threadIdx.x;
    int bh = blockIdx.x;
    int qt = blockIdx.y;

#if defined(__CUDA_ARCH_FEAT_SM103_ALL)
    uint32_t sb = smem_u32(sm);
    int wid = tid >> 5, lane = tid & 31;

    if (wid == 0) { TC_ALLOC(sb, 256); TC_RELINQ(); }
    if (tid == 0) { mbar_init(sb + 8, 1); mbar_init(sb + 16, 1); }
    __syncthreads();
    uint32_t tmem;
    asm volatile("ld.shared.b32 %0, [%1];" : "=r"(tmem) : "r"(sb));

    // load Q tile (hi/lo): threads 0-127 hi rows, 128-255 lo rows
    {
        int r = tid & 127;
        const bf16* src = (tid < 128 ? g_qkvh[0] : g_qkvl[0])
                        + ((size_t)bh * SS + qt * 128 + r) * DH;
        char* dst = sm + SM_Q + (tid < 128 ? 0 : 16384);
        const uint4* s4 = (const uint4*)src;
#pragma unroll
        for (int j = 0; j < 8; j++) {
            uint32_t off = (uint32_t)r * 128u + j * 16u;
            uint32_t swz = off ^ ((off >> 3) & 0x70);
            *(uint4*)(dst + swz) = s4[j];
        }
    }

    const uint32_t IDESC_S = (1u << 4) | (1u << 7) | (1u << 10) | (16u << 17) | (8u << 24);
    const uint32_t IDESC_O = (1u << 4) | (1u << 7) | (1u << 10) | (8u << 17) | (8u << 24);
    int sph = 0, oph = 0;
    float lpart = 0.f;

    for (int kt = 0; kt < SS / 128; kt++) {
        if (kt > 0) { mbar_wait(sb + 16, (uint32_t)(oph & 1)); oph++; }  // prev PV done
        // load K (swizzled) + V (linear staging), hi/lo: 512 row-tasks
#pragma unroll
        for (int i = 0; i < 2; i++) {
            int task = tid + i * 256;
            int arr = task >> 7, r = task & 127;
            const bf16* src;
            char* dst;
            if (arr == 0)      { src = g_qkvh[1]; dst = sm + SM_K; }
            else if (arr == 1) { src = g_qkvl[1]; dst = sm + SM_K + 16384; }
            else if (arr == 2) { src = g_qkvh[2]; dst = sm + SM_VST; }
            else               { src = g_qkvl[2]; dst = sm + SM_VST + 16384; }
            src += ((size_t)bh * SS + kt * 128 + r) * DH;
            const uint4* s4 = (const uint4*)src;
            if (arr < 2) {
#pragma unroll
                for (int j = 0; j < 8; j++) {
                    uint32_t off = (uint32_t)r * 128u + j * 16u;
                    uint32_t swz = off ^ ((off >> 3) & 0x70);
                    *(uint4*)(dst + swz) = s4[j];
                }
            } else {
#pragma unroll
                for (int j = 0; j < 8; j++)
                    *(uint4*)(dst + (uint32_t)r * 128u + j * 16u) = s4[j];
            }
        }
        asm volatile("fence.proxy.async.shared::cta;" ::: "memory");
        __syncthreads();

        // scores: S = Qh*Kh + Qh*Kl + Ql*Kh (M=128,N=128,K=64)
        if (wid == 0 && elect1()) {
            uint64_t dQh = mk_desc(sb + SM_Q);
            uint64_t dQl = mk_desc(sb + SM_Q + 16384);
            uint64_t dKh = mk_desc(sb + SM_K);
            uint64_t dKl = mk_desc(sb + SM_K + 16384);
#pragma unroll
            for (int ks = 0; ks < 4; ks++) {
                mma_f16_ss(tmem, dQh + 2 * ks, dKh + 2 * ks, IDESC_S, ks == 0 ? 0u : 1u);
                mma_f16_ss(tmem, dQh + 2 * ks, dKl + 2 * ks, IDESC_S, 1u);
                mma_f16_ss(tmem, dQl + 2 * ks, dKh + 2 * ks, IDESC_S, 1u);
            }
            tc_commit(sb + 8);
        }

        // transpose V (overlaps S MMA): VT block kb = [64 d-rows][64 s], SW128
        {
            int a  = tid >> 7;          // 0 = hi, 1 = lo
            int i2 = tid & 127;
            int d  = i2 >> 1;
            int shb = i2 & 1;           // kb block (s half)
            const unsigned short* vs = (const unsigned short*)(sm + SM_VST + a * 16384);
            char* vt = sm + SM_VT + a * 16384 + shb * 8192;
#pragma unroll
            for (int m = 0; m < 32; m++) {
                int s0 = shb * 64 + 2 * m;
                uint32_t u = (uint32_t)vs[s0 * 64 + d]
                           | ((uint32_t)vs[(s0 + 1) * 64 + d] << 16);
                uint32_t off = (uint32_t)d * 128u + m * 4u;
                uint32_t swz = off ^ ((off >> 3) & 0x70);
                *(uint32_t*)(vt + swz) = u;
            }
        }
        asm volatile("fence.proxy.async.shared::cta;" ::: "memory");
        __syncthreads();

        mbar_wait(sb + 8, (uint32_t)(sph & 1)); sph++;
        TC_FENCE_AFTER();

        // read S, exp, accumulate l, write P (bf16 hi/lo) to smem
        {
            int rw = wid & 3, cw = wid >> 2;
            uint32_t s0[32], s1[32];
            TC_LD_X32(s0, tmem + cw * 64);
            TC_LD_X32(s1, tmem + cw * 64 + 32);
            TC_WAIT_LD();
            TC_FENCE_BEFORE();
            int r = rw * 32 + lane;
            char* pbh = sm + SM_P + cw * 16384;
            char* pbl = sm + SM_P + 32768 + cw * 16384;
#pragma unroll
            for (int m = 0; m < 32; m++) {
                int c0 = 2 * m, c1 = 2 * m + 1;
                float a = __uint_as_float(c0 < 32 ? s0[c0] : s1[c0 - 32]);
                float b = __uint_as_float(c1 < 32 ? s0[c1] : s1[c1 - 32]);
                float pa = __expf(a * 0.125f);
                float pb = __expf(b * 0.125f);
                lpart += pa + pb;
                bf16 ha = __float2bfloat16(pa), hb = __float2bfloat16(pb);
                float la = pa - __bfloat162float(ha), lb = pb - __bfloat162float(hb);
                uint32_t uph = ((uint32_t)__bfloat16_as_ushort(hb) << 16) | __bfloat16_as_ushort(ha);
                uint32_t upl = pack_bf2(la, lb);
                uint32_t off = (uint32_t)r * 128u + m * 4u;
                uint32_t swz = off ^ ((off >> 3) & 0x70);
                *(uint32_t*)(pbh + swz) = uph;
                *(uint32_t*)(pbl + swz) = upl;
            }
        }
        asm volatile("fence.proxy.async.shared::cta;" ::: "memory");
        __syncthreads();

        // O += Ph*VTh + Pl*VTh + Ph*VTl  (plain K-major, M=128,N=64,K=64 per kb)
        if (wid == 0 && elect1()) {
#pragma unroll
            for (int kb = 0; kb < 2; kb++) {
                uint64_t dPh = mk_desc(sb + SM_P + kb * 16384);
                uint64_t dPl = mk_desc(sb + SM_P + 32768 + kb * 16384);
                uint64_t dVh = mk_desc(sb + SM_VT + kb * 8192);
                uint64_t dVl = mk_desc(sb + SM_VT + 16384 + kb * 8192);
#pragma unroll
                for (int ks = 0; ks < 4; ks++) {
                    uint32_t en0 = (kt == 0 && kb == 0 && ks == 0) ? 0u : 1u;
                    mma_f16_ss(tmem + 128, dPh + 2 * ks, dVh + 2 * ks, IDESC_O, en0);
                    mma_f16_ss(tmem + 128, dPl + 2 * ks, dVh + 2 * ks, IDESC_O, 1u);
                    mma_f16_ss(tmem + 128, dPh + 2 * ks, dVl + 2 * ks, IDESC_O, 1u);
                }
            }
            tc_commit(sb + 16);
        }
    }
    mbar_wait(sb + 16, (uint32_t)(oph & 1)); oph++;
    TC_FENCE_AFTER();

    // combine l partials (reuse P smem) and write output
    float* lred = (float*)(sm + SM_P);
    lred[tid] = lpart;
    __syncthreads();
    if (wid < 4) {
        uint32_t o0[32], o1[32];
        TC_LD_X32(o0, tmem + 128);
        TC_LD_X32(o1, tmem + 160);
        TC_WAIT_LD();
        TC_FENCE_BEFORE();
        int r = wid * 32 + lane;
        float inv = 1.f / (lred[r] + lred[r + 128]);
        int b = bh >> 4, h = bh & 15;
        int s = qt * 128 + r;
        size_t base = ((size_t)(b * SS + s)) * DD + h * 64;
        uint32_t* ph = (uint32_t*)(outh + base);
        uint32_t* pl = (uint32_t*)(outl + base);
#pragma unroll
        for (int m = 0; m < 32; m++) {
            int c0 = 2 * m, c1 = 2 * m + 1;
            float v0 = __uint_as_float(c0 < 32 ? o0[c0] : o1[c0 - 32]) * inv;
            float v1 = __uint_as_float(c1 < 32 ? o0[c1] : o1[c1 - 32]) * inv;
            bf16 h0 = __float2bfloat16(v0), h1 = __float2bfloat16(v1);
            ph[m] = ((uint32_t)__bfloat16_as_ushort(h1) << 16) | __bfloat16_as_ushort(h0);
            pl[m] = pack_bf2(v0 - __bfloat162float(h0), v1 - __bfloat162float(h1));
        }
    }
    __syncthreads();
    if (wid == 0) { TC_DEALLOC(tmem, 256); }

#else
    // ---- SIMT fallback: two 64-row halves per CTA ----
    float* smf  = (float*)sm;
    float* Qs   = smf;
    float* Ks   = Qs + 64 * 65;
    float* Vs   = Ks + 64 * 65;
    float* Ps   = Vs + 64 * 65;
    float* mrow = Ps + 64 * 65;
    float* lrow = mrow + 64;
    float* arow = lrow + 64;
    int tx = tid & 15, ty = tid >> 4;
    const float scale = 0.125f;
    int b = bh >> 4, h = bh & 15;

    for (int h2 = 0; h2 < 2; h2++) {
        int qt64 = qt * 2 + h2;
        __syncthreads();
        for (int i = tid; i < 64 * 64; i += 256) {
            int r = i >> 6, d = i & 63;
            size_t o = ((size_t)bh * SS + qt64 * 64 + r) * DH + d;
            Qs[r * 65 + d] = (__bfloat162float(g_qkvh[0][o]) + __bfloat162float(g_qkvl[0][o])) * scale;
        }
        if (tid < 64) { mrow[tid] = -1e30f; lrow[tid] = 0.f; }
        float acc[4][4];
#pragma unroll
        for (int i = 0; i < 4; i++)
#pragma unroll
            for (int j = 0; j < 4; j++) acc[i][j] = 0.f;
        __syncthreads();

        for (int kt = 0; kt < SS / 64; kt++) {
            for (int i = tid; i < 64 * 64; i += 256) {
                int r = i >> 6, d = i & 63;
                size_t o = ((size_t)bh * SS + kt * 64 + r) * DH + d;
                Ks[r * 65 + d] = __bfloat162float(g_qkvh[1][o]) + __bfloat162float(g_qkvl[1][o]);
                Vs[r * 65 + d] = __bfloat162float(g_qkvh[2][o]) + __bfloat162float(g_qkvl[2][o]);
            }
            __syncthreads();
            float sv[4][4];
#pragma unroll
            for (int i = 0; i < 4; i++)
#pragma unroll
                for (int j = 0; j < 4; j++) sv[i][j] = 0.f;
            for (int d = 0; d < 64; d++) {
                float ar[4], br[4];
#pragma unroll
                for (int i = 0; i < 4; i++) ar[i] = Qs[(ty * 4 + i) * 65 + d];
#pragma unroll
                for (int j = 0; j < 4; j++) br[j] = Ks[(tx * 4 + j) * 65 + d];
#pragma unroll
                for (int i = 0; i < 4; i++)
#pragma unroll
                    for (int j = 0; j < 4; j++) sv[i][j] = fmaf(ar[i], br[j], sv[i][j]);
            }
#pragma unroll
            for (int i = 0; i < 4; i++)
#pragma unroll
                for (int j = 0; j < 4; j++)
                    Ps[(ty * 4 + i) * 65 + tx * 4 + j] = sv[i][j];
            __syncthreads();
            if (tid < 64) {
                int rr = tid;
                float m = mrow[rr], mx = m;
                for (int c = 0; c < 64; c++) mx = fmaxf(mx, Ps[rr * 65 + c]);
                float a = expf(m - mx), sum = 0.f;
                for (int c = 0; c < 64; c++) {
                    float p = expf(Ps[rr * 65 + c] - mx);
                    Ps[rr * 65 + c] = p; sum += p;
                }
                lrow[rr] = lrow[rr] * a + sum; mrow[rr] = mx; arow[rr] = a;
            }
            __syncthreads();
#pragma unroll
            for (int i = 0; i < 4; i++) {
                float a = arow[ty * 4 + i];
#pragma unroll
                for (int j = 0; j < 4; j++) acc[i][j] *= a;
            }
            for (int kk = 0; kk < 64; kk++) {
                float pr[4], vr[4];
#pragma unroll
                for (int i = 0; i < 4; i++) pr[i] = Ps[(ty * 4 + i) * 65 + kk];
#pragma unroll
                for (int j = 0; j < 4; j++) vr[j] = Vs[kk * 65 + tx * 4 + j];
#pragma unroll
                for (int i = 0; i < 4; i++)
#pragma unroll
                    for (int j = 0; j < 4; j++) acc[i][j] = fmaf(pr[i], vr[j], acc[i][j]);
            }
            __syncthreads();
        }
#pragma unroll
        for (int i = 0; i < 4; i++) {
            int rr = ty * 4 + i;
            float inv = 1.f / lrow[rr];
            int s = qt64 * 64 + rr;
#pragma unroll
            for (int j = 0; j < 4; j++) {
                int d = tx * 4 + j;
                size_t idx = ((size_t)(b * SS + s)) * DD + h * 64 + d;
                float val = acc[i][j] * inv;
                bf16 hh = __float2bfloat16(val);
                outh[idx] = hh;
                outl[idx] = __float2bfloat16(val - __bfloat162float(hh));
            }
        }
    }
#endif
#endif // __CUDA_ARCH__
}

// ---------------- router ----------------
__global__ void zero_cnt_kernel() {
    if (threadIdx.x < NE) g_cnt[threadIdx.x] = 0;
}

__global__ void router_kernel(const float* __restrict__ xn2, const float* __restrict__ wr)
{
    int t = blockIdx.x;
    int lane = threadIdx.x;
    float p[NE];
#pragma unroll
    for (int e = 0; e < NE; e++) p[e] = 0.f;
    const float* xr = xn2 + (size_t)t * DD;
    for (int d = lane; d < DD; d += 32) {
        float xv = xr[d];
        const float* wrow = wr + (size_t)d * NE;
#pragma unroll
        for (int e = 0; e < NE; e++) p[e] = fmaf(xv, wrow[e], p[e]);
    }
#pragma unroll
    for (int e = 0; e < NE; e++) {
        for (int o = 16; o > 0; o >>= 1) p[e] += __shfl_xor_sync(0xffffffffu, p[e], o);
    }
    if (lane == 0) {
        float m = p[0];
#pragma unroll
        for (int e = 1; e < NE; e++) m = fmaxf(m, p[e]);
        float pr[NE];
        float sum = 0.f;
#pragma unroll
        for (int e = 0; e < NE; e++) { pr[e] = expf(p[e] - m); sum += pr[e]; }
        float inv = 1.f / sum;
#pragma unroll
        for (int e = 0; e < NE; e++) pr[e] *= inv;
        g_zz[t] = m + logf(sum);
#pragma unroll
        for (int e = 0; e < NE; e++) g_probs[t * NE + e] = pr[e];
        int i0 = 0; float v0 = pr[0];
#pragma unroll
        for (int e = 1; e < NE; e++) if (pr[e] > v0) { v0 = pr[e]; i0 = e; }
        int i1 = -1; float v1 = -1.f;
#pragma unroll
        for (int e = 0; e < NE; e++) { if (e == i0) continue; if (pr[e] > v1) { v1 = pr[e]; i1 = e; } }
        float wsum = v0 + v1;
        float w0 = v0 / wsum, w1 = v1 / wsum;
        int r0 = atomicAdd(&g_cnt[i0], 1); g_rowlist[i0 * TT + r0] = t;
        int r1 = atomicAdd(&g_cnt[i1], 1); g_rowlist[i1 * TT + r1] = t;
        g_slot_e[2 * t]     = i0; g_slot_r[2 * t]     = r0; g_slot_w[2 * t]     = w0;
        g_slot_e[2 * t + 1] = i1; g_slot_r[2 * t + 1] = r1; g_slot_w[2 * t + 1] = w1;
    }
}

// ---------------- loss (deterministic tree reduction) ----------------
__global__ void loss_kernel(float* __restrict__ out, int out_size)
{
    int tid = threadIdx.x;
    __shared__ float red[256];
    __shared__ float sumsp[NE];
    __shared__ float sumz;
    float accp[NE];
#pragma unroll
    for (int e = 0; e < NE; e++) accp[e] = 0.f;
    float accz = 0.f;
    for (int t = tid; t < TT; t += 256) {
        float z = g_zz[t];
        accz += z * z;
#pragma unroll
        for (int e = 0; e < NE; e++) accp[e] += g_probs[t * NE + e];
    }
    red[tid] = accz; __syncthreads();
    for (int o = 128; o > 0; o >>= 1) { if (tid < o) red[tid] += red[tid + o]; __syncthreads(); }
    if (tid == 0) sumz = red[0];
    __syncthreads();
    for (int e = 0; e < NE; e++) {
        red[tid] = accp[e]; __syncthreads();
        for (int o = 128; o > 0; o >>= 1) { if (tid < o) red[tid] += red[tid + o]; __syncthreads(); }
        if (tid == 0) sumsp[e] = red[0];
        __syncthreads();
    }
    if (tid == 0) {
        float aux = 0.f;
        for (int e = 0; e < NE; e++) {
            float ft = (float)g_cnt[e] / (float)TT;
            float fp = sumsp[e] / (float)TT;
            aux += ft * fp;
        }
        aux *= (float)NE / 2.f;
        float loss = aux + 0.001f * (sumz / (float)TT);
        for (int i = NMAIN; i < out_size; i++) out[i] = loss;
    }
}

// ---------------- combine ----------------
__global__ void combine_kernel(float* __restrict__ out)
{
    int idx = blockIdx.x * 256 + threadIdx.x;
    if (idx >= NMAIN) return;
    int t = idx >> 10;
    int d = idx & 1023;
    int e0 = g_slot_e[2 * t], r0 = g_slot_r[2 * t];
    int e1 = g_slot_e[2 * t + 1], r1 = g_slot_r[2 * t + 1];
    float w0 = g_slot_w[2 * t], w1 = g_slot_w[2 * t + 1];
    float y = g_x2[idx]
            + w0 * g_Y[((size_t)e0 * TT + r0) * DD + d]
            + w1 * g_Y[((size_t)e1 * TT + r1) * DD + d];
    out[idx] = y;
}

// ---------------- launch ----------------
extern "C" void kernel_launch(void* const* d_in, const int* in_sizes, int n_in,
                              void* d_out, int out_size)
{
    const float* x   = (const float*)d_in[0];
    const float* ln1 = (const float*)d_in[1];
    const float* ln2 = (const float*)d_in[2];
    const float* wq  = (const float*)d_in[3];
    const float* wk  = (const float*)d_in[4];
    const float* wv  = (const float*)d_in[5];
    const float* wo  = (const float*)d_in[6];
    const float* wr  = (const float*)d_in[7];
    const float* w1  = (const float*)d_in[8];
    const float* w2  = (const float*)d_in[9];
    float* out = (float*)d_out;

    cudaFuncSetAttribute(tc_attn, cudaFuncAttributeMaxDynamicSharedMemorySize, ATT_SMEM);
    cudaFuncSetAttribute(tc_gemm<GM_QKV>,  cudaFuncAttributeMaxDynamicSharedMemorySize, G_SMEM);
    cudaFuncSetAttribute(tc_gemm<GM_RES>,  cudaFuncAttributeMaxDynamicSharedMemorySize, G_SMEM);
    cudaFuncSetAttribute(tc_gemm<GM_MOE1>, cudaFuncAttributeMaxDynamicSharedMemorySize, G_SMEM);
    cudaFuncSetAttribute(tc_gemm<GM_MOE2>, cudaFuncAttributeMaxDynamicSharedMemorySize, G_SMEM);

    bf16 *p_xnh, *p_xnl, *p_xn2h, *p_xn2l, *p_ctxh, *p_ctxl;
    bf16 *p_wpth, *p_wptl, *p_w1th, *p_w1tl, *p_w2th, *p_w2tl, *p_Hh, *p_Hl;
    float *p_xn2, *p_x2, *p_Y;
    cudaGetSymbolAddress((void**)&p_xnh,  g_xnh);
    cudaGetSymbolAddress((void**)&p_xnl,  g_xnl);
    cudaGetSymbolAddress((void**)&p_xn2,  g_xn2);
    cudaGetSymbolAddress((void**)&p_xn2h, g_xn2h);
    cudaGetSymbolAddress((void**)&p_xn2l, g_xn2l);
    cudaGetSymbolAddress((void**)&p_ctxh, g_ctxh);
    cudaGetSymbolAddress((void**)&p_ctxl, g_ctxl);
    cudaGetSymbolAddress((void**)&p_x2,   g_x2);
    cudaGetSymbolAddress((void**)&p_wpth, g_wpth);
    cudaGetSymbolAddress((void**)&p_wptl, g_wptl);
    cudaGetSymbolAddress((void**)&p_w1th, g_w1th);
    cudaGetSymbolAddress((void**)&p_w1tl, g_w1tl);
    cudaGetSymbolAddress((void**)&p_w2th, g_w2th);
    cudaGetSymbolAddress((void**)&p_w2tl, g_w2tl);
    cudaGetSymbolAddress((void**)&p_Hh,   g_Hh);
    cudaGetSymbolAddress((void**)&p_Hl,   g_Hl);
    cudaGetSymbolAddress((void**)&p_Y,    g_Y);

    // 0. weight transpose + bf16 split (vectorized)
    dim3 bt(256);
    wt_convert_kernel<<<dim3(DD/64, DD/64, 1), bt>>>(wq, p_wpth,           p_wptl,           DD, DD);
    wt_convert_kernel<<<dim3(DD/64, DD/64, 1), bt>>>(wk, p_wpth + DD*DD,   p_wptl + DD*DD,   DD, DD);
    wt_convert_kernel<<<dim3(DD/64, DD/64, 1), bt>>>(wv, p_wpth + 2*DD*DD, p_wptl + 2*DD*DD, DD, DD);
    wt_convert_kernel<<<dim3(DD/64, DD/64, 1), bt>>>(wo, p_wpth + 3*DD*DD, p_wptl + 3*DD*DD, DD, DD);
    wt_convert_kernel<<<dim3(FF/64, DD/64, NE), bt>>>(w1, p_w1th, p_w1tl, DD, FF);
    wt_convert_kernel<<<dim3(DD/64, FF/64, NE), bt>>>(w2, p_w2th, p_w2tl, FF, DD);

    // 1. rmsnorm 1 (bf16 split only)
    rmsnorm_kernel<<<TT, 256>>>(x, ln1, nullptr, p_xnh, p_xnl);

    // 2. QKV projections (z selects wq/wk/wv; emits bf16 hi/lo [B,H,S,Dh])
    tc_gemm<GM_QKV><<<dim3(DD/128, TT/128, 3), 256, G_SMEM>>>(
        p_xnh, p_xnl, p_wpth, p_wptl, nullptr, nullptr, nullptr, nullptr, TT, DD, DD);

    // 3. attention (tcgen05, explicit V transpose) -> ctx bf16 split
    tc_attn<<<dim3(BB * NH, SS / 128), 256, ATT_SMEM>>>(p_ctxh, p_ctxl);

    // 4. output projection + residual
    tc_gemm<GM_RES><<<dim3(DD/128, TT/128, 1), 256, G_SMEM>>>(
        p_ctxh, p_ctxl, p_wpth + 3*DD*DD, p_wptl + 3*DD*DD, p_x2, x, nullptr, nullptr, TT, DD, DD);

    // 5. rmsnorm 2 (fp32 + bf16 split)
    rmsnorm_kernel<<<TT, 256>>>(p_x2, ln2, p_xn2, p_xn2h, p_xn2l);

    // 6. router
    zero_cnt_kernel<<<1, 32>>>();
    router_kernel<<<TT, 32>>>(p_xn2, wr);

    // 7. loss scalar -> out[NMAIN..]
    loss_kernel<<<1, 256>>>(out, out_size);

    // 8. MoE expert GEMMs (grouped; tiles beyond per-expert count early-exit)
    tc_gemm<GM_MOE1><<<dim3(FF/128, TT/128, NE), 256, G_SMEM>>>(
        p_xn2h, p_xn2l, p_w1th, p_w1tl, nullptr, nullptr, p_Hh, p_Hl, TT, FF, DD);
    tc_gemm<GM_MOE2><<<dim3(DD/128, TT/128, NE), 256, G_SMEM>>>(
        p_Hh, p_Hl, p_w2th, p_w2tl, p_Y, nullptr, nullptr, nullptr, TT, DD, FF);

    // 9. combine + residual -> out
    combine_kernel<<<(NMAIN + 255) / 256, 256>>>(out);
}

// round 6
// speedup vs baseline: 2.6830x; 1.2141x over previous
#include <cuda_runtime.h>
#include <cuda_bf16.h>
#include <math.h>
#include <stdint.h>

#define BB 2
#define SS 2048
#define DD 1024
#define NH 16
#define DH 64
#define NE 8
#define FF 4096
#define TT (BB*SS)   // 4096 tokens
#define NMAIN (TT*DD)

typedef __nv_bfloat16 bf16;

// ---------------- scratch (static device globals; no cudaMalloc allowed) ----
__device__ bf16  g_xnh[TT*DD],  g_xnl[TT*DD];          // rmsnorm1 out, split
__device__ float g_xn2[TT*DD];                          // rmsnorm2 out fp32 (router)
__device__ bf16  g_xn2h[TT*DD], g_xn2l[TT*DD];          // rmsnorm2 out, split
__device__ bf16  g_qkvh[3][(size_t)TT*DD];              // q,k,v hi  [B,H,S,Dh]
__device__ bf16  g_qkvl[3][(size_t)TT*DD];              // q,k,v lo  [B,H,S,Dh]
__device__ bf16  g_ctxh[TT*DD], g_ctxl[TT*DD];          // attention ctx, split
__device__ float g_x2[TT*DD];                           // x + attn_out
__device__ bf16  g_wpth[4*DD*DD], g_wptl[4*DD*DD];      // wq,wk,wv,wo transposed split
__device__ bf16  g_w1th[(size_t)NE*DD*FF], g_w1tl[(size_t)NE*DD*FF];
__device__ bf16  g_w2th[(size_t)NE*DD*FF], g_w2tl[(size_t)NE*DD*FF];
__device__ bf16  g_Hh[(size_t)NE*TT*FF], g_Hl[(size_t)NE*TT*FF];  // gelu(h) split
__device__ float g_Y[(size_t)NE*TT*DD];
__device__ float g_probs[TT*NE];
__device__ float g_zz[TT];
__device__ int   g_cnt[NE];
__device__ int   g_rowlist[NE*TT];
__device__ int   g_slot_e[2*TT];
__device__ int   g_slot_r[2*TT];
__device__ float g_slot_w[2*TT];

// ---------------- PTX helpers ----------------
__device__ __forceinline__ uint32_t smem_u32(const void* p) {
    uint32_t a;
    asm("{ .reg .u64 t; cvta.to.shared.u64 t, %1; cvt.u32.u64 %0, t; }" : "=r"(a) : "l"(p));
    return a;
}
__device__ __forceinline__ uint32_t elect1() {
    uint32_t p;
    asm volatile("{\n.reg .pred p;\nelect.sync _|p, 0xFFFFFFFF;\nselp.b32 %0, 1, 0, p;\n}" : "=r"(p));
    return p;
}
__device__ __forceinline__ void mbar_init(uint32_t a, uint32_t n) {
    asm volatile("mbarrier.init.shared.b64 [%0], %1;" :: "r"(a), "r"(n) : "memory");
}
__device__ __forceinline__ void mbar_wait(uint32_t a, uint32_t par) {
    asm volatile(
        "{\n.reg .pred P;\n"
        "LW%=:\n"
        "mbarrier.try_wait.parity.acquire.cta.shared::cta.b64 P, [%0], %1, 0x989680;\n"
        "@P bra LD%=;\n"
        "bra LW%=;\n"
        "LD%=:\n}"
        :: "r"(a), "r"(par) : "memory");
}
// K-major SW128 descriptor (row = 128B)
__device__ __forceinline__ uint64_t mk_desc(uint32_t addr) {
    return ((uint64_t)2 << 61) | ((uint64_t)1 << 46) | ((uint64_t)64 << 32)
         | ((uint64_t)1 << 16) | ((addr >> 4) & 0x3FFF);
}
__device__ __forceinline__ void tc_commit(uint32_t mbar) {
#if defined(__CUDA_ARCH_FEAT_SM103_ALL)
    asm volatile("tcgen05.commit.cta_group::1.mbarrier::arrive::one.shared::cluster.b64 [%0];"
                 :: "r"(mbar) : "memory");
#endif
}
__device__ __forceinline__ void mma_f16_ss(uint32_t d, uint64_t ad, uint64_t bd,
                                           uint32_t idesc, uint32_t en) {
#if defined(__CUDA_ARCH_FEAT_SM103_ALL)
    asm volatile(
        "{\n.reg .pred p;\n"
        "setp.ne.u32 p, %4, 0;\n"
        "tcgen05.mma.cta_group::1.kind::f16 [%0], %1, %2, %3, {%5, %5, %5, %5}, p;\n}"
        :: "r"(d), "l"(ad), "l"(bd), "r"(idesc), "r"(en), "r"(0u) : "memory");
#endif
}

#if defined(__CUDA_ARCH_FEAT_SM103_ALL)
#define TC_ALLOC(sbaddr, n) \
    asm volatile("tcgen05.alloc.cta_group::1.sync.aligned.shared::cta.b32 [%0], %1;" \
                 :: "r"(sbaddr), "r"((uint32_t)(n)) : "memory")
#define TC_RELINQ() \
    asm volatile("tcgen05.relinquish_alloc_permit.cta_group::1.sync.aligned;")
#define TC_DEALLOC(t, n) \
    asm volatile("tcgen05.dealloc.cta_group::1.sync.aligned.b32 %0, %1;" :: "r"(t), "r"((uint32_t)(n)))
#define TC_FENCE_AFTER()  asm volatile("tcgen05.fence::after_thread_sync;" ::: "memory")
#define TC_FENCE_BEFORE() asm volatile("tcgen05.fence::before_thread_sync;" ::: "memory")
#define TC_WAIT_LD()      asm volatile("tcgen05.wait::ld.sync.aligned;" ::: "memory")
#define TC_LD_X32(r, ta) \
    asm volatile( \
        "tcgen05.ld.sync.aligned.32x32b.x32.b32 " \
        "{%0, %1, %2, %3, %4, %5, %6, %7, " \
        " %8, %9, %10, %11, %12, %13, %14, %15, " \
        " %16, %17, %18, %19, %20, %21, %22, %23, " \
        " %24, %25, %26, %27, %28, %29, %30, %31}, [%32];" \
        : "=r"((r)[0]),  "=r"((r)[1]),  "=r"((r)[2]),  "=r"((r)[3]), \
          "=r"((r)[4]),  "=r"((r)[5]),  "=r"((r)[6]),  "=r"((r)[7]), \
          "=r"((r)[8]),  "=r"((r)[9]),  "=r"((r)[10]), "=r"((r)[11]), \
          "=r"((r)[12]), "=r"((r)[13]), "=r"((r)[14]), "=r"((r)[15]), \
          "=r"((r)[16]), "=r"((r)[17]), "=r"((r)[18]), "=r"((r)[19]), \
          "=r"((r)[20]), "=r"((r)[21]), "=r"((r)[22]), "=r"((r)[23]), \
          "=r"((r)[24]), "=r"((r)[25]), "=r"((r)[26]), "=r"((r)[27]), \
          "=r"((r)[28]), "=r"((r)[29]), "=r"((r)[30]), "=r"((r)[31]) \
        : "r"(ta))
#endif

__device__ __forceinline__ float gelu_tanh(float x) {
    float x3 = x * x * x;
    return 0.5f * x * (1.f + tanhf(0.7978845608028654f * (x + 0.044715f * x3)));
}
__device__ __forceinline__ uint32_t pack_bf2(float a, float b) {
    return ((uint32_t)__bfloat16_as_ushort(__float2bfloat16(b)) << 16)
         |  (uint32_t)__bfloat16_as_ushort(__float2bfloat16(a));
}

// ---------------- rmsnorm (writes fp32 optional + bf16 hi/lo) ----------------
__global__ void rmsnorm_kernel(const float* __restrict__ x, const float* __restrict__ w,
                               float* __restrict__ yf, bf16* __restrict__ yh, bf16* __restrict__ yl)
{
    int row = blockIdx.x;
    int tid = threadIdx.x;
    const float* xr = x + (size_t)row * DD;
    float s = 0.f;
    for (int d = tid; d < DD; d += 256) { float v = xr[d]; s += v * v; }
    __shared__ float red[256];
    red[tid] = s; __syncthreads();
    for (int o = 128; o > 0; o >>= 1) { if (tid < o) red[tid] += red[tid + o]; __syncthreads(); }
    float inv = rsqrtf(red[0] / (float)DD + 1e-6f);
    size_t base = (size_t)row * DD;
    for (int d = tid; d < DD; d += 256) {
        float v = xr[d] * inv * w[d];
        if (yf) yf[base + d] = v;
        bf16 h = __float2bfloat16(v);
        yh[base + d] = h;
        yl[base + d] = __float2bfloat16(v - __bfloat162float(h));
    }
}

// ---------------- weight transpose + bf16 split (vectorized) ----------------
__global__ void wt_convert_kernel(const float* __restrict__ W,
                                  bf16* __restrict__ Th, bf16* __restrict__ Tl,
                                  int K, int N)
{
    __shared__ float tile[64][68];
    size_t zoff = (size_t)blockIdx.z * K * N;
    int n0 = blockIdx.x * 64, k0 = blockIdx.y * 64;
    int tx = threadIdx.x & 15, ty = threadIdx.x >> 4;   // 16x16
#pragma unroll
    for (int i = 0; i < 4; i++) {
        int r = ty + 16 * i;
        float4 v = *(const float4*)(W + zoff + (size_t)(k0 + r) * N + n0 + tx * 4);
        *(float4*)&tile[r][tx * 4] = v;
    }
    __syncthreads();
#pragma unroll
    for (int i = 0; i < 4; i++) {
        int n = ty + 16 * i;
        int kk = tx * 4;
        float v0 = tile[kk + 0][n], v1 = tile[kk + 1][n];
        float v2 = tile[kk + 2][n], v3 = tile[kk + 3][n];
        bf16 h0 = __float2bfloat16(v0), h1 = __float2bfloat16(v1);
        bf16 h2 = __float2bfloat16(v2), h3 = __float2bfloat16(v3);
        float l0 = v0 - __bfloat162float(h0), l1 = v1 - __bfloat162float(h1);
        float l2 = v2 - __bfloat162float(h2), l3 = v3 - __bfloat162float(h3);
        size_t idx = zoff + (size_t)(n0 + n) * K + k0 + kk;
        uint2 ph, pl;
        ph.x = ((uint32_t)__bfloat16_as_ushort(h1) << 16) | __bfloat16_as_ushort(h0);
        ph.y = ((uint32_t)__bfloat16_as_ushort(h3) << 16) | __bfloat16_as_ushort(h2);
        pl.x = pack_bf2(l0, l1);
        pl.y = pack_bf2(l2, l3);
        *(uint2*)(Th + idx) = ph;
        *(uint2*)(Tl + idx) = pl;
    }
}

// ---------------- GEMM modes ----------------
#define GM_QKV  1
#define GM_RES  2
#define GM_MOE1 3
#define GM_MOE2 4
// N=256 tiles: per-chunk buffer {Ah 16K, Al 16K, Bh 32K, Bl 32K} = 96 KB, x2
#define BUF_BYTES 98304
#define G_SMEM  (1024 + 2 * BUF_BYTES)   // 197632 B

// scalar store (fallback path only)
template<int MODE>
__device__ __forceinline__ void store_elem(int e, int N, int row, int col, float v,
        float* __restrict__ Cf, const float* __restrict__ Res,
        bf16* __restrict__ Ch, bf16* __restrict__ Cl)
{
    if (MODE == GM_QKV) {
        int b = row >> 11, s5 = row & (SS - 1);
        int h = col >> 6, dh = col & 63;
        size_t o = (((size_t)(b * NH + h)) * SS + s5) * DH + dh;
        bf16 hh = __float2bfloat16(v);
        g_qkvh[e][o] = hh;
        g_qkvl[e][o] = __float2bfloat16(v - __bfloat162float(hh));
    } else if (MODE == GM_RES) {
        size_t o = (size_t)row * N + col;
        Cf[o] = v + Res[o];
    } else if (MODE == GM_MOE1) {
        size_t o = ((size_t)e * TT + row) * N + col;
        float g = gelu_tanh(v);
        bf16 h = __float2bfloat16(g);
        Ch[o] = h;
        Cl[o] = __float2bfloat16(g - __bfloat162float(h));
    } else {
        Cf[((size_t)e * TT + row) * N + col] = v;
    }
}

// ---------------- tcgen05 GEMM: C[128x256] tiles, 3-term bf16 split,
//                  cp.async double-buffered pipeline -----------------------
template<int MODE>
__global__ void __launch_bounds__(256, 1)
tc_gemm(const bf16* __restrict__ Ah, const bf16* __restrict__ Al,
        const bf16* __restrict__ Bh0, const bf16* __restrict__ Bl0,
        float* __restrict__ Cf, const float* __restrict__ Res,
        bf16* __restrict__ Ch, bf16* __restrict__ Cl,
        int M, int N, int K)
{
#if defined(__CUDA_ARCH__)
    extern __shared__ char sm[];
    int tid = threadIdx.x;
    int e  = blockIdx.z;
    int m0 = blockIdx.y * 128, n0 = blockIdx.x * 256;
    int Me = M;
    const bf16* Bh = Bh0;
    const bf16* Bl = Bl0;
    if (MODE == GM_MOE1 || MODE == GM_MOE2) {
        Me = g_cnt[e];
        if (m0 >= Me) return;
        Bh += (size_t)e * (size_t)K * N; Bl += (size_t)e * (size_t)K * N;
    } else if (MODE == GM_QKV) {
        Bh += (size_t)e * (size_t)K * N; Bl += (size_t)e * (size_t)K * N;
    }

#if defined(__CUDA_ARCH_FEAT_SM103_ALL)
    uint32_t sb = smem_u32(sm);
    int wid = tid >> 5, lid = tid & 31;
    int nk = K / 64;

    // fill chunk kc into buffer bufi via cp.async (384 row tasks: 128 A + 256 B)
    auto issue_fill = [&](int kc, int bufi) {
        uint32_t tb = sb + 1024 + (uint32_t)bufi * BUF_BYTES;
        for (int task = tid; task < 384; task += 256) {
            const bf16 *sh, *sl;
            uint32_t regionH, regionL;
            int row;
            bool val = true;
            if (task < 128) {
                int gr = m0 + task;
                val = gr < Me;
                size_t ri = 0;
                if (val) {
                    if (MODE == GM_MOE1)      ri = (size_t)g_rowlist[e * TT + gr];
                    else if (MODE == GM_MOE2) ri = (size_t)e * TT + gr;
                    else                      ri = (size_t)gr;
                }
                sh = Ah + ri * (size_t)K;
                sl = Al + ri * (size_t)K;
                regionH = tb; regionL = tb + 16384;
                row = task;
            } else {
                row = task - 128;
                sh = Bh + (size_t)(n0 + row) * K;
                sl = Bl + (size_t)(n0 + row) * K;
                regionH = tb + 32768; regionL = tb + 65536;
            }
            const char* srcH = (const char*)(sh + kc * 64);
            const char* srcL = (const char*)(sl + kc * 64);
            uint32_t sz = val ? 16u : 0u;
#pragma unroll
            for (int j = 0; j < 8; j++) {
                uint32_t off = (uint32_t)row * 128u + j * 16u;
                uint32_t swz = off ^ ((off >> 3) & 0x70);
                asm volatile("cp.async.cg.shared.global [%0], [%1], 16, %2;"
                             :: "r"(regionH + swz), "l"(srcH + j * 16), "r"(sz) : "memory");
                asm volatile("cp.async.cg.shared.global [%0], [%1], 16, %2;"
                             :: "r"(regionL + swz), "l"(srcL + j * 16), "r"(sz) : "memory");
            }
        }
        asm volatile("cp.async.commit_group;" ::: "memory");
    };

    // prologue: start chunks 0 and 1 immediately (overlaps TMEM alloc)
    issue_fill(0, 0);
    if (nk > 1) issue_fill(1, 1);

    if (wid == 0) { TC_ALLOC(sb, 256); TC_RELINQ(); }
    if (tid == 0) { mbar_init(sb + 8, 1); mbar_init(sb + 16, 1); }
    __syncthreads();
    uint32_t tmem;
    asm volatile("ld.shared.b32 %0, [%1];" : "=r"(tmem) : "r"(sb));

    const uint32_t IDESC = (1u << 4) | (1u << 7) | (1u << 10) | (16u << 17) | (8u << 24);
    int ph0 = 0, ph1 = 0;
    for (int kc = 0; kc < nk; kc++) {
        int b = kc & 1;
        if (kc >= 1 && kc + 1 < nk) {
            int nb = 1 - b;
            // buffer nb was consumed by chunk kc-1's MMAs; wait then refill
            if (nb == 0) { mbar_wait(sb + 8,  (uint32_t)(ph0 & 1)); ph0++; }
            else         { mbar_wait(sb + 16, (uint32_t)(ph1 & 1)); ph1++; }
            issue_fill(kc + 1, nb);
        }
        if (kc + 1 < nk) asm volatile("cp.async.wait_group 1;" ::: "memory");
        else             asm volatile("cp.async.wait_group 0;" ::: "memory");
        asm volatile("fence.proxy.async.shared::cta;" ::: "memory");
        __syncthreads();
        if (wid == 0 && elect1()) {
            uint32_t tb = sb + 1024 + (uint32_t)b * BUF_BYTES;
            uint64_t dAh = mk_desc(tb);
            uint64_t dAl = mk_desc(tb + 16384);
            uint64_t dBh = mk_desc(tb + 32768);
            uint64_t dBl = mk_desc(tb + 65536);
#pragma unroll
            for (int s = 0; s < 4; s++) {
#pragma unroll
                for (int h = 0; h < 2; h++) {
                    uint64_t bo = (uint64_t)(1024 * h + 2 * s);
                    uint32_t D = tmem + 128 * h;
                    uint32_t en0 = (kc == 0 && s == 0) ? 0u : 1u;
                    mma_f16_ss(D, dAh + 2 * s, dBh + bo, IDESC, en0);
                    mma_f16_ss(D, dAh + 2 * s, dBl + bo, IDESC, 1u);
                    mma_f16_ss(D, dAl + 2 * s, dBh + bo, IDESC, 1u);
                }
            }
            tc_commit(sb + 8 + b * 8);
        }
    }
    {
        int lb = (nk - 1) & 1;
        if (lb == 0) mbar_wait(sb + 8,  (uint32_t)(ph0 & 1));
        else         mbar_wait(sb + 16, (uint32_t)(ph1 & 1));
    }
    TC_FENCE_AFTER();

    // ---- staged epilogue: two 128-col passes, TMEM -> smem -> coalesced ----
    int rw = wid & 3, cw = wid >> 2;
    int rows_here = Me - m0; if (rows_here > 128) rows_here = 128;
    float* Cs = (float*)(sm + 1024);
#pragma unroll 1
    for (int p = 0; p < 2; p++) {
        uint32_t d0[32], d1[32];
        TC_LD_X32(d0, tmem + p * 128 + cw * 64);
        TC_LD_X32(d1, tmem + p * 128 + cw * 64 + 32);
        TC_WAIT_LD();
        TC_FENCE_BEFORE();
        __syncthreads();
        {
            int rr = rw * 32 + lid;
            int cb = cw * 64;
#pragma unroll
            for (int j = 0; j < 32; j++) {
                Cs[rr * 129 + cb + j]      = __uint_as_float(d0[j]);
                Cs[rr * 129 + cb + 32 + j] = __uint_as_float(d1[j]);
            }
        }
        __syncthreads();
#pragma unroll 4
        for (int it = 0; it < 16; it++) {
            int idx4 = (it * 256 + tid) * 4;
            int rr = idx4 >> 7, cc = idx4 & 127;
            if (rr >= rows_here) continue;
            float v0 = Cs[rr * 129 + cc + 0];
            float v1 = Cs[rr * 129 + cc + 1];
            float v2 = Cs[rr * 129 + cc + 2];
            float v3 = Cs[rr * 129 + cc + 3];
            int colb = n0 + p * 128 + cc;
            if (MODE == GM_RES) {
                size_t o = (size_t)(m0 + rr) * N + colb;
                float4 rs = *(const float4*)(Res + o);
                *(float4*)(Cf + o) = make_float4(v0 + rs.x, v1 + rs.y, v2 + rs.z, v3 + rs.w);
            } else if (MODE == GM_MOE2) {
                size_t o = ((size_t)e * TT + m0 + rr) * N + colb;
                *(float4*)(Cf + o) = make_float4(v0, v1, v2, v3);
            } else if (MODE == GM_MOE1) {
                size_t o = ((size_t)e * TT + m0 + rr) * N + colb;
                float g0 = gelu_tanh(v0), g1 = gelu_tanh(v1);
                float g2 = gelu_tanh(v2), g3 = gelu_tanh(v3);
                bf16 h0 = __float2bfloat16(g0), h1 = __float2bfloat16(g1);
                bf16 h2 = __float2bfloat16(g2), h3 = __float2bfloat16(g3);
                uint2 ph, pl;
                ph.x = ((uint32_t)__bfloat16_as_ushort(h1) << 16) | __bfloat16_as_ushort(h0);
                ph.y = ((uint32_t)__bfloat16_as_ushort(h3) << 16) | __bfloat16_as_ushort(h2);
                pl.x = pack_bf2(g0 - __bfloat162float(h0), g1 - __bfloat162float(h1));
                pl.y = pack_bf2(g2 - __bfloat162float(h2), g3 - __bfloat162float(h3));
                *(uint2*)(Ch + o) = ph;
                *(uint2*)(Cl + o) = pl;
            } else { // GM_QKV -> bf16 hi/lo [B,H,S,Dh]
                int row = m0 + rr;
                int b2 = row >> 11, s5 = row & (SS - 1);
                int h = colb >> 6, dh = colb & 63;
                size_t o = (((size_t)(b2 * NH + h)) * SS + s5) * DH + dh;
                bf16 h0 = __float2bfloat16(v0), h1 = __float2bfloat16(v1);
                bf16 h2 = __float2bfloat16(v2), h3 = __float2bfloat16(v3);
                uint2 ph, pl;
                ph.x = ((uint32_t)__bfloat16_as_ushort(h1) << 16) | __bfloat16_as_ushort(h0);
                ph.y = ((uint32_t)__bfloat16_as_ushort(h3) << 16) | __bfloat16_as_ushort(h2);
                pl.x = pack_bf2(v0 - __bfloat162float(h0), v1 - __bfloat162float(h1));
                pl.y = pack_bf2(v2 - __bfloat162float(h2), v3 - __bfloat162float(h3));
                *(uint2*)(g_qkvh[e] + o) = ph;
                *(uint2*)(g_qkvl[e] + o) = pl;
            }
        }
        __syncthreads();
    }
    if (wid == 0) { TC_DEALLOC(tmem, 256); }

#else
    // ---- SIMT fallback (base-arch pass): two 128-col halves ----
    float* As = (float*)sm;
    float* Bs = As + 16 * 128;
    int tx = tid & 15, ty = tid >> 4;
    for (int half = 0; half < 2; half++) {
        int n0h = n0 + half * 128;
        float acc[8][8];
#pragma unroll
        for (int i = 0; i < 8; i++)
#pragma unroll
            for (int j = 0; j < 8; j++) acc[i][j] = 0.f;
        for (int k0 = 0; k0 < K; k0 += 16) {
            __syncthreads();
            for (int l = tid; l < 16 * 128; l += 256) {
                int kk = l >> 7, rr = l & 127;
                int gr = m0 + rr;
                float av = 0.f;
                if (gr < Me) {
                    size_t ri;
                    if (MODE == GM_MOE1)      ri = (size_t)g_rowlist[e * TT + gr];
                    else if (MODE == GM_MOE2) ri = (size_t)e * TT + gr;
                    else                      ri = (size_t)gr;
                    av = __bfloat162float(Ah[ri * (size_t)K + k0 + kk])
                       + __bfloat162float(Al[ri * (size_t)K + k0 + kk]);
                }
                As[kk * 128 + rr] = av;
                Bs[kk * 128 + rr] = __bfloat162float(Bh[(size_t)(n0h + rr) * K + k0 + kk])
                                  + __bfloat162float(Bl[(size_t)(n0h + rr) * K + k0 + kk]);
            }
            __syncthreads();
            for (int kk = 0; kk < 16; kk++) {
                float ar[8], br[8];
#pragma unroll
                for (int i = 0; i < 8; i++) ar[i] = As[kk * 128 + ty * 8 + i];
#pragma unroll
                for (int j = 0; j < 8; j++) br[j] = Bs[kk * 128 + tx * 8 + j];
#pragma unroll
                for (int i = 0; i < 8; i++)
#pragma unroll
                    for (int j = 0; j < 8; j++) acc[i][j] = fmaf(ar[i], br[j], acc[i][j]);
            }
        }
#pragma unroll
        for (int i = 0; i < 8; i++) {
            int row = m0 + ty * 8 + i;
            if (row >= Me) continue;
#pragma unroll
            for (int j = 0; j < 8; j++)
                store_elem<MODE>(e, N, row, n0h + tx * 8 + j, acc[i][j], Cf, Res, Ch, Cl);
        }
        __syncthreads();
    }
#endif
#endif // __CUDA_ARCH__
}

// ---------------- tcgen05 flash attention (unchanged from passing R5) ------
#define SM_Q   1024
#define SM_K   33792
#define SM_VST 66560
#define SM_VT  99328
#define SM_P   132096
#define ATT_SMEM 197632

__global__ void __launch_bounds__(256, 1)
tc_attn(bf16* __restrict__ outh, bf16* __restrict__ outl)
{
#if defined(__CUDA_ARCH__)
    extern __shared__ char sm[];
    int tid = threadIdx.x;
    int bh = blockIdx.x;
    int qt = blockIdx.y;

#if defined(__CUDA_ARCH_FEAT_SM103_ALL)
    uint32_t sb = smem_u32(sm);
    int wid = tid >> 5, lane = tid & 31;

    if (wid == 0) { TC_ALLOC(sb, 256); TC_RELINQ(); }
    if (tid == 0) { mbar_init(sb + 8, 1); mbar_init(sb + 16, 1); }
    __syncthreads();
    uint32_t tmem;
    asm volatile("ld.shared.b32 %0, [%1];" : "=r"(tmem) : "r"(sb));

    // load Q tile (hi/lo): threads 0-127 hi rows, 128-255 lo rows
    {
        int r = tid & 127;
        const bf16* src = (tid < 128 ? g_qkvh[0] : g_qkvl[0])
                        + ((size_t)bh * SS + qt * 128 + r) * DH;
        char* dst = sm + SM_Q + (tid < 128 ? 0 : 16384);
        const uint4* s4 = (const uint4*)src;
#pragma unroll
        for (int j = 0; j < 8; j++) {
            uint32_t off = (uint32_t)r * 128u + j * 16u;
            uint32_t swz = off ^ ((off >> 3) & 0x70);
            *(uint4*)(dst + swz) = s4[j];
        }
    }

    const uint32_t IDESC_S = (1u << 4) | (1u << 7) | (1u << 10) | (16u << 17) | (8u << 24);
    const uint32_t IDESC_O = (1u << 4) | (1u << 7) | (1u << 10) | (8u << 17) | (8u << 24);
    int sph = 0, oph = 0;
    float lpart = 0.f;

    for (int kt = 0; kt < SS / 128; kt++) {
        if (kt > 0) { mbar_wait(sb + 16, (uint32_t)(oph & 1)); oph++; }
#pragma unroll
        for (int i = 0; i < 2; i++) {
            int task = tid + i * 256;
            int arr = task >> 7, r = task & 127;
            const bf16* src;
            char* dst;
            if (arr == 0)      { src = g_qkvh[1]; dst = sm + SM_K; }
            else if (arr == 1) { src = g_qkvl[1]; dst = sm + SM_K + 16384; }
            else if (arr == 2) { src = g_qkvh[2]; dst = sm + SM_VST; }
            else               { src = g_qkvl[2]; dst = sm + SM_VST + 16384; }
            src += ((size_t)bh * SS + kt * 128 + r) * DH;
            const uint4* s4 = (const uint4*)src;
            if (arr < 2) {
#pragma unroll
                for (int j = 0; j < 8; j++) {
                    uint32_t off = (uint32_t)r * 128u + j * 16u;
                    uint32_t swz = off ^ ((off >> 3) & 0x70);
                    *(uint4*)(dst + swz) = s4[j];
                }
            } else {
#pragma unroll
                for (int j = 0; j < 8; j++)
                    *(uint4*)(dst + (uint32_t)r * 128u + j * 16u) = s4[j];
            }
        }
        asm volatile("fence.proxy.async.shared::cta;" ::: "memory");
        __syncthreads();

        if (wid == 0 && elect1()) {
            uint64_t dQh = mk_desc(sb + SM_Q);
            uint64_t dQl = mk_desc(sb + SM_Q + 16384);
            uint64_t dKh = mk_desc(sb + SM_K);
            uint64_t dKl = mk_desc(sb + SM_K + 16384);
#pragma unroll
            for (int ks = 0; ks < 4; ks++) {
                mma_f16_ss(tmem, dQh + 2 * ks, dKh + 2 * ks, IDESC_S, ks == 0 ? 0u : 1u);
                mma_f16_ss(tmem, dQh + 2 * ks, dKl + 2 * ks, IDESC_S, 1u);
                mma_f16_ss(tmem, dQl + 2 * ks, dKh + 2 * ks, IDESC_S, 1u);
            }
            tc_commit(sb + 8);
        }

        // transpose V (overlaps S MMA): VT block kb = [64 d-rows][64 s], SW128
        {
            int a  = tid >> 7;
            int i2 = tid & 127;
            int d  = i2 >> 1;
            int shb = i2 & 1;
            const unsigned short* vs = (const unsigned short*)(sm + SM_VST + a * 16384);
            char* vt = sm + SM_VT + a * 16384 + shb * 8192;
#pragma unroll
            for (int m = 0; m < 32; m++) {
                int s0 = shb * 64 + 2 * m;
                uint32_t u = (uint32_t)vs[s0 * 64 + d]
                           | ((uint32_t)vs[(s0 + 1) * 64 + d] << 16);
                uint32_t off = (uint32_t)d * 128u + m * 4u;
                uint32_t swz = off ^ ((off >> 3) & 0x70);
                *(uint32_t*)(vt + swz) = u;
            }
        }
        asm volatile("fence.proxy.async.shared::cta;" ::: "memory");
        __syncthreads();

        mbar_wait(sb + 8, (uint32_t)(sph & 1)); sph++;
        TC_FENCE_AFTER();

        {
            int rw = wid & 3, cw = wid >> 2;
            uint32_t s0[32], s1[32];
            TC_LD_X32(s0, tmem + cw * 64);
            TC_LD_X32(s1, tmem + cw * 64 + 32);
            TC_WAIT_LD();
            TC_FENCE_BEFORE();
            int r = rw * 32 + lane;
            char* pbh = sm + SM_P + cw * 16384;
            char* pbl = sm + SM_P + 32768 + cw * 16384;
#pragma unroll
            for (int m = 0; m < 32; m++) {
                int c0 = 2 * m, c1 = 2 * m + 1;
                float a = __uint_as_float(c0 < 32 ? s0[c0] : s1[c0 - 32]);
                float b = __uint_as_float(c1 < 32 ? s0[c1] : s1[c1 - 32]);
                float pa = __expf(a * 0.125f);
                float pb = __expf(b * 0.125f);
                lpart += pa + pb;
                bf16 ha = __float2bfloat16(pa), hb = __float2bfloat16(pb);
                float la = pa - __bfloat162float(ha), lb = pb - __bfloat162float(hb);
                uint32_t uph = ((uint32_t)__bfloat16_as_ushort(hb) << 16) | __bfloat16_as_ushort(ha);
                uint32_t upl = pack_bf2(la, lb);
                uint32_t off = (uint32_t)r * 128u + m * 4u;
                uint32_t swz = off ^ ((off >> 3) & 0x70);
                *(uint32_t*)(pbh + swz) = uph;
                *(uint32_t*)(pbl + swz) = upl;
            }
        }
        asm volatile("fence.proxy.async.shared::cta;" ::: "memory");
        __syncthreads();

        if (wid == 0 && elect1()) {
#pragma unroll
            for (int kb = 0; kb < 2; kb++) {
                uint64_t dPh = mk_desc(sb + SM_P + kb * 16384);
                uint64_t dPl = mk_desc(sb + SM_P + 32768 + kb * 16384);
                uint64_t dVh = mk_desc(sb + SM_VT + kb * 8192);
                uint64_t dVl = mk_desc(sb + SM_VT + 16384 + kb * 8192);
#pragma unroll
                for (int ks = 0; ks < 4; ks++) {
                    uint32_t en0 = (kt == 0 && kb == 0 && ks == 0) ? 0u : 1u;
                    mma_f16_ss(tmem + 128, dPh + 2 * ks, dVh + 2 * ks, IDESC_O, en0);
                    mma_f16_ss(tmem + 128, dPl + 2 * ks, dVh + 2 * ks, IDESC_O, 1u);
                    mma_f16_ss(tmem + 128, dPh + 2 * ks, dVl + 2 * ks, IDESC_O, 1u);
                }
            }
            tc_commit(sb + 16);
        }
    }
    mbar_wait(sb + 16, (uint32_t)(oph & 1)); oph++;
    TC_FENCE_AFTER();

    float* lred = (float*)(sm + SM_P);
    lred[tid] = lpart;
    __syncthreads();
    if (wid < 4) {
        uint32_t o0[32], o1[32];
        TC_LD_X32(o0, tmem + 128);
        TC_LD_X32(o1, tmem + 160);
        TC_WAIT_LD();
        TC_FENCE_BEFORE();
        int r = wid * 32 + lane;
        float inv = 1.f / (lred[r] + lred[r + 128]);
        int b = bh >> 4, h = bh & 15;
        int s = qt * 128 + r;
        size_t base = ((size_t)(b * SS + s)) * DD + h * 64;
        uint32_t* ph = (uint32_t*)(outh + base);
        uint32_t* pl = (uint32_t*)(outl + base);
#pragma unroll
        for (int m = 0; m < 32; m++) {
            int c0 = 2 * m, c1 = 2 * m + 1;
            float v0 = __uint_as_float(c0 < 32 ? o0[c0] : o1[c0 - 32]) * inv;
            float v1 = __uint_as_float(c1 < 32 ? o0[c1] : o1[c1 - 32]) * inv;
            bf16 h0 = __float2bfloat16(v0), h1 = __float2bfloat16(v1);
            ph[m] = ((uint32_t)__bfloat16_as_ushort(h1) << 16) | __bfloat16_as_ushort(h0);
            pl[m] = pack_bf2(v0 - __bfloat162float(h0), v1 - __bfloat162float(h1));
        }
    }
    __syncthreads();
    if (wid == 0) { TC_DEALLOC(tmem, 256); }

#else
    // ---- SIMT fallback: two 64-row halves per CTA ----
    float* smf  = (float*)sm;
    float* Qs   = smf;
    float* Ks   = Qs + 64 * 65;
    float* Vs   = Ks + 64 * 65;
    float* Ps   = Vs + 64 * 65;
    float* mrow = Ps + 64 * 65;
    float* lrow = mrow + 64;
    float* arow = lrow + 64;
    int tx = tid & 15, ty = tid >> 4;
    const float scale = 0.125f;
    int b = bh >> 4, h = bh & 15;

    for (int h2 = 0; h2 < 2; h2++) {
        int qt64 = qt * 2 + h2;
        __syncthreads();
        for (int i = tid; i < 64 * 64; i += 256) {
            int r = i >> 6, d = i & 63;
            size_t o = ((size_t)bh * SS + qt64 * 64 + r) * DH + d;
            Qs[r * 65 + d] = (__bfloat162float(g_qkvh[0][o]) + __bfloat162float(g_qkvl[0][o])) * scale;
        }
        if (tid < 64) { mrow[tid] = -1e30f; lrow[tid] = 0.f; }
        float acc[4][4];
#pragma unroll
        for (int i = 0; i < 4; i++)
#pragma unroll
            for (int j = 0; j < 4; j++) acc[i][j] = 0.f;
        __syncthreads();

        for (int kt = 0; kt < SS / 64; kt++) {
            for (int i = tid; i < 64 * 64; i += 256) {
                int r = i >> 6, d = i & 63;
                size_t o = ((size_t)bh * SS + kt * 64 + r) * DH + d;
                Ks[r * 65 + d] = __bfloat162float(g_qkvh[1][o]) + __bfloat162float(g_qkvl[1][o]);
                Vs[r * 65 + d] = __bfloat162float(g_qkvh[2][o]) + __bfloat162float(g_qkvl[2][o]);
            }
            __syncthreads();
            float sv[4][4];
#pragma unroll
            for (int i = 0; i < 4; i++)
#pragma unroll
                for (int j = 0; j < 4; j++) sv[i][j] = 0.f;
            for (int d = 0; d < 64; d++) {
                float ar[4], br[4];
#pragma unroll
                for (int i = 0; i < 4; i++) ar[i] = Qs[(ty * 4 + i) * 65 + d];
#pragma unroll
                for (int j = 0; j < 4; j++) br[j] = Ks[(tx * 4 + j) * 65 + d];
#pragma unroll
                for (int i = 0; i < 4; i++)
#pragma unroll
                    for (int j = 0; j < 4; j++) sv[i][j] = fmaf(ar[i], br[j], sv[i][j]);
            }
#pragma unroll
            for (int i = 0; i < 4; i++)
#pragma unroll
                for (int j = 0; j < 4; j++)
                    Ps[(ty * 4 + i) * 65 + tx * 4 + j] = sv[i][j];
            __syncthreads();
            if (tid < 64) {
                int rr = tid;
                float m = mrow[rr], mx = m;
                for (int c = 0; c < 64; c++) mx = fmaxf(mx, Ps[rr * 65 + c]);
                float a = expf(m - mx), sum = 0.f;
                for (int c = 0; c < 64; c++) {
                    float p = expf(Ps[rr * 65 + c] - mx);
                    Ps[rr * 65 + c] = p; sum += p;
                }
                lrow[rr] = lrow[rr] * a + sum; mrow[rr] = mx; arow[rr] = a;
            }
            __syncthreads();
#pragma unroll
            for (int i = 0; i < 4; i++) {
                float a = arow[ty * 4 + i];
#pragma unroll
                for (int j = 0; j < 4; j++) acc[i][j] *= a;
            }
            for (int kk = 0; kk < 64; kk++) {
                float pr[4], vr[4];
#pragma unroll
                for (int i = 0; i < 4; i++) pr[i] = Ps[(ty * 4 + i) * 65 + kk];
#pragma unroll
                for (int j = 0; j < 4; j++) vr[j] = Vs[kk * 65 + tx * 4 + j];
#pragma unroll
                for (int i = 0; i < 4; i++)
#pragma unroll
                    for (int j = 0; j < 4; j++) acc[i][j] = fmaf(pr[i], vr[j], acc[i][j]);
            }
            __syncthreads();
        }
#pragma unroll
        for (int i = 0; i < 4; i++) {
            int rr = ty * 4 + i;
            float inv = 1.f / lrow[rr];
            int s = qt64 * 64 + rr;
#pragma unroll
            for (int j = 0; j < 4; j++) {
                int d = tx * 4 + j;
                size_t idx = ((size_t)(b * SS + s)) * DD + h * 64 + d;
                float val = acc[i][j] * inv;
                bf16 hh = __float2bfloat16(val);
                outh[idx] = hh;
                outl[idx] = __float2bfloat16(val - __bfloat162float(hh));
            }
        }
    }
#endif
#endif // __CUDA_ARCH__
}

// ---------------- router ----------------
__global__ void zero_cnt_kernel() {
    if (threadIdx.x < NE) g_cnt[threadIdx.x] = 0;
}

__global__ void router_kernel(const float* __restrict__ xn2, const float* __restrict__ wr)
{
    int t = blockIdx.x;
    int lane = threadIdx.x;
    float p[NE];
#pragma unroll
    for (int e = 0; e < NE; e++) p[e] = 0.f;
    const float* xr = xn2 + (size_t)t * DD;
    for (int d = lane; d < DD; d += 32) {
        float xv = xr[d];
        const float* wrow = wr + (size_t)d * NE;
#pragma unroll
        for (int e = 0; e < NE; e++) p[e] = fmaf(xv, wrow[e], p[e]);
    }
#pragma unroll
    for (int e = 0; e < NE; e++) {
        for (int o = 16; o > 0; o >>= 1) p[e] += __shfl_xor_sync(0xffffffffu, p[e], o);
    }
    if (lane == 0) {
        float m = p[0];
#pragma unroll
        for (int e = 1; e < NE; e++) m = fmaxf(m, p[e]);
        float pr[NE];
        float sum = 0.f;
#pragma unroll
        for (int e = 0; e < NE; e++) { pr[e] = expf(p[e] - m); sum += pr[e]; }
        float inv = 1.f / sum;
#pragma unroll
        for (int e = 0; e < NE; e++) pr[e] *= inv;
        g_zz[t] = m + logf(sum);
#pragma unroll
        for (int e = 0; e < NE; e++) g_probs[t * NE + e] = pr[e];
        int i0 = 0; float v0 = pr[0];
#pragma unroll
        for (int e = 1; e < NE; e++) if (pr[e] > v0) { v0 = pr[e]; i0 = e; }
        int i1 = -1; float v1 = -1.f;
#pragma unroll
        for (int e = 0; e < NE; e++) { if (e == i0) continue; if (pr[e] > v1) { v1 = pr[e]; i1 = e; } }
        float wsum = v0 + v1;
        float w0 = v0 / wsum, w1 = v1 / wsum;
        int r0 = atomicAdd(&g_cnt[i0], 1); g_rowlist[i0 * TT + r0] = t;
        int r1 = atomicAdd(&g_cnt[i1], 1); g_rowlist[i1 * TT + r1] = t;
        g_slot_e[2 * t]     = i0; g_slot_r[2 * t]     = r0; g_slot_w[2 * t]     = w0;
        g_slot_e[2 * t + 1] = i1; g_slot_r[2 * t + 1] = r1; g_slot_w[2 * t + 1] = w1;
    }
}

// ---------------- loss (deterministic tree reduction) ----------------
__global__ void loss_kernel(float* __restrict__ out, int out_size)
{
    int tid = threadIdx.x;
    __shared__ float red[256];
    __shared__ float sumsp[NE];
    __shared__ float sumz;
    float accp[NE];
#pragma unroll
    for (int e = 0; e < NE; e++) accp[e] = 0.f;
    float accz = 0.f;
    for (int t = tid; t < TT; t += 256) {
        float z = g_zz[t];
        accz += z * z;
#pragma unroll
        for (int e = 0; e < NE; e++) accp[e] += g_probs[t * NE + e];
    }
    red[tid] = accz; __syncthreads();
    for (int o = 128; o > 0; o >>= 1) { if (tid < o) red[tid] += red[tid + o]; __syncthreads(); }
    if (tid == 0) sumz = red[0];
    __syncthreads();
    for (int e = 0; e < NE; e++) {
        red[tid] = accp[e]; __syncthreads();
        for (int o = 128; o > 0; o >>= 1) { if (tid < o) red[tid] += red[tid + o]; __syncthreads(); }
        if (tid == 0) sumsp[e] = red[0];
        __syncthreads();
    }
    if (tid == 0) {
        float aux = 0.f;
        for (int e = 0; e < NE; e++) {
            float ft = (float)g_cnt[e] / (float)TT;
            float fp = sumsp[e] / (float)TT;
            aux += ft * fp;
        }
        aux *= (float)NE / 2.f;
        float loss = aux + 0.001f * (sumz / (float)TT);
        for (int i = NMAIN; i < out_size; i++) out[i] = loss;
    }
}

// ---------------- combine ----------------
__global__ void combine_kernel(float* __restrict__ out)
{
    int idx = blockIdx.x * 256 + threadIdx.x;
    if (idx >= NMAIN) return;
    int t = idx >> 10;
    int d = idx & 1023;
    int e0 = g_slot_e[2 * t], r0 = g_slot_r[2 * t];
    int e1 = g_slot_e[2 * t + 1], r1 = g_slot_r[2 * t + 1];
    float w0 = g_slot_w[2 * t], w1 = g_slot_w[2 * t + 1];
    float y = g_x2[idx]
            + w0 * g_Y[((size_t)e0 * TT + r0) * DD + d]
            + w1 * g_Y[((size_t)e1 * TT + r1) * DD + d];
    out[idx] = y;
}

// ---------------- launch ----------------
extern "C" void kernel_launch(void* const* d_in, const int* in_sizes, int n_in,
                              void* d_out, int out_size)
{
    const float* x   = (const float*)d_in[0];
    const float* ln1 = (const float*)d_in[1];
    const float* ln2 = (const float*)d_in[2];
    const float* wq  = (const float*)d_in[3];
    const float* wk  = (const float*)d_in[4];
    const float* wv  = (const float*)d_in[5];
    const float* wo  = (const float*)d_in[6];
    const float* wr  = (const float*)d_in[7];
    const float* w1  = (const float*)d_in[8];
    const float* w2  = (const float*)d_in[9];
    float* out = (float*)d_out;

    cudaFuncSetAttribute(tc_attn, cudaFuncAttributeMaxDynamicSharedMemorySize, ATT_SMEM);
    cudaFuncSetAttribute(tc_gemm<GM_QKV>,  cudaFuncAttributeMaxDynamicSharedMemorySize, G_SMEM);
    cudaFuncSetAttribute(tc_gemm<GM_RES>,  cudaFuncAttributeMaxDynamicSharedMemorySize, G_SMEM);
    cudaFuncSetAttribute(tc_gemm<GM_MOE1>, cudaFuncAttributeMaxDynamicSharedMemorySize, G_SMEM);
    cudaFuncSetAttribute(tc_gemm<GM_MOE2>, cudaFuncAttributeMaxDynamicSharedMemorySize, G_SMEM);

    bf16 *p_xnh, *p_xnl, *p_xn2h, *p_xn2l, *p_ctxh, *p_ctxl;
    bf16 *p_wpth, *p_wptl, *p_w1th, *p_w1tl, *p_w2th, *p_w2tl, *p_Hh, *p_Hl;
    float *p_xn2, *p_x2, *p_Y;
    cudaGetSymbolAddress((void**)&p_xnh,  g_xnh);
    cudaGetSymbolAddress((void**)&p_xnl,  g_xnl);
    cudaGetSymbolAddress((void**)&p_xn2,  g_xn2);
    cudaGetSymbolAddress((void**)&p_xn2h, g_xn2h);
    cudaGetSymbolAddress((void**)&p_xn2l, g_xn2l);
    cudaGetSymbolAddress((void**)&p_ctxh, g_ctxh);
    cudaGetSymbolAddress((void**)&p_ctxl, g_ctxl);
    cudaGetSymbolAddress((void**)&p_x2,   g_x2);
    cudaGetSymbolAddress((void**)&p_wpth, g_wpth);
    cudaGetSymbolAddress((void**)&p_wptl, g_wptl);
    cudaGetSymbolAddress((void**)&p_w1th, g_w1th);
    cudaGetSymbolAddress((void**)&p_w1tl, g_w1tl);
    cudaGetSymbolAddress((void**)&p_w2th, g_w2th);
    cudaGetSymbolAddress((void**)&p_w2tl, g_w2tl);
    cudaGetSymbolAddress((void**)&p_Hh,   g_Hh);
    cudaGetSymbolAddress((void**)&p_Hl,   g_Hl);
    cudaGetSymbolAddress((void**)&p_Y,    g_Y);

    // 0. weight transpose + bf16 split
    dim3 bt(256);
    wt_convert_kernel<<<dim3(DD/64, DD/64, 1), bt>>>(wq, p_wpth,           p_wptl,           DD, DD);
    wt_convert_kernel<<<dim3(DD/64, DD/64, 1), bt>>>(wk, p_wpth + DD*DD,   p_wptl + DD*DD,   DD, DD);
    wt_convert_kernel<<<dim3(DD/64, DD/64, 1), bt>>>(wv, p_wpth + 2*DD*DD, p_wptl + 2*DD*DD, DD, DD);
    wt_convert_kernel<<<dim3(DD/64, DD/64, 1), bt>>>(wo, p_wpth + 3*DD*DD, p_wptl + 3*DD*DD, DD, DD);
    wt_convert_kernel<<<dim3(FF/64, DD/64, NE), bt>>>(w1, p_w1th, p_w1tl, DD, FF);
    wt_convert_kernel<<<dim3(DD/64, FF/64, NE), bt>>>(w2, p_w2th, p_w2tl, FF, DD);

    // 1. rmsnorm 1
    rmsnorm_kernel<<<TT, 256>>>(x, ln1, nullptr, p_xnh, p_xnl);

    // 2. QKV projections (z selects wq/wk/wv; emits bf16 hi/lo [B,H,S,Dh])
    tc_gemm<GM_QKV><<<dim3(DD/256, TT/128, 3), 256, G_SMEM>>>(
        p_xnh, p_xnl, p_wpth, p_wptl, nullptr, nullptr, nullptr, nullptr, TT, DD, DD);

    // 3. attention (tcgen05, explicit V transpose) -> ctx bf16 split
    tc_attn<<<dim3(BB * NH, SS / 128), 256, ATT_SMEM>>>(p_ctxh, p_ctxl);

    // 4. output projection + residual
    tc_gemm<GM_RES><<<dim3(DD/256, TT/128, 1), 256, G_SMEM>>>(
        p_ctxh, p_ctxl, p_wpth + 3*DD*DD, p_wptl + 3*DD*DD, p_x2, x, nullptr, nullptr, TT, DD, DD);

    // 5. rmsnorm 2
    rmsnorm_kernel<<<TT, 256>>>(p_x2, ln2, p_xn2, p_xn2h, p_xn2l);

    // 6. router
    zero_cnt_kernel<<<1, 32>>>();
    router_kernel<<<TT, 32>>>(p_xn2, wr);

    // 7. loss scalar -> out[NMAIN..]
    loss_kernel<<<1, 256>>>(out, out_size);

    // 8. MoE expert GEMMs (grouped; tiles beyond per-expert count early-exit)
    tc_gemm<GM_MOE1><<<dim3(FF/256, TT/128, NE), 256, G_SMEM>>>(
        p_xn2h, p_xn2l, p_w1th, p_w1tl, nullptr, nullptr, p_Hh, p_Hl, TT, FF, DD);
    tc_gemm<GM_MOE2><<<dim3(DD/256, TT/128, NE), 256, G_SMEM>>>(
        p_Hh, p_Hl, p_w2th, p_w2tl, p_Y, nullptr, nullptr, nullptr, TT, DD, FF);

    // 9. combine + residual -> out
    combine_kernel<<<(NMAIN + 255) / 256, 256>>>(out);
}

// round 7
// speedup vs baseline: 2.8801x; 1.0735x over previous
#include <cuda_runtime.h>
#include <cuda_bf16.h>
#include <math.h>
#include <stdint.h>

#define BB 2
#define SS 2048
#define DD 1024
#define NH 16
#define DH 64
#define NE 8
#define FF 4096
#define TT (BB*SS)   // 4096 tokens
#define NMAIN (TT*DD)

typedef __nv_bfloat16 bf16;

// ---------------- scratch (static device globals; no cudaMalloc allowed) ----
__device__ bf16  g_xnh[TT*DD],  g_xnl[TT*DD];          // rmsnorm1 out, split
__device__ float g_xn2[TT*DD];                          // rmsnorm2 out fp32 (router)
__device__ bf16  g_xn2h[TT*DD], g_xn2l[TT*DD];          // rmsnorm2 out, split
__device__ bf16  g_qkvh[3][(size_t)TT*DD];              // q,k,v hi  [B,H,S,Dh]
__device__ bf16  g_qkvl[3][(size_t)TT*DD];              // q,k,v lo  [B,H,S,Dh]
__device__ bf16  g_ctxh[TT*DD], g_ctxl[TT*DD];          // attention ctx, split
__device__ float g_x2[TT*DD];                           // x + attn_out
__device__ bf16  g_wpth[4*DD*DD], g_wptl[4*DD*DD];      // wq,wk,wv,wo transposed split
__device__ bf16  g_w1th[(size_t)NE*DD*FF], g_w1tl[(size_t)NE*DD*FF];
__device__ bf16  g_w2th[(size_t)NE*DD*FF], g_w2tl[(size_t)NE*DD*FF];
__device__ bf16  g_Hh[(size_t)NE*TT*FF], g_Hl[(size_t)NE*TT*FF];  // gelu(h) split
__device__ float g_Y[(size_t)NE*TT*DD];
__device__ float g_probs[TT*NE];
__device__ float g_zz[TT];
__device__ int   g_cnt[NE];
__device__ int   g_rowlist[NE*TT];
__device__ int   g_slot_e[2*TT];
__device__ int   g_slot_r[2*TT];
__device__ float g_slot_w[2*TT];

// ---------------- PTX helpers ----------------
__device__ __forceinline__ uint32_t smem_u32(const void* p) {
    uint32_t a;
    asm("{ .reg .u64 t; cvta.to.shared.u64 t, %1; cvt.u32.u64 %0, t; }" : "=r"(a) : "l"(p));
    return a;
}
__device__ __forceinline__ uint32_t elect1() {
    uint32_t p;
    asm volatile("{\n.reg .pred p;\nelect.sync _|p, 0xFFFFFFFF;\nselp.b32 %0, 1, 0, p;\n}" : "=r"(p));
    return p;
}
__device__ __forceinline__ void mbar_init(uint32_t a, uint32_t n) {
    asm volatile("mbarrier.init.shared.b64 [%0], %1;" :: "r"(a), "r"(n) : "memory");
}
__device__ __forceinline__ void mbar_wait(uint32_t a, uint32_t par) {
    asm volatile(
        "{\n.reg .pred P;\n"
        "LW%=:\n"
        "mbarrier.try_wait.parity.acquire.cta.shared::cta.b64 P, [%0], %1, 0x989680;\n"
        "@P bra LD%=;\n"
        "bra LW%=;\n"
        "LD%=:\n}"
        :: "r"(a), "r"(par) : "memory");
}
// K-major SW128 descriptor (row = 128B)
__device__ __forceinline__ uint64_t mk_desc(uint32_t addr) {
    return ((uint64_t)2 << 61) | ((uint64_t)1 << 46) | ((uint64_t)64 << 32)
         | ((uint64_t)1 << 16) | ((addr >> 4) & 0x3FFF);
}
__device__ __forceinline__ void tc_commit(uint32_t mbar) {
#if defined(__CUDA_ARCH_FEAT_SM103_ALL)
    asm volatile("tcgen05.commit.cta_group::1.mbarrier::arrive::one.shared::cluster.b64 [%0];"
                 :: "r"(mbar) : "memory");
#endif
}
__device__ __forceinline__ void mma_f16_ss(uint32_t d, uint64_t ad, uint64_t bd,
                                           uint32_t idesc, uint32_t en) {
#if defined(__CUDA_ARCH_FEAT_SM103_ALL)
    asm volatile(
        "{\n.reg .pred p;\n"
        "setp.ne.u32 p, %4, 0;\n"
        "tcgen05.mma.cta_group::1.kind::f16 [%0], %1, %2, %3, {%5, %5, %5, %5}, p;\n}"
        :: "r"(d), "l"(ad), "l"(bd), "r"(idesc), "r"(en), "r"(0u) : "memory");
#endif
}

#if defined(__CUDA_ARCH_FEAT_SM103_ALL)
#define TC_ALLOC(sbaddr, n) \
    asm volatile("tcgen05.alloc.cta_group::1.sync.aligned.shared::cta.b32 [%0], %1;" \
                 :: "r"(sbaddr), "r"((uint32_t)(n)) : "memory")
#define TC_RELINQ() \
    asm volatile("tcgen05.relinquish_alloc_permit.cta_group::1.sync.aligned;")
#define TC_DEALLOC(t, n) \
    asm volatile("tcgen05.dealloc.cta_group::1.sync.aligned.b32 %0, %1;" :: "r"(t), "r"((uint32_t)(n)))
#define TC_FENCE_AFTER()  asm volatile("tcgen05.fence::after_thread_sync;" ::: "memory")
#define TC_FENCE_BEFORE() asm volatile("tcgen05.fence::before_thread_sync;" ::: "memory")
#define TC_WAIT_LD()      asm volatile("tcgen05.wait::ld.sync.aligned;" ::: "memory")
#define TC_LD_X32(r, ta) \
    asm volatile( \
        "tcgen05.ld.sync.aligned.32x32b.x32.b32 " \
        "{%0, %1, %2, %3, %4, %5, %6, %7, " \
        " %8, %9, %10, %11, %12, %13, %14, %15, " \
        " %16, %17, %18, %19, %20, %21, %22, %23, " \
        " %24, %25, %26, %27, %28, %29, %30, %31}, [%32];" \
        : "=r"((r)[0]),  "=r"((r)[1]),  "=r"((r)[2]),  "=r"((r)[3]), \
          "=r"((r)[4]),  "=r"((r)[5]),  "=r"((r)[6]),  "=r"((r)[7]), \
          "=r"((r)[8]),  "=r"((r)[9]),  "=r"((r)[10]), "=r"((r)[11]), \
          "=r"((r)[12]), "=r"((r)[13]), "=r"((r)[14]), "=r"((r)[15]), \
          "=r"((r)[16]), "=r"((r)[17]), "=r"((r)[18]), "=r"((r)[19]), \
          "=r"((r)[20]), "=r"((r)[21]), "=r"((r)[22]), "=r"((r)[23]), \
          "=r"((r)[24]), "=r"((r)[25]), "=r"((r)[26]), "=r"((r)[27]), \
          "=r"((r)[28]), "=r"((r)[29]), "=r"((r)[30]), "=r"((r)[31]) \
        : "r"(ta))
#endif

__device__ __forceinline__ float gelu_tanh(float x) {
    float x3 = x * x * x;
    return 0.5f * x * (1.f + tanhf(0.7978845608028654f * (x + 0.044715f * x3)));
}
__device__ __forceinline__ uint32_t pack_bf2(float a, float b) {
    return ((uint32_t)__bfloat16_as_ushort(__float2bfloat16(b)) << 16)
         |  (uint32_t)__bfloat16_as_ushort(__float2bfloat16(a));
}

// ---------------- rmsnorm (writes fp32 optional + bf16 hi/lo) ----------------
__global__ void rmsnorm_kernel(const float* __restrict__ x, const float* __restrict__ w,
                               float* __restrict__ yf, bf16* __restrict__ yh, bf16* __restrict__ yl)
{
    int row = blockIdx.x;
    int tid = threadIdx.x;
    const float* xr = x + (size_t)row * DD;
    float s = 0.f;
    for (int d = tid; d < DD; d += 256) { float v = xr[d]; s += v * v; }
    __shared__ float red[256];
    red[tid] = s; __syncthreads();
    for (int o = 128; o > 0; o >>= 1) { if (tid < o) red[tid] += red[tid + o]; __syncthreads(); }
    float inv = rsqrtf(red[0] / (float)DD + 1e-6f);
    size_t base = (size_t)row * DD;
    for (int d = tid; d < DD; d += 256) {
        float v = xr[d] * inv * w[d];
        if (yf) yf[base + d] = v;
        bf16 h = __float2bfloat16(v);
        yh[base + d] = h;
        yl[base + d] = __float2bfloat16(v - __bfloat162float(h));
    }
}

// ---------------- weight transpose + bf16 split (vectorized) ----------------
__global__ void wt_convert_kernel(const float* __restrict__ W,
                                  bf16* __restrict__ Th, bf16* __restrict__ Tl,
                                  int K, int N)
{
    __shared__ float tile[64][68];
    size_t zoff = (size_t)blockIdx.z * K * N;
    int n0 = blockIdx.x * 64, k0 = blockIdx.y * 64;
    int tx = threadIdx.x & 15, ty = threadIdx.x >> 4;   // 16x16
#pragma unroll
    for (int i = 0; i < 4; i++) {
        int r = ty + 16 * i;
        float4 v = *(const float4*)(W + zoff + (size_t)(k0 + r) * N + n0 + tx * 4);
        *(float4*)&tile[r][tx * 4] = v;
    }
    __syncthreads();
#pragma unroll
    for (int i = 0; i < 4; i++) {
        int n = ty + 16 * i;
        int kk = tx * 4;
        float v0 = tile[kk + 0][n], v1 = tile[kk + 1][n];
        float v2 = tile[kk + 2][n], v3 = tile[kk + 3][n];
        bf16 h0 = __float2bfloat16(v0), h1 = __float2bfloat16(v1);
        bf16 h2 = __float2bfloat16(v2), h3 = __float2bfloat16(v3);
        float l0 = v0 - __bfloat162float(h0), l1 = v1 - __bfloat162float(h1);
        float l2 = v2 - __bfloat162float(h2), l3 = v3 - __bfloat162float(h3);
        size_t idx = zoff + (size_t)(n0 + n) * K + k0 + kk;
        uint2 ph, pl;
        ph.x = ((uint32_t)__bfloat16_as_ushort(h1) << 16) | __bfloat16_as_ushort(h0);
        ph.y = ((uint32_t)__bfloat16_as_ushort(h3) << 16) | __bfloat16_as_ushort(h2);
        pl.x = pack_bf2(l0, l1);
        pl.y = pack_bf2(l2, l3);
        *(uint2*)(Th + idx) = ph;
        *(uint2*)(Tl + idx) = pl;
    }
}

// ---------------- GEMM modes ----------------
#define GM_QKV  1
#define GM_RES  2
#define GM_MOE1 3
#define GM_MOE2 4
// N=256 tiles: per-chunk buffer {Ah 16K, Al 16K, Bh 32K, Bl 32K} = 96 KB, x2
#define BUF_BYTES 98304
#define G_SMEM  (1024 + 2 * BUF_BYTES)   // 197632 B

// scalar store (fallback path only)
template<int MODE>
__device__ __forceinline__ void store_elem(int e, int N, int row, int col, float v,
        float* __restrict__ Cf, const float* __restrict__ Res,
        bf16* __restrict__ Ch, bf16* __restrict__ Cl)
{
    if (MODE == GM_QKV) {
        int b = row >> 11, s5 = row & (SS - 1);
        int h = col >> 6, dh = col & 63;
        size_t o = (((size_t)(b * NH + h)) * SS + s5) * DH + dh;
        bf16 hh = __float2bfloat16(v);
        g_qkvh[e][o] = hh;
        g_qkvl[e][o] = __float2bfloat16(v - __bfloat162float(hh));
    } else if (MODE == GM_RES) {
        size_t o = (size_t)row * N + col;
        Cf[o] = v + Res[o];
    } else if (MODE == GM_MOE1) {
        size_t o = ((size_t)e * TT + row) * N + col;
        float g = gelu_tanh(v);
        bf16 h = __float2bfloat16(g);
        Ch[o] = h;
        Cl[o] = __float2bfloat16(g - __bfloat162float(h));
    } else {
        Cf[((size_t)e * TT + row) * N + col] = v;
    }
}

// ---------------- tcgen05 GEMM: C[128x256] tiles, 3-term bf16 split,
//                  cp.async double-buffered pipeline, N=256 MMAs ------------
template<int MODE>
__global__ void __launch_bounds__(256, 1)
tc_gemm(const bf16* __restrict__ Ah, const bf16* __restrict__ Al,
        const bf16* __restrict__ Bh0, const bf16* __restrict__ Bl0,
        float* __restrict__ Cf, const float* __restrict__ Res,
        bf16* __restrict__ Ch, bf16* __restrict__ Cl,
        int M, int N, int K)
{
#if defined(__CUDA_ARCH__)
    extern __shared__ char sm[];
    int tid = threadIdx.x;
    int e  = blockIdx.z;
    int m0 = blockIdx.y * 128, n0 = blockIdx.x * 256;
    int Me = M;
    const bf16* Bh = Bh0;
    const bf16* Bl = Bl0;
    if (MODE == GM_MOE1 || MODE == GM_MOE2) {
        Me = g_cnt[e];
        if (m0 >= Me) return;
        Bh += (size_t)e * (size_t)K * N; Bl += (size_t)e * (size_t)K * N;
    } else if (MODE == GM_QKV) {
        Bh += (size_t)e * (size_t)K * N; Bl += (size_t)e * (size_t)K * N;
    }

#if defined(__CUDA_ARCH_FEAT_SM103_ALL)
    uint32_t sb = smem_u32(sm);
    int wid = tid >> 5, lid = tid & 31;
    int nk = K / 64;

    // fill chunk kc into buffer bufi via cp.async (384 row tasks: 128 A + 256 B)
    auto issue_fill = [&](int kc, int bufi) {
        uint32_t tb = sb + 1024 + (uint32_t)bufi * BUF_BYTES;
        for (int task = tid; task < 384; task += 256) {
            const bf16 *sh, *sl;
            uint32_t regionH, regionL;
            int row;
            bool val = true;
            if (task < 128) {
                int gr = m0 + task;
                val = gr < Me;
                size_t ri = 0;
                if (val) {
                    if (MODE == GM_MOE1)      ri = (size_t)g_rowlist[e * TT + gr];
                    else if (MODE == GM_MOE2) ri = (size_t)e * TT + gr;
                    else                      ri = (size_t)gr;
                }
                sh = Ah + ri * (size_t)K;
                sl = Al + ri * (size_t)K;
                regionH = tb; regionL = tb + 16384;
                row = task;
            } else {
                row = task - 128;
                sh = Bh + (size_t)(n0 + row) * K;
                sl = Bl + (size_t)(n0 + row) * K;
                regionH = tb + 32768; regionL = tb + 65536;
            }
            const char* srcH = (const char*)(sh + kc * 64);
            const char* srcL = (const char*)(sl + kc * 64);
            uint32_t sz = val ? 16u : 0u;
#pragma unroll
            for (int j = 0; j < 8; j++) {
                uint32_t off = (uint32_t)row * 128u + j * 16u;
                uint32_t swz = off ^ ((off >> 3) & 0x70);
                asm volatile("cp.async.cg.shared.global [%0], [%1], 16, %2;"
                             :: "r"(regionH + swz), "l"(srcH + j * 16), "r"(sz) : "memory");
                asm volatile("cp.async.cg.shared.global [%0], [%1], 16, %2;"
                             :: "r"(regionL + swz), "l"(srcL + j * 16), "r"(sz) : "memory");
            }
        }
        asm volatile("cp.async.commit_group;" ::: "memory");
    };

    // prologue: start chunks 0 and 1 immediately (overlaps TMEM alloc)
    issue_fill(0, 0);
    if (nk > 1) issue_fill(1, 1);

    if (wid == 0) { TC_ALLOC(sb, 256); TC_RELINQ(); }
    if (tid == 0) { mbar_init(sb + 8, 1); mbar_init(sb + 16, 1); }
    __syncthreads();
    uint32_t tmem;
    asm volatile("ld.shared.b32 %0, [%1];" : "=r"(tmem) : "r"(sb));

    const uint32_t IDESC = (1u << 4) | (1u << 7) | (1u << 10) | (32u << 17) | (8u << 24);
    int ph0 = 0, ph1 = 0;
    for (int kc = 0; kc < nk; kc++) {
        int b = kc & 1;
        if (kc >= 1 && kc + 1 < nk) {
            int nb = 1 - b;
            // buffer nb was consumed by chunk kc-1's MMAs; wait then refill
            if (nb == 0) { mbar_wait(sb + 8,  (uint32_t)(ph0 & 1)); ph0++; }
            else         { mbar_wait(sb + 16, (uint32_t)(ph1 & 1)); ph1++; }
            issue_fill(kc + 1, nb);
        }
        if (kc + 1 < nk) asm volatile("cp.async.wait_group 1;" ::: "memory");
        else             asm volatile("cp.async.wait_group 0;" ::: "memory");
        asm volatile("fence.proxy.async.shared::cta;" ::: "memory");
        __syncthreads();
        if (wid == 0 && elect1()) {
            uint32_t tb = sb + 1024 + (uint32_t)b * BUF_BYTES;
            uint64_t dAh = mk_desc(tb);
            uint64_t dAl = mk_desc(tb + 16384);
            uint64_t dBh = mk_desc(tb + 32768);
            uint64_t dBl = mk_desc(tb + 65536);
#pragma unroll
            for (int s = 0; s < 4; s++) {
                uint32_t en0 = (kc == 0 && s == 0) ? 0u : 1u;
                mma_f16_ss(tmem, dAh + 2 * s, dBh + 2 * s, IDESC, en0);
                mma_f16_ss(tmem, dAh + 2 * s, dBl + 2 * s, IDESC, 1u);
                mma_f16_ss(tmem, dAl + 2 * s, dBh + 2 * s, IDESC, 1u);
            }
            tc_commit(sb + 8 + b * 8);
        }
    }
    {
        int lb = (nk - 1) & 1;
        if (lb == 0) mbar_wait(sb + 8,  (uint32_t)(ph0 & 1));
        else         mbar_wait(sb + 16, (uint32_t)(ph1 & 1));
    }
    TC_FENCE_AFTER();

    // ---- staged epilogue: two 128-col passes, TMEM -> smem -> coalesced ----
    int rw = wid & 3, cw = wid >> 2;
    int rows_here = Me - m0; if (rows_here > 128) rows_here = 128;
    float* Cs = (float*)(sm + 1024);
#pragma unroll 1
    for (int p = 0; p < 2; p++) {
        uint32_t d0[32], d1[32];
        TC_LD_X32(d0, tmem + p * 128 + cw * 64);
        TC_LD_X32(d1, tmem + p * 128 + cw * 64 + 32);
        TC_WAIT_LD();
        TC_FENCE_BEFORE();
        __syncthreads();
        {
            int rr = rw * 32 + lid;
            int cb = cw * 64;
#pragma unroll
            for (int j = 0; j < 32; j++) {
                Cs[rr * 129 + cb + j]      = __uint_as_float(d0[j]);
                Cs[rr * 129 + cb + 32 + j] = __uint_as_float(d1[j]);
            }
        }
        __syncthreads();
#pragma unroll 4
        for (int it = 0; it < 16; it++) {
            int idx4 = (it * 256 + tid) * 4;
            int rr = idx4 >> 7, cc = idx4 & 127;
            if (rr >= rows_here) continue;
            float v0 = Cs[rr * 129 + cc + 0];
            float v1 = Cs[rr * 129 + cc + 1];
            float v2 = Cs[rr * 129 + cc + 2];
            float v3 = Cs[rr * 129 + cc + 3];
            int colb = n0 + p * 128 + cc;
            if (MODE == GM_RES) {
                size_t o = (size_t)(m0 + rr) * N + colb;
                float4 rs = *(const float4*)(Res + o);
                *(float4*)(Cf + o) = make_float4(v0 + rs.x, v1 + rs.y, v2 + rs.z, v3 + rs.w);
            } else if (MODE == GM_MOE2) {
                size_t o = ((size_t)e * TT + m0 + rr) * N + colb;
                *(float4*)(Cf + o) = make_float4(v0, v1, v2, v3);
            } else if (MODE == GM_MOE1) {
                size_t o = ((size_t)e * TT + m0 + rr) * N + colb;
                float g0 = gelu_tanh(v0), g1 = gelu_tanh(v1);
                float g2 = gelu_tanh(v2), g3 = gelu_tanh(v3);
                bf16 h0 = __float2bfloat16(g0), h1 = __float2bfloat16(g1);
                bf16 h2 = __float2bfloat16(g2), h3 = __float2bfloat16(g3);
                uint2 ph, pl;
                ph.x = ((uint32_t)__bfloat16_as_ushort(h1) << 16) | __bfloat16_as_ushort(h0);
                ph.y = ((uint32_t)__bfloat16_as_ushort(h3) << 16) | __bfloat16_as_ushort(h2);
                pl.x = pack_bf2(g0 - __bfloat162float(h0), g1 - __bfloat162float(h1));
                pl.y = pack_bf2(g2 - __bfloat162float(h2), g3 - __bfloat162float(h3));
                *(uint2*)(Ch + o) = ph;
                *(uint2*)(Cl + o) = pl;
            } else { // GM_QKV -> bf16 hi/lo [B,H,S,Dh]
                int row = m0 + rr;
                int b2 = row >> 11, s5 = row & (SS - 1);
                int h = colb >> 6, dh = colb & 63;
                size_t o = (((size_t)(b2 * NH + h)) * SS + s5) * DH + dh;
                bf16 h0 = __float2bfloat16(v0), h1 = __float2bfloat16(v1);
                bf16 h2 = __float2bfloat16(v2), h3 = __float2bfloat16(v3);
                uint2 ph, pl;
                ph.x = ((uint32_t)__bfloat16_as_ushort(h1) << 16) | __bfloat16_as_ushort(h0);
                ph.y = ((uint32_t)__bfloat16_as_ushort(h3) << 16) | __bfloat16_as_ushort(h2);
                pl.x = pack_bf2(v0 - __bfloat162float(h0), v1 - __bfloat162float(h1));
                pl.y = pack_bf2(v2 - __bfloat162float(h2), v3 - __bfloat162float(h3));
                *(uint2*)(g_qkvh[e] + o) = ph;
                *(uint2*)(g_qkvl[e] + o) = pl;
            }
        }
        __syncthreads();
    }
    if (wid == 0) { TC_DEALLOC(tmem, 256); }

#else
    // ---- SIMT fallback (base-arch pass): two 128-col halves ----
    float* As = (float*)sm;
    float* Bs = As + 16 * 128;
    int tx = tid & 15, ty = tid >> 4;
    for (int half = 0; half < 2; half++) {
        int n0h = n0 + half * 128;
        float acc[8][8];
#pragma unroll
        for (int i = 0; i < 8; i++)
#pragma unroll
            for (int j = 0; j < 8; j++) acc[i][j] = 0.f;
        for (int k0 = 0; k0 < K; k0 += 16) {
            __syncthreads();
            for (int l = tid; l < 16 * 128; l += 256) {
                int kk = l >> 7, rr = l & 127;
                int gr = m0 + rr;
                float av = 0.f;
                if (gr < Me) {
                    size_t ri;
                    if (MODE == GM_MOE1)      ri = (size_t)g_rowlist[e * TT + gr];
                    else if (MODE == GM_MOE2) ri = (size_t)e * TT + gr;
                    else                      ri = (size_t)gr;
                    av = __bfloat162float(Ah[ri * (size_t)K + k0 + kk])
                       + __bfloat162float(Al[ri * (size_t)K + k0 + kk]);
                }
                As[kk * 128 + rr] = av;
                Bs[kk * 128 + rr] = __bfloat162float(Bh[(size_t)(n0h + rr) * K + k0 + kk])
                                  + __bfloat162float(Bl[(size_t)(n0h + rr) * K + k0 + kk]);
            }
            __syncthreads();
            for (int kk = 0; kk < 16; kk++) {
                float ar[8], br[8];
#pragma unroll
                for (int i = 0; i < 8; i++) ar[i] = As[kk * 128 + ty * 8 + i];
#pragma unroll
                for (int j = 0; j < 8; j++) br[j] = Bs[kk * 128 + tx * 8 + j];
#pragma unroll
                for (int i = 0; i < 8; i++)
#pragma unroll
                    for (int j = 0; j < 8; j++) acc[i][j] = fmaf(ar[i], br[j], acc[i][j]);
            }
        }
#pragma unroll
        for (int i = 0; i < 8; i++) {
            int row = m0 + ty * 8 + i;
            if (row >= Me) continue;
#pragma unroll
            for (int j = 0; j < 8; j++)
                store_elem<MODE>(e, N, row, n0h + tx * 8 + j, acc[i][j], Cf, Res, Ch, Cl);
        }
        __syncthreads();
    }
#endif
#endif // __CUDA_ARCH__
}

// ---------------- tcgen05 flash attention, cp.async KV prefetch ------------
#define SM_Q   1024
#define SM_K   33792
#define SM_VST 66560
#define SM_VT  99328
#define SM_P   132096
#define ATT_SMEM 197632

__global__ void __launch_bounds__(256, 1)
tc_attn(bf16* __restrict__ outh, bf16* __restrict__ outl)
{
#if defined(__CUDA_ARCH__)
    extern __shared__ char sm[];
    int tid = threadIdx.x;
    int bh = blockIdx.x;
    int qt = blockIdx.y;

#if defined(__CUDA_ARCH_FEAT_SM103_ALL)
    uint32_t sb = smem_u32(sm);
    int wid = tid >> 5, lane = tid & 31;

    // async fill of K (swizzled) + V (linear) hi/lo for chunk kt
    auto fill_kv = [&](int kt) {
#pragma unroll
        for (int i = 0; i < 2; i++) {
            int task = tid + i * 256;
            int arr = task >> 7, r = task & 127;
            const bf16* src;
            uint32_t dstb;
            if (arr == 0)      { src = g_qkvh[1]; dstb = sb + SM_K; }
            else if (arr == 1) { src = g_qkvl[1]; dstb = sb + SM_K + 16384; }
            else if (arr == 2) { src = g_qkvh[2]; dstb = sb + SM_VST; }
            else               { src = g_qkvl[2]; dstb = sb + SM_VST + 16384; }
            const char* s4 = (const char*)(src + ((size_t)bh * SS + kt * 128 + r) * DH);
            if (arr < 2) {
#pragma unroll
                for (int j = 0; j < 8; j++) {
                    uint32_t off = (uint32_t)r * 128u + j * 16u;
                    uint32_t swz = off ^ ((off >> 3) & 0x70);
                    asm volatile("cp.async.cg.shared.global [%0], [%1], 16;"
                                 :: "r"(dstb + swz), "l"(s4 + j * 16) : "memory");
                }
            } else {
#pragma unroll
                for (int j = 0; j < 8; j++)
                    asm volatile("cp.async.cg.shared.global [%0], [%1], 16;"
                                 :: "r"(dstb + (uint32_t)r * 128u + j * 16u), "l"(s4 + j * 16) : "memory");
            }
        }
        asm volatile("cp.async.commit_group;" ::: "memory");
    };

    // prologue: kick off chunk 0 loads immediately
    fill_kv(0);

    if (wid == 0) { TC_ALLOC(sb, 256); TC_RELINQ(); }
    if (tid == 0) { mbar_init(sb + 8, 1); mbar_init(sb + 16, 1); }
    __syncthreads();
    uint32_t tmem;
    asm volatile("ld.shared.b32 %0, [%1];" : "=r"(tmem) : "r"(sb));

    // load Q tile (hi/lo): threads 0-127 hi rows, 128-255 lo rows
    {
        int r = tid & 127;
        const bf16* src = (tid < 128 ? g_qkvh[0] : g_qkvl[0])
                        + ((size_t)bh * SS + qt * 128 + r) * DH;
        char* dst = sm + SM_Q + (tid < 128 ? 0 : 16384);
        const uint4* s4 = (const uint4*)src;
#pragma unroll
        for (int j = 0; j < 8; j++) {
            uint32_t off = (uint32_t)r * 128u + j * 16u;
            uint32_t swz = off ^ ((off >> 3) & 0x70);
            *(uint4*)(dst + swz) = s4[j];
        }
    }

    const uint32_t IDESC_S = (1u << 4) | (1u << 7) | (1u << 10) | (16u << 17) | (8u << 24);
    const uint32_t IDESC_O = (1u << 4) | (1u << 7) | (1u << 10) | (8u << 17) | (8u << 24);
    int sph = 0, oph = 0;
    float lpart = 0.f;
    const int NKT = SS / 128;

    for (int kt = 0; kt < NKT; kt++) {
        if (kt > 0) { mbar_wait(sb + 16, (uint32_t)(oph & 1)); oph++; }  // PV of kt-1 done
        asm volatile("cp.async.wait_group 0;" ::: "memory");             // KV chunk kt arrived
        asm volatile("fence.proxy.async.shared::cta;" ::: "memory");
        __syncthreads();

        // scores: S = Qh*Kh + Qh*Kl + Ql*Kh (M=128,N=128,K=64)
        if (wid == 0 && elect1()) {
            uint64_t dQh = mk_desc(sb + SM_Q);
            uint64_t dQl = mk_desc(sb + SM_Q + 16384);
            uint64_t dKh = mk_desc(sb + SM_K);
            uint64_t dKl = mk_desc(sb + SM_K + 16384);
#pragma unroll
            for (int ks = 0; ks < 4; ks++) {
                mma_f16_ss(tmem, dQh + 2 * ks, dKh + 2 * ks, IDESC_S, ks == 0 ? 0u : 1u);
                mma_f16_ss(tmem, dQh + 2 * ks, dKl + 2 * ks, IDESC_S, 1u);
                mma_f16_ss(tmem, dQl + 2 * ks, dKh + 2 * ks, IDESC_S, 1u);
            }
            tc_commit(sb + 8);
        }

        // transpose V (overlaps S MMA): VT block kb = [64 d-rows][64 s], SW128
        {
            int a  = tid >> 7;
            int i2 = tid & 127;
            int d  = i2 >> 1;
            int shb = i2 & 1;
            const unsigned short* vs = (const unsigned short*)(sm + SM_VST + a * 16384);
            char* vt = sm + SM_VT + a * 16384 + shb * 8192;
#pragma unroll
            for (int m = 0; m < 32; m++) {
                int s0 = shb * 64 + 2 * m;
                uint32_t u = (uint32_t)vs[s0 * 64 + d]
                           | ((uint32_t)vs[(s0 + 1) * 64 + d] << 16);
                uint32_t off = (uint32_t)d * 128u + m * 4u;
                uint32_t swz = off ^ ((off >> 3) & 0x70);
                *(uint32_t*)(vt + swz) = u;
            }
        }
        asm volatile("fence.proxy.async.shared::cta;" ::: "memory");
        __syncthreads();                                  // VT visible; VST free

        mbar_wait(sb + 8, (uint32_t)(sph & 1)); sph++;    // S MMA done; K smem free
        TC_FENCE_AFTER();

        // prefetch next KV chunk, overlapping exp epilogue + PV MMA
        if (kt + 1 < NKT) fill_kv(kt + 1);

        // read S, exp, accumulate l, write P (bf16 hi/lo) to smem
        {
            int rw = wid & 3, cw = wid >> 2;
            uint32_t s0[32], s1[32];
            TC_LD_X32(s0, tmem + cw * 64);
            TC_LD_X32(s1, tmem + cw * 64 + 32);
            TC_WAIT_LD();
            TC_FENCE_BEFORE();
            int r = rw * 32 + lane;
            char* pbh = sm + SM_P + cw * 16384;
            char* pbl = sm + SM_P + 32768 + cw * 16384;
#pragma unroll
            for (int m = 0; m < 32; m++) {
                int c0 = 2 * m, c1 = 2 * m + 1;
                float a = __uint_as_float(c0 < 32 ? s0[c0] : s1[c0 - 32]);
                float b = __uint_as_float(c1 < 32 ? s0[c1] : s1[c1 - 32]);
                float pa = __expf(a * 0.125f);
                float pb = __expf(b * 0.125f);
                lpart += pa + pb;
                bf16 ha = __float2bfloat16(pa), hb = __float2bfloat16(pb);
                float la = pa - __bfloat162float(ha), lb = pb - __bfloat162float(hb);
                uint32_t uph = ((uint32_t)__bfloat16_as_ushort(hb) << 16) | __bfloat16_as_ushort(ha);
                uint32_t upl = pack_bf2(la, lb);
                uint32_t off = (uint32_t)r * 128u + m * 4u;
                uint32_t swz = off ^ ((off >> 3) & 0x70);
                *(uint32_t*)(pbh + swz) = uph;
                *(uint32_t*)(pbl + swz) = upl;
            }
        }
        asm volatile("fence.proxy.async.shared::cta;" ::: "memory");
        __syncthreads();

        // O += Ph*VTh + Pl*VTh + Ph*VTl (plain K-major, M=128,N=64,K=64 per kb)
        if (wid == 0 && elect1()) {
#pragma unroll
            for (int kb = 0; kb < 2; kb++) {
                uint64_t dPh = mk_desc(sb + SM_P + kb * 16384);
                uint64_t dPl = mk_desc(sb + SM_P + 32768 + kb * 16384);
                uint64_t dVh = mk_desc(sb + SM_VT + kb * 8192);
                uint64_t dVl = mk_desc(sb + SM_VT + 16384 + kb * 8192);
#pragma unroll
                for (int ks = 0; ks < 4; ks++) {
                    uint32_t en0 = (kt == 0 && kb == 0 && ks == 0) ? 0u : 1u;
                    mma_f16_ss(tmem + 128, dPh + 2 * ks, dVh + 2 * ks, IDESC_O, en0);
                    mma_f16_ss(tmem + 128, dPl + 2 * ks, dVh + 2 * ks, IDESC_O, 1u);
                    mma_f16_ss(tmem + 128, dPh + 2 * ks, dVl + 2 * ks, IDESC_O, 1u);
                }
            }
            tc_commit(sb + 16);
        }
    }
    mbar_wait(sb + 16, (uint32_t)(oph & 1)); oph++;
    TC_FENCE_AFTER();

    float* lred = (float*)(sm + SM_P);
    lred[tid] = lpart;
    __syncthreads();
    if (wid < 4) {
        uint32_t o0[32], o1[32];
        TC_LD_X32(o0, tmem + 128);
        TC_LD_X32(o1, tmem + 160);
        TC_WAIT_LD();
        TC_FENCE_BEFORE();
        int r = wid * 32 + lane;
        float inv = 1.f / (lred[r] + lred[r + 128]);
        int b = bh >> 4, h = bh & 15;
        int s = qt * 128 + r;
        size_t base = ((size_t)(b * SS + s)) * DD + h * 64;
        uint32_t* ph = (uint32_t*)(outh + base);
        uint32_t* pl = (uint32_t*)(outl + base);
#pragma unroll
        for (int m = 0; m < 32; m++) {
            int c0 = 2 * m, c1 = 2 * m + 1;
            float v0 = __uint_as_float(c0 < 32 ? o0[c0] : o1[c0 - 32]) * inv;
            float v1 = __uint_as_float(c1 < 32 ? o0[c1] : o1[c1 - 32]) * inv;
            bf16 h0 = __float2bfloat16(v0), h1 = __float2bfloat16(v1);
            ph[m] = ((uint32_t)__bfloat16_as_ushort(h1) << 16) | __bfloat16_as_ushort(h0);
            pl[m] = pack_bf2(v0 - __bfloat162float(h0), v1 - __bfloat162float(h1));
        }
    }
    __syncthreads();
    if (wid == 0) { TC_DEALLOC(tmem, 256); }

#else
    // ---- SIMT fallback: two 64-row halves per CTA ----
    float* smf  = (float*)sm;
    float* Qs   = smf;
    float* Ks   = Qs + 64 * 65;
    float* Vs   = Ks + 64 * 65;
    float* Ps   = Vs + 64 * 65;
    float* mrow = Ps + 64 * 65;
    float* lrow = mrow + 64;
    float* arow = lrow + 64;
    int tx = tid & 15, ty = tid >> 4;
    const float scale = 0.125f;
    int b = bh >> 4, h = bh & 15;

    for (int h2 = 0; h2 < 2; h2++) {
        int qt64 = qt * 2 + h2;
        __syncthreads();
        for (int i = tid; i < 64 * 64; i += 256) {
            int r = i >> 6, d = i & 63;
            size_t o = ((size_t)bh * SS + qt64 * 64 + r) * DH + d;
            Qs[r * 65 + d] = (__bfloat162float(g_qkvh[0][o]) + __bfloat162float(g_qkvl[0][o])) * scale;
        }
        if (tid < 64) { mrow[tid] = -1e30f; lrow[tid] = 0.f; }
        float acc[4][4];
#pragma unroll
        for (int i = 0; i < 4; i++)
#pragma unroll
            for (int j = 0; j < 4; j++) acc[i][j] = 0.f;
        __syncthreads();

        for (int kt = 0; kt < SS / 64; kt++) {
            for (int i = tid; i < 64 * 64; i += 256) {
                int r = i >> 6, d = i & 63;
                size_t o = ((size_t)bh * SS + kt * 64 + r) * DH + d;
                Ks[r * 65 + d] = __bfloat162float(g_qkvh[1][o]) + __bfloat162float(g_qkvl[1][o]);
                Vs[r * 65 + d] = __bfloat162float(g_qkvh[2][o]) + __bfloat162float(g_qkvl[2][o]);
            }
            __syncthreads();
            float sv[4][4];
#pragma unroll
            for (int i = 0; i < 4; i++)
#pragma unroll
                for (int j = 0; j < 4; j++) sv[i][j] = 0.f;
            for (int d = 0; d < 64; d++) {
                float ar[4], br[4];
#pragma unroll
                for (int i = 0; i < 4; i++) ar[i] = Qs[(ty * 4 + i) * 65 + d];
#pragma unroll
                for (int j = 0; j < 4; j++) br[j] = Ks[(tx * 4 + j) * 65 + d];
#pragma unroll
                for (int i = 0; i < 4; i++)
#pragma unroll
                    for (int j = 0; j < 4; j++) sv[i][j] = fmaf(ar[i], br[j], sv[i][j]);
            }
#pragma unroll
            for (int i = 0; i < 4; i++)
#pragma unroll
                for (int j = 0; j < 4; j++)
                    Ps[(ty * 4 + i) * 65 + tx * 4 + j] = sv[i][j];
            __syncthreads();
            if (tid < 64) {
                int rr = tid;
                float m = mrow[rr], mx = m;
                for (int c = 0; c < 64; c++) mx = fmaxf(mx, Ps[rr * 65 + c]);
                float a = expf(m - mx), sum = 0.f;
                for (int c = 0; c < 64; c++) {
                    float p = expf(Ps[rr * 65 + c] - mx);
                    Ps[rr * 65 + c] = p; sum += p;
                }
                lrow[rr] = lrow[rr] * a + sum; mrow[rr] = mx; arow[rr] = a;
            }
            __syncthreads();
#pragma unroll
            for (int i = 0; i < 4; i++) {
                float a = arow[ty * 4 + i];
#pragma unroll
                for (int j = 0; j < 4; j++) acc[i][j] *= a;
            }
            for (int kk = 0; kk < 64; kk++) {
                float pr[4], vr[4];
#pragma unroll
                for (int i = 0; i < 4; i++) pr[i] = Ps[(ty * 4 + i) * 65 + kk];
#pragma unroll
                for (int j = 0; j < 4; j++) vr[j] = Vs[kk * 65 + tx * 4 + j];
#pragma unroll
                for (int i = 0; i < 4; i++)
#pragma unroll
                    for (int j = 0; j < 4; j++) acc[i][j] = fmaf(pr[i], vr[j], acc[i][j]);
            }
            __syncthreads();
        }
#pragma unroll
        for (int i = 0; i < 4; i++) {
            int rr = ty * 4 + i;
            float inv = 1.f / lrow[rr];
            int s = qt64 * 64 + rr;
#pragma unroll
            for (int j = 0; j < 4; j++) {
                int d = tx * 4 + j;
                size_t idx = ((size_t)(b * SS + s)) * DD + h * 64 + d;
                float val = acc[i][j] * inv;
                bf16 hh = __float2bfloat16(val);
                outh[idx] = hh;
                outl[idx] = __float2bfloat16(val - __bfloat162float(hh));
            }
        }
    }
#endif
#endif // __CUDA_ARCH__
}

// ---------------- router ----------------
__global__ void zero_cnt_kernel() {
    if (threadIdx.x < NE) g_cnt[threadIdx.x] = 0;
}

__global__ void router_kernel(const float* __restrict__ xn2, const float* __restrict__ wr)
{
    int t = blockIdx.x;
    int lane = threadIdx.x;
    float p[NE];
#pragma unroll
    for (int e = 0; e < NE; e++) p[e] = 0.f;
    const float* xr = xn2 + (size_t)t * DD;
    for (int d = lane; d < DD; d += 32) {
        float xv = xr[d];
        const float* wrow = wr + (size_t)d * NE;
#pragma unroll
        for (int e = 0; e < NE; e++) p[e] = fmaf(xv, wrow[e], p[e]);
    }
#pragma unroll
    for (int e = 0; e < NE; e++) {
        for (int o = 16; o > 0; o >>= 1) p[e] += __shfl_xor_sync(0xffffffffu, p[e], o);
    }
    if (lane == 0) {
        float m = p[0];
#pragma unroll
        for (int e = 1; e < NE; e++) m = fmaxf(m, p[e]);
        float pr[NE];
        float sum = 0.f;
#pragma unroll
        for (int e = 0; e < NE; e++) { pr[e] = expf(p[e] - m); sum += pr[e]; }
        float inv = 1.f / sum;
#pragma unroll
        for (int e = 0; e < NE; e++) pr[e] *= inv;
        g_zz[t] = m + logf(sum);
#pragma unroll
        for (int e = 0; e < NE; e++) g_probs[t * NE + e] = pr[e];
        int i0 = 0; float v0 = pr[0];
#pragma unroll
        for (int e = 1; e < NE; e++) if (pr[e] > v0) { v0 = pr[e]; i0 = e; }
        int i1 = -1; float v1 = -1.f;
#pragma unroll
        for (int e = 0; e < NE; e++) { if (e == i0) continue; if (pr[e] > v1) { v1 = pr[e]; i1 = e; } }
        float wsum = v0 + v1;
        float w0 = v0 / wsum, w1 = v1 / wsum;
        int r0 = atomicAdd(&g_cnt[i0], 1); g_rowlist[i0 * TT + r0] = t;
        int r1 = atomicAdd(&g_cnt[i1], 1); g_rowlist[i1 * TT + r1] = t;
        g_slot_e[2 * t]     = i0; g_slot_r[2 * t]     = r0; g_slot_w[2 * t]     = w0;
        g_slot_e[2 * t + 1] = i1; g_slot_r[2 * t + 1] = r1; g_slot_w[2 * t + 1] = w1;
    }
}

// ---------------- loss (deterministic tree reduction) ----------------
__global__ void loss_kernel(float* __restrict__ out, int out_size)
{
    int tid = threadIdx.x;
    __shared__ float red[256];
    __shared__ float sumsp[NE];
    __shared__ float sumz;
    float accp[NE];
#pragma unroll
    for (int e = 0; e < NE; e++) accp[e] = 0.f;
    float accz = 0.f;
    for (int t = tid; t < TT; t += 256) {
        float z = g_zz[t];
        accz += z * z;
#pragma unroll
        for (int e = 0; e < NE; e++) accp[e] += g_probs[t * NE + e];
    }
    red[tid] = accz; __syncthreads();
    for (int o = 128; o > 0; o >>= 1) { if (tid < o) red[tid] += red[tid + o]; __syncthreads(); }
    if (tid == 0) sumz = red[0];
    __syncthreads();
    for (int e = 0; e < NE; e++) {
        red[tid] = accp[e]; __syncthreads();
        for (int o = 128; o > 0; o >>= 1) { if (tid < o) red[tid] += red[tid + o]; __syncthreads(); }
        if (tid == 0) sumsp[e] = red[0];
        __syncthreads();
    }
    if (tid == 0) {
        float aux = 0.f;
        for (int e = 0; e < NE; e++) {
            float ft = (float)g_cnt[e] / (float)TT;
            float fp = sumsp[e] / (float)TT;
            aux += ft * fp;
        }
        aux *= (float)NE / 2.f;
        float loss = aux + 0.001f * (sumz / (float)TT);
        for (int i = NMAIN; i < out_size; i++) out[i] = loss;
    }
}

// ---------------- combine ----------------
__global__ void combine_kernel(float* __restrict__ out)
{
    int idx = blockIdx.x * 256 + threadIdx.x;
    if (idx >= NMAIN) return;
    int t = idx >> 10;
    int d = idx & 1023;
    int e0 = g_slot_e[2 * t], r0 = g_slot_r[2 * t];
    int e1 = g_slot_e[2 * t + 1], r1 = g_slot_r[2 * t + 1];
    float w0 = g_slot_w[2 * t], w1 = g_slot_w[2 * t + 1];
    float y = g_x2[idx]
            + w0 * g_Y[((size_t)e0 * TT + r0) * DD + d]
            + w1 * g_Y[((size_t)e1 * TT + r1) * DD + d];
    out[idx] = y;
}

// ---------------- launch ----------------
extern "C" void kernel_launch(void* const* d_in, const int* in_sizes, int n_in,
                              void* d_out, int out_size)
{
    const float* x   = (const float*)d_in[0];
    const float* ln1 = (const float*)d_in[1];
    const float* ln2 = (const float*)d_in[2];
    const float* wq  = (const float*)d_in[3];
    const float* wk  = (const float*)d_in[4];
    const float* wv  = (const float*)d_in[5];
    const float* wo  = (const float*)d_in[6];
    const float* wr  = (const float*)d_in[7];
    const float* w1  = (const float*)d_in[8];
    const float* w2  = (const float*)d_in[9];
    float* out = (float*)d_out;

    cudaFuncSetAttribute(tc_attn, cudaFuncAttributeMaxDynamicSharedMemorySize, ATT_SMEM);
    cudaFuncSetAttribute(tc_gemm<GM_QKV>,  cudaFuncAttributeMaxDynamicSharedMemorySize, G_SMEM);
    cudaFuncSetAttribute(tc_gemm<GM_RES>,  cudaFuncAttributeMaxDynamicSharedMemorySize, G_SMEM);
    cudaFuncSetAttribute(tc_gemm<GM_MOE1>, cudaFuncAttributeMaxDynamicSharedMemorySize, G_SMEM);
    cudaFuncSetAttribute(tc_gemm<GM_MOE2>, cudaFuncAttributeMaxDynamicSharedMemorySize, G_SMEM);

    bf16 *p_xnh, *p_xnl, *p_xn2h, *p_xn2l, *p_ctxh, *p_ctxl;
    bf16 *p_wpth, *p_wptl, *p_w1th, *p_w1tl, *p_w2th, *p_w2tl, *p_Hh, *p_Hl;
    float *p_xn2, *p_x2, *p_Y;
    cudaGetSymbolAddress((void**)&p_xnh,  g_xnh);
    cudaGetSymbolAddress((void**)&p_xnl,  g_xnl);
    cudaGetSymbolAddress((void**)&p_xn2,  g_xn2);
    cudaGetSymbolAddress((void**)&p_xn2h, g_xn2h);
    cudaGetSymbolAddress((void**)&p_xn2l, g_xn2l);
    cudaGetSymbolAddress((void**)&p_ctxh, g_ctxh);
    cudaGetSymbolAddress((void**)&p_ctxl, g_ctxl);
    cudaGetSymbolAddress((void**)&p_x2,   g_x2);
    cudaGetSymbolAddress((void**)&p_wpth, g_wpth);
    cudaGetSymbolAddress((void**)&p_wptl, g_wptl);
    cudaGetSymbolAddress((void**)&p_w1th, g_w1th);
    cudaGetSymbolAddress((void**)&p_w1tl, g_w1tl);
    cudaGetSymbolAddress((void**)&p_w2th, g_w2th);
    cudaGetSymbolAddress((void**)&p_w2tl, g_w2tl);
    cudaGetSymbolAddress((void**)&p_Hh,   g_Hh);
    cudaGetSymbolAddress((void**)&p_Hl,   g_Hl);
    cudaGetSymbolAddress((void**)&p_Y,    g_Y);

    // launches 0-3: attention-path weight converts
    dim3 bt(256);
    wt_convert_kernel<<<dim3(DD/64, DD/64, 1), bt>>>(wq, p_wpth,           p_wptl,           DD, DD);
    wt_convert_kernel<<<dim3(DD/64, DD/64, 1), bt>>>(wk, p_wpth + DD*DD,   p_wptl + DD*DD,   DD, DD);
    wt_convert_kernel<<<dim3(DD/64, DD/64, 1), bt>>>(wv, p_wpth + 2*DD*DD, p_wptl + 2*DD*DD, DD, DD);
    wt_convert_kernel<<<dim3(DD/64, DD/64, 1), bt>>>(wo, p_wpth + 3*DD*DD, p_wptl + 3*DD*DD, DD, DD);

    // launch 4: rmsnorm 1
    rmsnorm_kernel<<<TT, 256>>>(x, ln1, nullptr, p_xnh, p_xnl);

    // launch 5 (profiled by ncu -s 5): QKV projections
    tc_gemm<GM_QKV><<<dim3(DD/256, TT/128, 3), 256, G_SMEM>>>(
        p_xnh, p_xnl, p_wpth, p_wptl, nullptr, nullptr, nullptr, nullptr, TT, DD, DD);

    // MoE weight converts (any time before MOE1)
    wt_convert_kernel<<<dim3(FF/64, DD/64, NE), bt>>>(w1, p_w1th, p_w1tl, DD, FF);
    wt_convert_kernel<<<dim3(DD/64, FF/64, NE), bt>>>(w2, p_w2th, p_w2tl, FF, DD);

    // attention (tcgen05, cp.async KV prefetch) -> ctx bf16 split
    tc_attn<<<dim3(BB * NH, SS / 128), 256, ATT_SMEM>>>(p_ctxh, p_ctxl);

    // output projection + residual
    tc_gemm<GM_RES><<<dim3(DD/256, TT/128, 1), 256, G_SMEM>>>(
        p_ctxh, p_ctxl, p_wpth + 3*DD*DD, p_wptl + 3*DD*DD, p_x2, x, nullptr, nullptr, TT, DD, DD);

    // rmsnorm 2
    rmsnorm_kernel<<<TT, 256>>>(p_x2, ln2, p_xn2, p_xn2h, p_xn2l);

    // router
    zero_cnt_kernel<<<1, 32>>>();
    router_kernel<<<TT, 32>>>(p_xn2, wr);

    // loss scalar -> out[NMAIN..]
    loss_kernel<<<1, 256>>>(out, out_size);

    // MoE expert GEMMs (grouped; tiles beyond per-expert count early-exit)
    tc_gemm<GM_MOE1><<<dim3(FF/256, TT/128, NE), 256, G_SMEM>>>(
        p_xn2h, p_xn2l, p_w1th, p_w1tl, nullptr, nullptr, p_Hh, p_Hl, TT, FF, DD);
    tc_gemm<GM_MOE2><<<dim3(DD/256, TT/128, NE), 256, G_SMEM>>>(
        p_Hh, p_Hl, p_w2th, p_w2tl, p_Y, nullptr, nullptr, nullptr, TT, DD, FF);

    // combine + residual -> out
    combine_kernel<<<(NMAIN + 255) / 256, 256>>>(out);
}